// round 3
// baseline (speedup 1.0000x reference)
#include <cuda_runtime.h>
#include <math.h>

// ---------------------------------------------------------------------------
// GCN: 3x GCNConv(+lrelu) -> reshape(40 nodes/graph) -> 3x Linear -> sigmoid
// N=200000 nodes, E=1000000 edges, C=40, hid 128/256/128, MLP 5120->512->128->1
// edge_index is int32 (JAX x64-disabled downgrades the requested int64).
// ---------------------------------------------------------------------------

#define BM 128
#define BN 128
#define BK 8
#define TM 8
#define TN 8

// Scratch (device globals; allocation inside kernel_launch is forbidden).
__device__ __align__(256) float g_bufA[(size_t)200000 * 256];
__device__ __align__(256) float g_bufB[(size_t)200000 * 256];
__device__ __align__(256) float g_bufC[(size_t)200000 * 256];
__device__ __align__(256) float g_dis[200000];

__device__ __forceinline__ float lrelu_f(float v) { return v > 0.f ? v : 0.1f * v; }

// ---------------------------- degree kernels ------------------------------
__global__ void k_init_deg(float* deg, int n) {
    int i = blockIdx.x * blockDim.x + threadIdx.x;
    if (i < n) deg[i] = 1.0f;  // self-loop
}

__global__ void k_count_deg(float* deg, const int* __restrict__ dst, int E) {
    int e = blockIdx.x * blockDim.x + threadIdx.x;
    if (e < E) atomicAdd(&deg[dst[e]], 1.0f);
}

__global__ void k_rsqrt_deg(float* deg, int n) {
    int i = blockIdx.x * blockDim.x + threadIdx.x;
    if (i < n) deg[i] = rsqrtf(deg[i]);
}

// ------------------------------- GEMM --------------------------------------
// C = act(A) @ W^T, A:[M,K] row-major, W:[N,K] row-major.
// H gets the linear result (+hbias[col] if hbias != null).
// If AGG != null, also writes AGG = H * dis[row]^2 + bias[col]
// (fused GCN self-loop + aggregation-bias init).
// If applyLrelu, LeakyReLU(0.1) is applied to A elements on load.
__global__ void __launch_bounds__(256, 2)
k_gemm(const float* __restrict__ A, const float* __restrict__ W,
       float* __restrict__ H, float* __restrict__ AGG,
       const float* __restrict__ bias, const float* __restrict__ hbias,
       const float* __restrict__ dis,
       int M, int N, int K, int applyLrelu)
{
    __shared__ float As[BK][BM];
    __shared__ float Ws[BK][BN];

    const int tid  = threadIdx.x;
    const int tx   = tid % 16;          // 16 col-threads  * TN=8 -> 128
    const int ty   = tid / 16;          // 16 row-threads  * TM=8 -> 128
    const int mBase = blockIdx.y * BM;
    const int nBase = blockIdx.x * BN;

    // Tile load mapping: 256 threads, each loads one float4 of A and of W.
    const int lRow = tid >> 1;          // 0..127
    const int lCol = (tid & 1) * 4;     // 0 or 4

    float acc[TM][TN];
#pragma unroll
    for (int i = 0; i < TM; i++)
#pragma unroll
        for (int j = 0; j < TN; j++) acc[i][j] = 0.f;

    const float* Ablk = A + (long long)mBase * K;
    const float* Wblk = W + (long long)nBase * K;

    for (int k0 = 0; k0 < K; k0 += BK) {
        // ---- load A tile (transposed into smem), lrelu on load ----
        float4 av = make_float4(0.f, 0.f, 0.f, 0.f);
        if (mBase + lRow < M)
            av = *(const float4*)(Ablk + (long long)lRow * K + k0 + lCol);
        if (applyLrelu) {
            av.x = lrelu_f(av.x); av.y = lrelu_f(av.y);
            av.z = lrelu_f(av.z); av.w = lrelu_f(av.w);
        }
        As[lCol + 0][lRow] = av.x;
        As[lCol + 1][lRow] = av.y;
        As[lCol + 2][lRow] = av.z;
        As[lCol + 3][lRow] = av.w;

        // ---- load W tile (N rows always in-bounds: N % 128 == 0) ----
        float4 wv = *(const float4*)(Wblk + (long long)lRow * K + k0 + lCol);
        Ws[lCol + 0][lRow] = wv.x;
        Ws[lCol + 1][lRow] = wv.y;
        Ws[lCol + 2][lRow] = wv.z;
        Ws[lCol + 3][lRow] = wv.w;

        __syncthreads();

#pragma unroll
        for (int k = 0; k < BK; k++) {
            float ar[TM], wr[TN];
#pragma unroll
            for (int i = 0; i < TM; i++) ar[i] = As[k][ty * TM + i];
#pragma unroll
            for (int j = 0; j < TN; j++) wr[j] = Ws[k][tx * TN + j];
#pragma unroll
            for (int i = 0; i < TM; i++)
#pragma unroll
                for (int j = 0; j < TN; j++) acc[i][j] += ar[i] * wr[j];
        }
        __syncthreads();
    }

    // ---- epilogue: write H (+hbias), and fused AGG init (H*dis^2 + bias) ----
#pragma unroll
    for (int i = 0; i < TM; i++) {
        int gm = mBase + ty * TM + i;
        if (gm >= M) continue;
        float d2 = 0.f;
        if (AGG) { float dv = dis[gm]; d2 = dv * dv; }
        long long rowOff = (long long)gm * N;
#pragma unroll
        for (int j = 0; j < TN; j++) {
            int gn = nBase + tx * TN + j;
            float h = acc[i][j];
            if (hbias) h += __ldg(&hbias[gn]);
            H[rowOff + gn] = h;
            if (AGG) AGG[rowOff + gn] = h * d2 + __ldg(&bias[gn]);
        }
    }
}

// ----------------------------- edge scatter --------------------------------
// One warp per edge. AGG[dst] += H[src] * (dis[src]*dis[dst]) over F channels.
// atomicAdd with unused result lowers to REDG.ADD.F32 (fire-and-forget).
template <int F>
__global__ void __launch_bounds__(256)
k_scatter(const float* __restrict__ H, float* __restrict__ AGG,
          const int* __restrict__ src, const int* __restrict__ dst,
          const float* __restrict__ dis, int E)
{
    int warp = (blockIdx.x * blockDim.x + threadIdx.x) >> 5;
    int lane = threadIdx.x & 31;
    if (warp >= E) return;

    int s = src[warp];
    int d = dst[warp];
    float norm = dis[s] * dis[d];

    const float4* hs = (const float4*)(H + (long long)s * F);
    float*        ag = AGG + (long long)d * F;

#pragma unroll
    for (int i = lane; i < F / 4; i += 32) {
        float4 v = hs[i];
        atomicAdd(ag + i * 4 + 0, v.x * norm);
        atomicAdd(ag + i * 4 + 1, v.y * norm);
        atomicAdd(ag + i * 4 + 2, v.z * norm);
        atomicAdd(ag + i * 4 + 3, v.w * norm);
    }
}

// --------------------------- final linear + sigmoid -------------------------
__global__ void k_mlp_out(const float* __restrict__ g2, const float* __restrict__ L3w,
                          const float* __restrict__ L3b, float* __restrict__ out, int G)
{
    int w    = (blockIdx.x * blockDim.x + threadIdx.x) >> 5;
    int lane = threadIdx.x & 31;
    if (w >= G) return;
    float s = 0.f;
#pragma unroll
    for (int c = lane; c < 128; c += 32)
        s += lrelu_f(g2[(long long)w * 128 + c]) * __ldg(&L3w[c]);
#pragma unroll
    for (int off = 16; off; off >>= 1) s += __shfl_xor_sync(0xffffffffu, s, off);
    if (lane == 0) out[w] = 1.f / (1.f + expf(-(s + L3b[0])));
}

// ------------------------------- launch ------------------------------------
extern "C" void kernel_launch(void* const* d_in, const int* in_sizes, int n_in,
                              void* d_out, int out_size)
{
    const float* x   = (const float*)d_in[0];
    const int*   ei  = (const int*)d_in[1];           // int32 (JAX x64 disabled)
    const float* W1 = (const float*)d_in[2];  const float* b1 = (const float*)d_in[3];
    const float* W2 = (const float*)d_in[4];  const float* b2 = (const float*)d_in[5];
    const float* W3 = (const float*)d_in[6];  const float* b3 = (const float*)d_in[7];
    const float* L1w = (const float*)d_in[8];  const float* L1b = (const float*)d_in[9];
    const float* L2w = (const float*)d_in[10]; const float* L2b = (const float*)d_in[11];
    const float* L3w = (const float*)d_in[12]; const float* L3b = (const float*)d_in[13];
    float* out = (float*)d_out;

    const int C = 40;
    const int N = in_sizes[0] / C;     // 200000
    const int E = in_sizes[1] / 2;     // 1000000
    const int G = N / 40;              // 5000

    const int* srcIdx = ei;
    const int* dstIdx = ei + E;

    float *bufA, *bufB, *bufC, *dis;
    cudaGetSymbolAddress((void**)&bufA, g_bufA);
    cudaGetSymbolAddress((void**)&bufB, g_bufB);
    cudaGetSymbolAddress((void**)&bufC, g_bufC);
    cudaGetSymbolAddress((void**)&dis,  g_dis);

    // ---- degree / normalization ----
    k_init_deg <<<(N + 255) / 256, 256>>>(dis, N);
    k_count_deg<<<(E + 255) / 256, 256>>>(dis, dstIdx, E);
    k_rsqrt_deg<<<(N + 255) / 256, 256>>>(dis, N);

    const int mBlocksN = (N + BM - 1) / BM;
    const int scatBlocks = (int)(((long long)E * 32 + 255) / 256);

    // ---- conv1: x[N,40] @ W1^T -> H1(bufA), AGG1(bufB) ----
    k_gemm<<<dim3(128 / BN, mBlocksN), 256>>>(x, W1, bufA, bufB, b1, nullptr, dis,
                                              N, 128, 40, 0);
    k_scatter<128><<<scatBlocks, 256>>>(bufA, bufB, srcIdx, dstIdx, dis, E);

    // ---- conv2: lrelu(AGG1)[N,128] @ W2^T -> H2(bufA), AGG2(bufC) ----
    k_gemm<<<dim3(256 / BN, mBlocksN), 256>>>(bufB, W2, bufA, bufC, b2, nullptr, dis,
                                              N, 256, 128, 1);
    k_scatter<256><<<scatBlocks, 256>>>(bufA, bufC, srcIdx, dstIdx, dis, E);

    // ---- conv3: lrelu(AGG2)[N,256] @ W3^T -> H3(bufA), AGG3(bufB) ----
    k_gemm<<<dim3(128 / BN, mBlocksN), 256>>>(bufC, W3, bufA, bufB, b3, nullptr, dis,
                                              N, 128, 256, 1);
    k_scatter<128><<<scatBlocks, 256>>>(bufA, bufB, srcIdx, dstIdx, dis, E);

    // ---- MLP: g = lrelu(AGG3).reshape(G, 5120) ----
    const int mBlocksG = (G + BM - 1) / BM;
    // L1: [G,5120] @ L1w^T + L1b -> g1(bufA) [G,512]   (pre-activation)
    k_gemm<<<dim3(512 / BN, mBlocksG), 256>>>(bufB, L1w, bufA, nullptr, nullptr, L1b,
                                              nullptr, G, 512, 5120, 1);
    // L2: lrelu(g1) @ L2w^T + L2b -> g2(bufC) [G,128]  (pre-activation)
    k_gemm<<<dim3(128 / BN, mBlocksG), 256>>>(bufA, L2w, bufC, nullptr, nullptr, L2b,
                                              nullptr, G, 128, 512, 1);
    // L3 + sigmoid
    k_mlp_out<<<(G * 32 + 255) / 256, 256>>>(bufC, L3w, L3b, out, G);
}

// round 4
// speedup vs baseline: 1.2376x; 1.2376x over previous
#include <cuda_runtime.h>
#include <math.h>

// ---------------------------------------------------------------------------
// GCN: 3x GCNConv(+lrelu) -> reshape(40 nodes/graph) -> 3x Linear -> sigmoid
// N=200000, E=1000000, C=40, hid 128/256/128, MLP 5120->512->128->1
// edge_index is int32.
// GEMM: double-buffered smem tiles + packed fma.rn.f32x2 (Blackwell fp32x2)
// ---------------------------------------------------------------------------

#define BM 128
#define BN 128
#define BK 16

// Scratch (device globals; allocation inside kernel_launch is forbidden).
__device__ __align__(256) float g_bufA[(size_t)200000 * 256];
__device__ __align__(256) float g_bufB[(size_t)200000 * 256];
__device__ __align__(256) float g_bufC[(size_t)200000 * 256];
__device__ __align__(256) float g_dis[200000];

__device__ __forceinline__ float lrelu_f(float v) { return v > 0.f ? v : 0.1f * v; }

__device__ __forceinline__ unsigned long long pack2(float lo, float hi) {
    unsigned long long r;
    asm("mov.b64 %0, {%1, %2};" : "=l"(r) : "f"(lo), "f"(hi));
    return r;
}
__device__ __forceinline__ void fma2(unsigned long long& c, unsigned long long a,
                                     unsigned long long b) {
    asm("fma.rn.f32x2 %0, %1, %2, %0;" : "+l"(c) : "l"(a), "l"(b));
}
__device__ __forceinline__ float2 unpack2(unsigned long long v) {
    float2 f;
    asm("mov.b64 {%0, %1}, %2;" : "=f"(f.x), "=f"(f.y) : "l"(v));
    return f;
}

// ---------------------------- small kernels --------------------------------
__global__ void k_init_deg(float* deg, int n) {
    int i = blockIdx.x * blockDim.x + threadIdx.x;
    if (i < n) deg[i] = 1.0f;  // self-loop
}
__global__ void k_count_deg(float* deg, const int* __restrict__ dst, int E) {
    int e = blockIdx.x * blockDim.x + threadIdx.x;
    if (e < E) atomicAdd(&deg[dst[e]], 1.0f);
}
__global__ void k_rsqrt_deg(float* deg, int n) {
    int i = blockIdx.x * blockDim.x + threadIdx.x;
    if (i < n) deg[i] = rsqrtf(deg[i]);
}
// H[m, 0:N] = b[0:N]  (init for split-K accumulation)
__global__ void k_fill_bias(float* __restrict__ H, const float* __restrict__ b,
                            int M, int N) {
    int i = blockIdx.x * blockDim.x + threadIdx.x;
    if (i < M * N) H[i] = b[i % N];
}

// ------------------------------- GEMM --------------------------------------
// C = act(A) @ W^T, A:[M,K] row-major, W:[N,K] row-major.
// kSplit == 1: H = result (+ fused AGG = H*dis^2 + bias when AGG != null).
// kSplit  > 1: H += partial result via atomicAdd (H must be pre-initialized
//              with the bias); AGG path unused.
// applyLrelu: LeakyReLU(0.1) applied to A elements on load.
__global__ void __launch_bounds__(256, 2)
k_gemm(const float* __restrict__ A, const float* __restrict__ W,
       float* __restrict__ H, float* __restrict__ AGG,
       const float* __restrict__ bias, const float* __restrict__ dis,
       int M, int N, int K, int applyLrelu, int kSplit)
{
    __shared__ float As[2][BK][BM];
    __shared__ float Ws[2][BK][BN];

    const int tid   = threadIdx.x;
    const int tx    = tid % 16;             // 16 col-threads * 8 -> 128
    const int ty    = tid / 16;             // 16 row-threads * 8 -> 128
    const int mBase = blockIdx.y * BM;
    const int nBase = blockIdx.x * BN;

    const int kChunk = K / kSplit;          // divisible by BK (or K=40 case, kSplit=1)
    const int kStart = blockIdx.z * kChunk;
    const int kEnd   = kStart + kChunk;

    // Tile-load mapping: each thread loads 2 float4 of A and 2 of W per stage.
    const int lRow = tid >> 2;              // 0..63
    const int lCol = (tid & 3) * 4;         // 0,4,8,12

    const float* Arow0 = A + (long long)(mBase + lRow)      * K;
    const float* Arow1 = A + (long long)(mBase + lRow + 64) * K;
    const float* Wrow0 = W + (long long)(nBase + lRow)      * K;
    const float* Wrow1 = W + (long long)(nBase + lRow + 64) * K;
    const bool mOk0 = (mBase + lRow)      < M;
    const bool mOk1 = (mBase + lRow + 64) < M;

    float4 pA0, pA1, pW0, pW1;

    auto gload = [&](int k0) {
        const bool kOk = (k0 + lCol + 4) <= K;   // full float4 in-bounds (K%4==0)
        pA0 = (mOk0 && kOk) ? *(const float4*)(Arow0 + k0 + lCol)
                            : make_float4(0.f, 0.f, 0.f, 0.f);
        pA1 = (mOk1 && kOk) ? *(const float4*)(Arow1 + k0 + lCol)
                            : make_float4(0.f, 0.f, 0.f, 0.f);
        pW0 = kOk ? *(const float4*)(Wrow0 + k0 + lCol) : make_float4(0.f, 0.f, 0.f, 0.f);
        pW1 = kOk ? *(const float4*)(Wrow1 + k0 + lCol) : make_float4(0.f, 0.f, 0.f, 0.f);
        if (applyLrelu) {
            pA0.x = lrelu_f(pA0.x); pA0.y = lrelu_f(pA0.y);
            pA0.z = lrelu_f(pA0.z); pA0.w = lrelu_f(pA0.w);
            pA1.x = lrelu_f(pA1.x); pA1.y = lrelu_f(pA1.y);
            pA1.z = lrelu_f(pA1.z); pA1.w = lrelu_f(pA1.w);
        }
    };
    auto smstore = [&](int s) {
        As[s][lCol + 0][lRow] = pA0.x;  As[s][lCol + 1][lRow] = pA0.y;
        As[s][lCol + 2][lRow] = pA0.z;  As[s][lCol + 3][lRow] = pA0.w;
        As[s][lCol + 0][lRow + 64] = pA1.x;  As[s][lCol + 1][lRow + 64] = pA1.y;
        As[s][lCol + 2][lRow + 64] = pA1.z;  As[s][lCol + 3][lRow + 64] = pA1.w;
        Ws[s][lCol + 0][lRow] = pW0.x;  Ws[s][lCol + 1][lRow] = pW0.y;
        Ws[s][lCol + 2][lRow] = pW0.z;  Ws[s][lCol + 3][lRow] = pW0.w;
        Ws[s][lCol + 0][lRow + 64] = pW1.x;  Ws[s][lCol + 1][lRow + 64] = pW1.y;
        Ws[s][lCol + 2][lRow + 64] = pW1.z;  Ws[s][lCol + 3][lRow + 64] = pW1.w;
    };

    unsigned long long acc[8][4];
#pragma unroll
    for (int i = 0; i < 8; i++)
#pragma unroll
        for (int j = 0; j < 4; j++) acc[i][j] = 0ull;

    gload(kStart);
    smstore(0);
    __syncthreads();

    int s = 0;
    for (int k0 = kStart; k0 < kEnd; k0 += BK) {
        const bool more = (k0 + BK) < kEnd;
        if (more) gload(k0 + BK);

#pragma unroll
        for (int k = 0; k < BK; k++) {
            float4 a0 = *(const float4*)&As[s][k][ty * 8];
            float4 a1 = *(const float4*)&As[s][k][ty * 8 + 4];
            float4 w0 = *(const float4*)&Ws[s][k][tx * 8];
            float4 w1 = *(const float4*)&Ws[s][k][tx * 8 + 4];

            unsigned long long bp[4];
            bp[0] = pack2(w0.x, w0.y);  bp[1] = pack2(w0.z, w0.w);
            bp[2] = pack2(w1.x, w1.y);  bp[3] = pack2(w1.z, w1.w);

            float ar[8] = {a0.x, a0.y, a0.z, a0.w, a1.x, a1.y, a1.z, a1.w};
#pragma unroll
            for (int i = 0; i < 8; i++) {
                unsigned long long ad = pack2(ar[i], ar[i]);
#pragma unroll
                for (int jp = 0; jp < 4; jp++) fma2(acc[i][jp], ad, bp[jp]);
            }
        }

        if (more) {
            smstore(s ^ 1);
            __syncthreads();
            s ^= 1;
        }
    }

    // ---- epilogue ----
#pragma unroll
    for (int i = 0; i < 8; i++) {
        int gm = mBase + ty * 8 + i;
        if (gm >= M) continue;
        float d2 = 0.f;
        if (AGG) { float dv = dis[gm]; d2 = dv * dv; }
        long long rowOff = (long long)gm * N;
#pragma unroll
        for (int jp = 0; jp < 4; jp++) {
            int gn = nBase + tx * 8 + jp * 2;
            float2 v = unpack2(acc[i][jp]);
            if (kSplit > 1) {
                atomicAdd(&H[rowOff + gn + 0], v.x);
                atomicAdd(&H[rowOff + gn + 1], v.y);
            } else {
                H[rowOff + gn + 0] = v.x;
                H[rowOff + gn + 1] = v.y;
                if (AGG) {
                    AGG[rowOff + gn + 0] = v.x * d2 + __ldg(&bias[gn + 0]);
                    AGG[rowOff + gn + 1] = v.y * d2 + __ldg(&bias[gn + 1]);
                }
            }
        }
    }
}

// ----------------------------- edge scatter --------------------------------
// One warp per edge. AGG[dst] += H[src] * (dis[src]*dis[dst]) over F channels.
// atomicAdd with unused result lowers to REDG.ADD.F32 (fire-and-forget).
template <int F>
__global__ void __launch_bounds__(256)
k_scatter(const float* __restrict__ H, float* __restrict__ AGG,
          const int* __restrict__ src, const int* __restrict__ dst,
          const float* __restrict__ dis, int E)
{
    int warp = (blockIdx.x * blockDim.x + threadIdx.x) >> 5;
    int lane = threadIdx.x & 31;
    if (warp >= E) return;

    int s = src[warp];
    int d = dst[warp];
    float norm = dis[s] * dis[d];

    const float4* hs = (const float4*)(H + (long long)s * F);
    float*        ag = AGG + (long long)d * F;

#pragma unroll
    for (int i = lane; i < F / 4; i += 32) {
        float4 v = hs[i];
        atomicAdd(ag + i * 4 + 0, v.x * norm);
        atomicAdd(ag + i * 4 + 1, v.y * norm);
        atomicAdd(ag + i * 4 + 2, v.z * norm);
        atomicAdd(ag + i * 4 + 3, v.w * norm);
    }
}

// --------------------------- final linear + sigmoid -------------------------
__global__ void k_mlp_out(const float* __restrict__ g2, const float* __restrict__ L3w,
                          const float* __restrict__ L3b, float* __restrict__ out, int G)
{
    int w    = (blockIdx.x * blockDim.x + threadIdx.x) >> 5;
    int lane = threadIdx.x & 31;
    if (w >= G) return;
    float s = 0.f;
#pragma unroll
    for (int c = lane; c < 128; c += 32)
        s += lrelu_f(g2[(long long)w * 128 + c]) * __ldg(&L3w[c]);
#pragma unroll
    for (int off = 16; off; off >>= 1) s += __shfl_xor_sync(0xffffffffu, s, off);
    if (lane == 0) out[w] = 1.f / (1.f + expf(-(s + L3b[0])));
}

// ------------------------------- launch ------------------------------------
extern "C" void kernel_launch(void* const* d_in, const int* in_sizes, int n_in,
                              void* d_out, int out_size)
{
    const float* x   = (const float*)d_in[0];
    const int*   ei  = (const int*)d_in[1];           // int32
    const float* W1 = (const float*)d_in[2];  const float* b1 = (const float*)d_in[3];
    const float* W2 = (const float*)d_in[4];  const float* b2 = (const float*)d_in[5];
    const float* W3 = (const float*)d_in[6];  const float* b3 = (const float*)d_in[7];
    const float* L1w = (const float*)d_in[8];  const float* L1b = (const float*)d_in[9];
    const float* L2w = (const float*)d_in[10]; const float* L2b = (const float*)d_in[11];
    const float* L3w = (const float*)d_in[12]; const float* L3b = (const float*)d_in[13];
    float* out = (float*)d_out;

    const int C = 40;
    const int N = in_sizes[0] / C;     // 200000
    const int E = in_sizes[1] / 2;     // 1000000
    const int G = N / 40;              // 5000

    const int* srcIdx = ei;
    const int* dstIdx = ei + E;

    float *bufA, *bufB, *bufC, *dis;
    cudaGetSymbolAddress((void**)&bufA, g_bufA);
    cudaGetSymbolAddress((void**)&bufB, g_bufB);
    cudaGetSymbolAddress((void**)&bufC, g_bufC);
    cudaGetSymbolAddress((void**)&dis,  g_dis);

    // ---- degree / normalization ----
    k_init_deg <<<(N + 255) / 256, 256>>>(dis, N);
    k_count_deg<<<(E + 255) / 256, 256>>>(dis, dstIdx, E);
    k_rsqrt_deg<<<(N + 255) / 256, 256>>>(dis, N);

    const int mBlocksN = (N + BM - 1) / BM;    // 1563
    const int mBlocksG = (G + BM - 1) / BM;    // 40
    const int scatBlocks = (int)(((long long)E * 32 + 255) / 256);

    // ---- conv1: x[N,40] @ W1^T -> H1(bufA), AGG1(bufB) ----
    k_gemm<<<dim3(1, mBlocksN, 1), 256>>>(x, W1, bufA, bufB, b1, dis,
                                          N, 128, 40, 0, 1);
    k_scatter<128><<<scatBlocks, 256>>>(bufA, bufB, srcIdx, dstIdx, dis, E);

    // ---- conv2: lrelu(AGG1)[N,128] @ W2^T -> H2(bufA), AGG2(bufC) ----
    k_gemm<<<dim3(2, mBlocksN, 1), 256>>>(bufB, W2, bufA, bufC, b2, dis,
                                          N, 256, 128, 1, 1);
    k_scatter<256><<<scatBlocks, 256>>>(bufA, bufC, srcIdx, dstIdx, dis, E);

    // ---- conv3: lrelu(AGG2)[N,256] @ W3^T -> H3(bufA), AGG3(bufB) ----
    k_gemm<<<dim3(1, mBlocksN, 1), 256>>>(bufC, W3, bufA, bufB, b3, dis,
                                          N, 128, 256, 1, 1);
    k_scatter<128><<<scatBlocks, 256>>>(bufA, bufB, srcIdx, dstIdx, dis, E);

    // ---- MLP ----
    // L1: lrelu(AGG3).reshape(G,5120) @ L1w^T + L1b -> bufA [G,512], split-K x8
    k_fill_bias<<<(G * 512 + 255) / 256, 256>>>(bufA, L1b, G, 512);
    k_gemm<<<dim3(4, mBlocksG, 8), 256>>>(bufB, L1w, bufA, nullptr, nullptr, nullptr,
                                          G, 512, 5120, 1, 8);
    // L2: lrelu(g1) @ L2w^T + L2b -> bufC [G,128], split-K x8 (chunk 64)
    k_fill_bias<<<(G * 128 + 255) / 256, 256>>>(bufC, L2b, G, 128);
    k_gemm<<<dim3(1, mBlocksG, 8), 256>>>(bufA, L2w, bufC, nullptr, nullptr, nullptr,
                                          G, 128, 512, 1, 8);
    // L3 + sigmoid
    k_mlp_out<<<(G * 32 + 255) / 256, 256>>>(bufC, L3w, L3b, out, G);
}

// round 6
// speedup vs baseline: 1.7586x; 1.4210x over previous
#include <cuda_runtime.h>
#include <cuda_bf16.h>
#include <math.h>
#include <stdint.h>

// ---------------------------------------------------------------------------
// GCN: 3x GCNConv(+lrelu) -> reshape(40/graph) -> 3x Linear -> sigmoid
// GEMMs via mma.sync m16n8k16 bf16 with bf16x3 fp32 emulation
// (hi*hi + hi*lo + lo*hi, fp32 accum). Works on plain sm_103 target.
// ---------------------------------------------------------------------------

#define TILE_M 128
#define TILE_N 128
#define KC 32                      // k-chunk
#define SROW 80                    // smem row stride bytes (40 halves, pad)
#define STG_BYTES (128 * SROW)     // 10240 per stage per array

// dynamic smem layout (4 arrays x 2 stages)
#define OFF_AH 0
#define OFF_AL (2 * STG_BYTES)
#define OFF_WH (4 * STG_BYTES)
#define OFF_WL (6 * STG_BYTES)
#define SMB    (8 * STG_BYTES)     // 81920 bytes

__device__ __align__(256) float g_bufA[(size_t)200000 * 256];
__device__ __align__(256) float g_bufB[(size_t)200000 * 256];
__device__ __align__(256) float g_bufC[(size_t)200000 * 256];
__device__ __align__(256) float g_dis[200000];

__device__ __forceinline__ float lrelu_f(float v) { return v > 0.f ? v : 0.1f * v; }

__device__ __forceinline__ uint32_t smem_u32(const void* p) {
    uint32_t a;
    asm("{ .reg .u64 t; cvta.to.shared.u64 t, %1; cvt.u32.u64 %0, t; }" : "=r"(a) : "l"(p));
    return a;
}
__device__ __forceinline__ uint32_t lds32(uint32_t a) {
    uint32_t v;
    asm volatile("ld.shared.b32 %0, [%1];" : "=r"(v) : "r"(a));
    return v;
}
__device__ __forceinline__ void mma16816(float* c, const uint32_t* a, const uint32_t* b) {
    asm volatile(
        "mma.sync.aligned.m16n8k16.row.col.f32.bf16.bf16.f32 "
        "{%0,%1,%2,%3}, {%4,%5,%6,%7}, {%8,%9}, {%0,%1,%2,%3};"
        : "+f"(c[0]), "+f"(c[1]), "+f"(c[2]), "+f"(c[3])
        : "r"(a[0]), "r"(a[1]), "r"(a[2]), "r"(a[3]), "r"(b[0]), "r"(b[1]));
}
__device__ __forceinline__ uint32_t packbf(float x, float y) {
    __nv_bfloat16 hx = __float2bfloat16_rn(x), hy = __float2bfloat16_rn(y);
    return (uint32_t)__bfloat16_as_ushort(hx) | ((uint32_t)__bfloat16_as_ushort(hy) << 16);
}

// ---------------------------- small kernels --------------------------------
__global__ void k_init_deg(float* deg, int n) {
    int i = blockIdx.x * blockDim.x + threadIdx.x;
    if (i < n) deg[i] = 1.0f;
}
__global__ void k_count_deg(float* deg, const int* __restrict__ dst, int E) {
    int e = blockIdx.x * blockDim.x + threadIdx.x;
    if (e < E) atomicAdd(&deg[dst[e]], 1.0f);
}
__global__ void k_rsqrt_deg(float* deg, int n) {
    int i = blockIdx.x * blockDim.x + threadIdx.x;
    if (i < n) deg[i] = rsqrtf(deg[i]);
}
__global__ void k_fill_bias(float* __restrict__ H, const float* __restrict__ b,
                            int M, int N) {
    int i = blockIdx.x * blockDim.x + threadIdx.x;
    if (i < M * N) H[i] = b[i % N];
}

// ------------------------ tensor-core bf16x3 GEMM ---------------------------
// C = act(A) @ W^T ; A:[M,K] fp32 row-major, W:[Nout,K] fp32 row-major.
// kSplit==1: H = result; if AGG != null, AGG = H*dis[row]^2 + bias[col].
// kSplit >1: atomicAdd partials into pre-biased H.
// Grid: (Nout/128, ceil(M/128), kSplit). kLen: padded K per z-slice (mult of 32).
__global__ void __launch_bounds__(256, 2)
k_mma_gemm(const float* __restrict__ A, const float* __restrict__ W,
           float* __restrict__ H, float* __restrict__ AGG,
           const float* __restrict__ bias, const float* __restrict__ dis,
           int M, int Nout, int K, int kLen, int applyLrelu, int kSplit)
{
    extern __shared__ char smem[];
    const uint32_t sb = smem_u32(smem);
    const int tid  = threadIdx.x;
    const int wid  = tid >> 5;
    const int lane = tid & 31;
    const int g    = lane >> 2;          // group id 0..7
    const int tig  = lane & 3;           // thread-in-group
    const int warpM = wid >> 1;          // 0..3 -> 32-row slab
    const int warpN = wid & 1;           // 0..1 -> 64-col slab
    const int mBase = blockIdx.y * TILE_M;
    const int nBase = blockIdx.x * TILE_N;
    const long long zOff = (long long)blockIdx.z * kLen;

    float acc[2][8][4];
#pragma unroll
    for (int i = 0; i < 2; i++)
#pragma unroll
        for (int j = 0; j < 8; j++)
#pragma unroll
            for (int q = 0; q < 4; q++) acc[i][j][q] = 0.f;

    auto loadStage = [&](int stg, int kb) {
        const int so = stg * STG_BYTES;
        // ---- A tile: 128 x 32 fp32 -> hi/lo bf16 ----
#pragma unroll
        for (int q = tid; q < 1024; q += 256) {
            int row = q >> 3, kq = q & 7;
            long long gk = zOff + kb + kq * 4;
            int gm = mBase + row;
            float4 v = make_float4(0.f, 0.f, 0.f, 0.f);
            if (gm < M && gk + 4 <= (long long)K)
                v = *(const float4*)(A + (long long)gm * K + gk);
            if (applyLrelu) {
                v.x = lrelu_f(v.x); v.y = lrelu_f(v.y);
                v.z = lrelu_f(v.z); v.w = lrelu_f(v.w);
            }
            __nv_bfloat16 h0 = __float2bfloat16_rn(v.x), h1 = __float2bfloat16_rn(v.y);
            __nv_bfloat16 h2 = __float2bfloat16_rn(v.z), h3 = __float2bfloat16_rn(v.w);
            uint32_t hiA = (uint32_t)__bfloat16_as_ushort(h0) | ((uint32_t)__bfloat16_as_ushort(h1) << 16);
            uint32_t hiB = (uint32_t)__bfloat16_as_ushort(h2) | ((uint32_t)__bfloat16_as_ushort(h3) << 16);
            uint32_t loA = packbf(v.x - __bfloat162float(h0), v.y - __bfloat162float(h1));
            uint32_t loB = packbf(v.z - __bfloat162float(h2), v.w - __bfloat162float(h3));
            uint32_t off = so + row * SROW + kq * 8;
            *(uint2*)(smem + OFF_AH + off) = make_uint2(hiA, hiB);
            *(uint2*)(smem + OFF_AL + off) = make_uint2(loA, loB);
        }
        // ---- W tile: 128 x 32 (rows nBase..nBase+127, always valid) ----
#pragma unroll
        for (int q = tid; q < 1024; q += 256) {
            int row = q >> 3, kq = q & 7;
            long long gk = zOff + kb + kq * 4;
            float4 v = make_float4(0.f, 0.f, 0.f, 0.f);
            if (gk + 4 <= (long long)K)
                v = *(const float4*)(W + (long long)(nBase + row) * K + gk);
            __nv_bfloat16 h0 = __float2bfloat16_rn(v.x), h1 = __float2bfloat16_rn(v.y);
            __nv_bfloat16 h2 = __float2bfloat16_rn(v.z), h3 = __float2bfloat16_rn(v.w);
            uint32_t hiA = (uint32_t)__bfloat16_as_ushort(h0) | ((uint32_t)__bfloat16_as_ushort(h1) << 16);
            uint32_t hiB = (uint32_t)__bfloat16_as_ushort(h2) | ((uint32_t)__bfloat16_as_ushort(h3) << 16);
            uint32_t loA = packbf(v.x - __bfloat162float(h0), v.y - __bfloat162float(h1));
            uint32_t loB = packbf(v.z - __bfloat162float(h2), v.w - __bfloat162float(h3));
            uint32_t off = so + row * SROW + kq * 8;
            *(uint2*)(smem + OFF_WH + off) = make_uint2(hiA, hiB);
            *(uint2*)(smem + OFF_WL + off) = make_uint2(loA, loB);
        }
    };

    loadStage(0, 0);
    __syncthreads();

    int s = 0;
    for (int kb = 0; kb < kLen; kb += KC) {
        if (kb + KC < kLen) loadStage(s ^ 1, kb + KC);

        const uint32_t so = (uint32_t)(s * STG_BYTES);
#pragma unroll
        for (int kk = 0; kk < 2; kk++) {
            const uint32_t kcb = (uint32_t)((kk * 16 + 2 * tig) * 2);  // byte col
            uint32_t ah[2][4], alo[2][4];
#pragma unroll
            for (int ms = 0; ms < 2; ms++) {
                uint32_t base = sb + so + (uint32_t)((warpM * 32 + ms * 16 + g) * SROW) + kcb;
                ah[ms][0]  = lds32(base + OFF_AH);
                ah[ms][1]  = lds32(base + OFF_AH + 8 * SROW);
                ah[ms][2]  = lds32(base + OFF_AH + 16);
                ah[ms][3]  = lds32(base + OFF_AH + 8 * SROW + 16);
                alo[ms][0] = lds32(base + OFF_AL);
                alo[ms][1] = lds32(base + OFF_AL + 8 * SROW);
                alo[ms][2] = lds32(base + OFF_AL + 16);
                alo[ms][3] = lds32(base + OFF_AL + 8 * SROW + 16);
            }
#pragma unroll
            for (int nh = 0; nh < 2; nh++) {       // two halves of 4 n-subtiles
                uint32_t bh[4][2], blo[4][2];
#pragma unroll
                for (int j = 0; j < 4; j++) {
                    int ns = nh * 4 + j;
                    uint32_t base = sb + so + (uint32_t)((warpN * 64 + ns * 8 + g) * SROW) + kcb;
                    bh[j][0]  = lds32(base + OFF_WH);
                    bh[j][1]  = lds32(base + OFF_WH + 16);
                    blo[j][0] = lds32(base + OFF_WL);
                    blo[j][1] = lds32(base + OFF_WL + 16);
                }
#pragma unroll
                for (int ms = 0; ms < 2; ms++)
#pragma unroll
                    for (int j = 0; j < 4; j++) {
                        float* c = acc[ms][nh * 4 + j];
                        mma16816(c, ah[ms],  bh[j]);
                        mma16816(c, ah[ms],  blo[j]);
                        mma16816(c, alo[ms], bh[j]);
                    }
            }
        }
        __syncthreads();
        s ^= 1;
    }

    // ---- epilogue ----
    const int mW = mBase + warpM * 32;
#pragma unroll
    for (int ms = 0; ms < 2; ms++) {
#pragma unroll
        for (int half = 0; half < 2; half++) {
            int row = mW + ms * 16 + g + half * 8;
            if (row >= M) continue;
            float d2 = 0.f;
            if (AGG != nullptr) { float dv = dis[row]; d2 = dv * dv; }
            long long ro = (long long)row * Nout;
#pragma unroll
            for (int ns = 0; ns < 8; ns++) {
                int col = nBase + warpN * 64 + ns * 8 + 2 * tig;
                float c0 = acc[ms][ns][half * 2 + 0];
                float c1 = acc[ms][ns][half * 2 + 1];
                if (kSplit > 1) {
                    atomicAdd(&H[ro + col + 0], c0);
                    atomicAdd(&H[ro + col + 1], c1);
                } else {
                    *(float2*)(H + ro + col) = make_float2(c0, c1);
                    if (AGG) {
                        float b0v = __ldg(&bias[col]), b1v = __ldg(&bias[col + 1]);
                        *(float2*)(AGG + ro + col) = make_float2(c0 * d2 + b0v, c1 * d2 + b1v);
                    }
                }
            }
        }
    }
}

// ----------------------------- edge scatter --------------------------------
template <int F>
__global__ void __launch_bounds__(256)
k_scatter(const float* __restrict__ H, float* __restrict__ AGG,
          const int* __restrict__ src, const int* __restrict__ dst,
          const float* __restrict__ dis, int E)
{
    int warp = (blockIdx.x * blockDim.x + threadIdx.x) >> 5;
    int lane = threadIdx.x & 31;
    if (warp >= E) return;

    int s = src[warp];
    int d = dst[warp];
    float norm = dis[s] * dis[d];

    const float4* hs = (const float4*)(H + (long long)s * F);
    float*        ag = AGG + (long long)d * F;

#pragma unroll
    for (int i = lane; i < F / 4; i += 32) {
        float4 v = hs[i];
        atomicAdd(ag + i * 4 + 0, v.x * norm);
        atomicAdd(ag + i * 4 + 1, v.y * norm);
        atomicAdd(ag + i * 4 + 2, v.z * norm);
        atomicAdd(ag + i * 4 + 3, v.w * norm);
    }
}

// --------------------------- final linear + sigmoid -------------------------
__global__ void k_mlp_out(const float* __restrict__ g2, const float* __restrict__ L3w,
                          const float* __restrict__ L3b, float* __restrict__ out, int G)
{
    int w    = (blockIdx.x * blockDim.x + threadIdx.x) >> 5;
    int lane = threadIdx.x & 31;
    if (w >= G) return;
    float s = 0.f;
#pragma unroll
    for (int c = lane; c < 128; c += 32)
        s += lrelu_f(g2[(long long)w * 128 + c]) * __ldg(&L3w[c]);
#pragma unroll
    for (int off = 16; off; off >>= 1) s += __shfl_xor_sync(0xffffffffu, s, off);
    if (lane == 0) out[w] = 1.f / (1.f + expf(-(s + L3b[0])));
}

// ------------------------------- launch ------------------------------------
extern "C" void kernel_launch(void* const* d_in, const int* in_sizes, int n_in,
                              void* d_out, int out_size)
{
    const float* x   = (const float*)d_in[0];
    const int*   ei  = (const int*)d_in[1];
    const float* W1 = (const float*)d_in[2];  const float* b1 = (const float*)d_in[3];
    const float* W2 = (const float*)d_in[4];  const float* b2 = (const float*)d_in[5];
    const float* W3 = (const float*)d_in[6];  const float* b3 = (const float*)d_in[7];
    const float* L1w = (const float*)d_in[8];  const float* L1b = (const float*)d_in[9];
    const float* L2w = (const float*)d_in[10]; const float* L2b = (const float*)d_in[11];
    const float* L3w = (const float*)d_in[12]; const float* L3b = (const float*)d_in[13];
    float* out = (float*)d_out;

    const int C = 40;
    const int N = in_sizes[0] / C;     // 200000
    const int E = in_sizes[1] / 2;     // 1000000
    const int G = N / 40;              // 5000

    const int* srcIdx = ei;
    const int* dstIdx = ei + E;

    float *bufA, *bufB, *bufC, *dis;
    cudaGetSymbolAddress((void**)&bufA, g_bufA);
    cudaGetSymbolAddress((void**)&bufB, g_bufB);
    cudaGetSymbolAddress((void**)&bufC, g_bufC);
    cudaGetSymbolAddress((void**)&dis,  g_dis);

    cudaFuncSetAttribute(k_mma_gemm, cudaFuncAttributeMaxDynamicSharedMemorySize, SMB);

    // ---- degree / normalization ----
    k_init_deg <<<(N + 255) / 256, 256>>>(dis, N);
    k_count_deg<<<(E + 255) / 256, 256>>>(dis, dstIdx, E);
    k_rsqrt_deg<<<(N + 255) / 256, 256>>>(dis, N);

    const int mTilesN = (N + 127) / 128;   // 1563
    const int mTilesG = (G + 127) / 128;   // 40
    const int scatBlocks = (int)(((long long)E * 32 + 255) / 256);

    // ---- conv1: x[N,40] @ W1^T -> H1(bufA), AGG1(bufB) ----
    k_mma_gemm<<<dim3(1, mTilesN, 1), 256, SMB>>>(
        x, W1, bufA, bufB, b1, dis, N, 128, 40, 64, 0, 1);
    k_scatter<128><<<scatBlocks, 256>>>(bufA, bufB, srcIdx, dstIdx, dis, E);

    // ---- conv2: lrelu(AGG1)[N,128] @ W2^T -> H2(bufA), AGG2(bufC) ----
    k_mma_gemm<<<dim3(2, mTilesN, 1), 256, SMB>>>(
        bufB, W2, bufA, bufC, b2, dis, N, 256, 128, 128, 1, 1);
    k_scatter<256><<<scatBlocks, 256>>>(bufA, bufC, srcIdx, dstIdx, dis, E);

    // ---- conv3: lrelu(AGG2)[N,256] @ W3^T -> H3(bufA), AGG3(bufB) ----
    k_mma_gemm<<<dim3(1, mTilesN, 1), 256, SMB>>>(
        bufC, W3, bufA, bufB, b3, dis, N, 128, 256, 256, 1, 1);
    k_scatter<128><<<scatBlocks, 256>>>(bufA, bufB, srcIdx, dstIdx, dis, E);

    // ---- MLP ----
    // L1: lrelu(AGG3).reshape(G,5120) @ L1w^T + L1b -> bufA [G,512], split-K x4
    k_fill_bias<<<(G * 512 + 255) / 256, 256>>>(bufA, L1b, G, 512);
    k_mma_gemm<<<dim3(4, mTilesG, 4), 256, SMB>>>(
        bufB, L1w, bufA, nullptr, nullptr, nullptr, G, 512, 5120, 1280, 1, 4);
    // L2: lrelu(g1) @ L2w^T + L2b -> bufC [G,128], split-K x4
    k_fill_bias<<<(G * 128 + 255) / 256, 256>>>(bufC, L2b, G, 128);
    k_mma_gemm<<<dim3(1, mTilesG, 4), 256, SMB>>>(
        bufA, L2w, bufC, nullptr, nullptr, nullptr, G, 128, 512, 128, 1, 4);
    // L3 + sigmoid
    k_mlp_out<<<(G * 32 + 255) / 256, 256>>>(bufC, L3w, L3b, out, G);
}

// round 7
// speedup vs baseline: 2.2997x; 1.3077x over previous
#include <cuda_runtime.h>
#include <cuda_bf16.h>
#include <math.h>
#include <stdint.h>

// ---------------------------------------------------------------------------
// GCN: 3x GCNConv(+lrelu) -> reshape(40/graph) -> 3x Linear -> sigmoid
// GEMMs via mma.sync m16n8k16 bf16 with bf16x3 fp32 emulation.
// Aggregate-first for conv1/conv2 (scatter on the narrower side),
// transform-first for conv3. Weights pre-split into bf16 hi/lo once.
// ---------------------------------------------------------------------------

#define TILE_M 128
#define TILE_N 128
#define KC 32                      // k-chunk
#define SROW 80                    // smem row stride bytes
#define STG_BYTES (128 * SROW)     // per stage per array

#define OFF_AH 0
#define OFF_AL (2 * STG_BYTES)
#define OFF_WH (4 * STG_BYTES)
#define OFF_WL (6 * STG_BYTES)
#define SMB    (8 * STG_BYTES)     // 81920 bytes

__device__ __align__(256) float g_bufA[(size_t)200000 * 256];
__device__ __align__(256) float g_bufB[(size_t)200000 * 256];
__device__ __align__(256) float g_bufC[(size_t)200000 * 256];
__device__ __align__(256) float g_dis[200000];
__device__ __align__(256) __nv_bfloat16 g_whi[2760000];
__device__ __align__(256) __nv_bfloat16 g_wlo[2760000];

__device__ __forceinline__ float lrelu_f(float v) { return v > 0.f ? v : 0.1f * v; }

__device__ __forceinline__ uint32_t smem_u32(const void* p) {
    uint32_t a;
    asm("{ .reg .u64 t; cvta.to.shared.u64 t, %1; cvt.u32.u64 %0, t; }" : "=r"(a) : "l"(p));
    return a;
}
__device__ __forceinline__ uint32_t lds32(uint32_t a) {
    uint32_t v;
    asm volatile("ld.shared.b32 %0, [%1];" : "=r"(v) : "r"(a));
    return v;
}
__device__ __forceinline__ void mma16816(float* c, const uint32_t* a, const uint32_t* b) {
    asm volatile(
        "mma.sync.aligned.m16n8k16.row.col.f32.bf16.bf16.f32 "
        "{%0,%1,%2,%3}, {%4,%5,%6,%7}, {%8,%9}, {%0,%1,%2,%3};"
        : "+f"(c[0]), "+f"(c[1]), "+f"(c[2]), "+f"(c[3])
        : "r"(a[0]), "r"(a[1]), "r"(a[2]), "r"(a[3]), "r"(b[0]), "r"(b[1]));
}
__device__ __forceinline__ uint32_t packbf(float x, float y) {
    __nv_bfloat16 hx = __float2bfloat16_rn(x), hy = __float2bfloat16_rn(y);
    return (uint32_t)__bfloat16_as_ushort(hx) | ((uint32_t)__bfloat16_as_ushort(hy) << 16);
}

// ---------------------------- small kernels --------------------------------
__global__ void k_init_deg(float* deg, int n) {
    int i = blockIdx.x * blockDim.x + threadIdx.x;
    if (i < n) deg[i] = 1.0f;
}
__global__ void k_count_deg(float* deg, const int* __restrict__ dst, int E) {
    int e = blockIdx.x * blockDim.x + threadIdx.x;
    if (e < E) atomicAdd(&deg[dst[e]], 1.0f);
}
__global__ void k_rsqrt_deg(float* deg, int n) {
    int i = blockIdx.x * blockDim.x + threadIdx.x;
    if (i < n) deg[i] = rsqrtf(deg[i]);
}
__global__ void k_fill_bias(float* __restrict__ H, const float* __restrict__ b,
                            int M, int N) {
    int i = blockIdx.x * blockDim.x + threadIdx.x;
    if (i < M * N) H[i] = b[i % N];
}
// out[i] = in[i] * dis[i / F]^2   (self-loop init for aggregate-first)
__global__ void k_rowscale(const float* __restrict__ in, float* __restrict__ out,
                           const float* __restrict__ dis, int total, int F) {
    int i = blockIdx.x * blockDim.x + threadIdx.x;
    if (i < total) { float d = dis[i / F]; out[i] = in[i] * d * d; }
}
// split fp32 weights into bf16 hi/lo
__global__ void k_convW(const float* __restrict__ W, __nv_bfloat16* __restrict__ hi,
                        __nv_bfloat16* __restrict__ lo, int n) {
    int i = blockIdx.x * blockDim.x + threadIdx.x;
    if (i < n) {
        float v = W[i];
        __nv_bfloat16 h = __float2bfloat16_rn(v);
        hi[i] = h;
        lo[i] = __float2bfloat16_rn(v - __bfloat162float(h));
    }
}

// ------------------------ tensor-core bf16x3 GEMM ---------------------------
// C = act(A) @ W^T ; A:[M,K] fp32 row-major; W pre-split bf16 hi/lo [Nout,K].
// Epilogue: r2 = r + bias[col]; h = lreluOut ? lrelu(r2) : r2; H = h;
//           if AGG: AGG = h*dis[row]^2 + aggb[col].
// kSplit>1: atomicAdd partials into pre-initialized H (bias/act disabled).
__global__ void __launch_bounds__(256, 2)
k_mma_gemm(const float* __restrict__ A,
           const __nv_bfloat16* __restrict__ Whi, const __nv_bfloat16* __restrict__ Wlo,
           float* __restrict__ H, float* __restrict__ AGG,
           const float* __restrict__ bias, const float* __restrict__ aggb,
           const float* __restrict__ dis,
           int M, int Nout, int K, int kLen, int applyLrelu, int lreluOut, int kSplit)
{
    extern __shared__ char smem[];
    const uint32_t sb = smem_u32(smem);
    const int tid  = threadIdx.x;
    const int wid  = tid >> 5;
    const int lane = tid & 31;
    const int g    = lane >> 2;
    const int tig  = lane & 3;
    const int warpM = wid >> 1;
    const int warpN = wid & 1;
    const int mBase = blockIdx.y * TILE_M;
    const int nBase = blockIdx.x * TILE_N;
    const long long zOff = (long long)blockIdx.z * kLen;

    float acc[2][8][4];
#pragma unroll
    for (int i = 0; i < 2; i++)
#pragma unroll
        for (int j = 0; j < 8; j++)
#pragma unroll
            for (int q = 0; q < 4; q++) acc[i][j][q] = 0.f;

    auto loadStage = [&](int stg, int kb) {
        const int so = stg * STG_BYTES;
        // ---- A tile: 128 x 32 fp32 -> hi/lo bf16 ----
#pragma unroll
        for (int q = tid; q < 1024; q += 256) {
            int row = q >> 3, kq = q & 7;
            long long gk = zOff + kb + kq * 4;
            int gm = mBase + row;
            float4 v = make_float4(0.f, 0.f, 0.f, 0.f);
            if (gm < M && gk + 4 <= (long long)K)
                v = *(const float4*)(A + (long long)gm * K + gk);
            if (applyLrelu) {
                v.x = lrelu_f(v.x); v.y = lrelu_f(v.y);
                v.z = lrelu_f(v.z); v.w = lrelu_f(v.w);
            }
            __nv_bfloat16 h0 = __float2bfloat16_rn(v.x), h1 = __float2bfloat16_rn(v.y);
            __nv_bfloat16 h2 = __float2bfloat16_rn(v.z), h3 = __float2bfloat16_rn(v.w);
            uint32_t hiA = (uint32_t)__bfloat16_as_ushort(h0) | ((uint32_t)__bfloat16_as_ushort(h1) << 16);
            uint32_t hiB = (uint32_t)__bfloat16_as_ushort(h2) | ((uint32_t)__bfloat16_as_ushort(h3) << 16);
            uint32_t loA = packbf(v.x - __bfloat162float(h0), v.y - __bfloat162float(h1));
            uint32_t loB = packbf(v.z - __bfloat162float(h2), v.w - __bfloat162float(h3));
            uint32_t off = so + row * SROW + kq * 8;
            *(uint2*)(smem + OFF_AH + off) = make_uint2(hiA, hiB);
            *(uint2*)(smem + OFF_AL + off) = make_uint2(loA, loB);
        }
        // ---- W tile: pre-converted bf16, straight copy ----
#pragma unroll
        for (int q = tid; q < 1024; q += 256) {
            int row = q >> 3, kq = q & 7;
            long long gk = zOff + kb + kq * 4;
            uint2 hv = make_uint2(0u, 0u), lv = make_uint2(0u, 0u);
            if (gk + 4 <= (long long)K) {
                long long woff = (long long)(nBase + row) * K + gk;
                hv = *(const uint2*)(Whi + woff);
                lv = *(const uint2*)(Wlo + woff);
            }
            uint32_t off = so + row * SROW + kq * 8;
            *(uint2*)(smem + OFF_WH + off) = hv;
            *(uint2*)(smem + OFF_WL + off) = lv;
        }
    };

    loadStage(0, 0);
    __syncthreads();

    int s = 0;
    for (int kb = 0; kb < kLen; kb += KC) {
        if (kb + KC < kLen) loadStage(s ^ 1, kb + KC);

        const uint32_t so = (uint32_t)(s * STG_BYTES);
#pragma unroll
        for (int kk = 0; kk < 2; kk++) {
            const uint32_t kcb = (uint32_t)((kk * 16 + 2 * tig) * 2);
            uint32_t ah[2][4], alo[2][4];
#pragma unroll
            for (int ms = 0; ms < 2; ms++) {
                uint32_t base = sb + so + (uint32_t)((warpM * 32 + ms * 16 + g) * SROW) + kcb;
                ah[ms][0]  = lds32(base + OFF_AH);
                ah[ms][1]  = lds32(base + OFF_AH + 8 * SROW);
                ah[ms][2]  = lds32(base + OFF_AH + 16);
                ah[ms][3]  = lds32(base + OFF_AH + 8 * SROW + 16);
                alo[ms][0] = lds32(base + OFF_AL);
                alo[ms][1] = lds32(base + OFF_AL + 8 * SROW);
                alo[ms][2] = lds32(base + OFF_AL + 16);
                alo[ms][3] = lds32(base + OFF_AL + 8 * SROW + 16);
            }
#pragma unroll
            for (int nh = 0; nh < 2; nh++) {
                uint32_t bh[4][2], blo[4][2];
#pragma unroll
                for (int j = 0; j < 4; j++) {
                    int ns = nh * 4 + j;
                    uint32_t base = sb + so + (uint32_t)((warpN * 64 + ns * 8 + g) * SROW) + kcb;
                    bh[j][0]  = lds32(base + OFF_WH);
                    bh[j][1]  = lds32(base + OFF_WH + 16);
                    blo[j][0] = lds32(base + OFF_WL);
                    blo[j][1] = lds32(base + OFF_WL + 16);
                }
#pragma unroll
                for (int ms = 0; ms < 2; ms++)
#pragma unroll
                    for (int j = 0; j < 4; j++) {
                        float* c = acc[ms][nh * 4 + j];
                        mma16816(c, ah[ms],  bh[j]);
                        mma16816(c, ah[ms],  blo[j]);
                        mma16816(c, alo[ms], bh[j]);
                    }
            }
        }
        __syncthreads();
        s ^= 1;
    }

    // ---- epilogue ----
    const int mW = mBase + warpM * 32;
#pragma unroll
    for (int ms = 0; ms < 2; ms++) {
#pragma unroll
        for (int half = 0; half < 2; half++) {
            int row = mW + ms * 16 + g + half * 8;
            if (row >= M) continue;
            float d2 = 0.f;
            if (AGG != nullptr) { float dv = dis[row]; d2 = dv * dv; }
            long long ro = (long long)row * Nout;
#pragma unroll
            for (int ns = 0; ns < 8; ns++) {
                int col = nBase + warpN * 64 + ns * 8 + 2 * tig;
                float c0 = acc[ms][ns][half * 2 + 0];
                float c1 = acc[ms][ns][half * 2 + 1];
                if (kSplit > 1) {
                    atomicAdd(&H[ro + col + 0], c0);
                    atomicAdd(&H[ro + col + 1], c1);
                } else {
                    if (bias) { c0 += __ldg(&bias[col]); c1 += __ldg(&bias[col + 1]); }
                    if (lreluOut) { c0 = lrelu_f(c0); c1 = lrelu_f(c1); }
                    *(float2*)(H + ro + col) = make_float2(c0, c1);
                    if (AGG) {
                        float a0 = c0 * d2, a1 = c1 * d2;
                        if (aggb) { a0 += __ldg(&aggb[col]); a1 += __ldg(&aggb[col + 1]); }
                        *(float2*)(AGG + ro + col) = make_float2(a0, a1);
                    }
                }
            }
        }
    }
}

// ----------------------------- edge scatter --------------------------------
// GSZ lanes per edge. AGG[dst] += H[src] * (dis[src]*dis[dst]).
template <int F, int GSZ>
__global__ void __launch_bounds__(256)
k_scatter(const float* __restrict__ H, float* __restrict__ AGG,
          const int* __restrict__ src, const int* __restrict__ dst,
          const float* __restrict__ dis, int E)
{
    int gidx = (int)(((long long)blockIdx.x * blockDim.x + threadIdx.x) / GSZ);
    int sub  = threadIdx.x & (GSZ - 1);
    if (gidx >= E) return;

    int s = src[gidx];
    int d = dst[gidx];
    float norm = dis[s] * dis[d];

    const float4* hs = (const float4*)(H + (long long)s * F);
    float*        ag = AGG + (long long)d * F;

#pragma unroll
    for (int i = sub; i < F / 4; i += GSZ) {
        float4 v = hs[i];
        atomicAdd(ag + i * 4 + 0, v.x * norm);
        atomicAdd(ag + i * 4 + 1, v.y * norm);
        atomicAdd(ag + i * 4 + 2, v.z * norm);
        atomicAdd(ag + i * 4 + 3, v.w * norm);
    }
}

// --------------------------- final linear + sigmoid -------------------------
__global__ void k_mlp_out(const float* __restrict__ g2, const float* __restrict__ L3w,
                          const float* __restrict__ L3b, float* __restrict__ out, int G)
{
    int w    = (blockIdx.x * blockDim.x + threadIdx.x) >> 5;
    int lane = threadIdx.x & 31;
    if (w >= G) return;
    float s = 0.f;
#pragma unroll
    for (int c = lane; c < 128; c += 32)
        s += lrelu_f(g2[(long long)w * 128 + c]) * __ldg(&L3w[c]);
#pragma unroll
    for (int off = 16; off; off >>= 1) s += __shfl_xor_sync(0xffffffffu, s, off);
    if (lane == 0) out[w] = 1.f / (1.f + expf(-(s + L3b[0])));
}

// ------------------------------- launch ------------------------------------
extern "C" void kernel_launch(void* const* d_in, const int* in_sizes, int n_in,
                              void* d_out, int out_size)
{
    const float* x   = (const float*)d_in[0];
    const int*   ei  = (const int*)d_in[1];
    const float* W1 = (const float*)d_in[2];  const float* b1 = (const float*)d_in[3];
    const float* W2 = (const float*)d_in[4];  const float* b2 = (const float*)d_in[5];
    const float* W3 = (const float*)d_in[6];  const float* b3 = (const float*)d_in[7];
    const float* L1w = (const float*)d_in[8];  const float* L1b = (const float*)d_in[9];
    const float* L2w = (const float*)d_in[10]; const float* L2b = (const float*)d_in[11];
    const float* L3w = (const float*)d_in[12]; const float* L3b = (const float*)d_in[13];
    float* out = (float*)d_out;

    const int C = 40;
    const int N = in_sizes[0] / C;     // 200000
    const int E = in_sizes[1] / 2;     // 1000000
    const int G = N / 40;              // 5000

    const int* srcIdx = ei;
    const int* dstIdx = ei + E;

    float *bufA, *bufB, *bufC, *dis;
    __nv_bfloat16 *whi, *wlo;
    cudaGetSymbolAddress((void**)&bufA, g_bufA);
    cudaGetSymbolAddress((void**)&bufB, g_bufB);
    cudaGetSymbolAddress((void**)&bufC, g_bufC);
    cudaGetSymbolAddress((void**)&dis,  g_dis);
    cudaGetSymbolAddress((void**)&whi,  g_whi);
    cudaGetSymbolAddress((void**)&wlo,  g_wlo);

    cudaFuncSetAttribute(k_mma_gemm, cudaFuncAttributeMaxDynamicSharedMemorySize, SMB);

    // weight offsets in the converted buffers
    const int O1 = 0;                       // W1: 128*40
    const int O2 = O1 + 128 * 40;           // W2: 256*128
    const int O3 = O2 + 256 * 128;          // W3: 128*256
    const int O4 = O3 + 128 * 256;          // L1w: 512*5120
    const int O5 = O4 + 512 * 5120;         // L2w: 128*512

    k_convW<<<(128 * 40   + 255) / 256, 256>>>(W1,  whi + O1, wlo + O1, 128 * 40);
    k_convW<<<(256 * 128  + 255) / 256, 256>>>(W2,  whi + O2, wlo + O2, 256 * 128);
    k_convW<<<(128 * 256  + 255) / 256, 256>>>(W3,  whi + O3, wlo + O3, 128 * 256);
    k_convW<<<(512 * 5120 + 255) / 256, 256>>>(L1w, whi + O4, wlo + O4, 512 * 5120);
    k_convW<<<(128 * 512  + 255) / 256, 256>>>(L2w, whi + O5, wlo + O5, 128 * 512);

    // ---- degree / normalization ----
    k_init_deg <<<(N + 255) / 256, 256>>>(dis, N);
    k_count_deg<<<(E + 255) / 256, 256>>>(dis, dstIdx, E);
    k_rsqrt_deg<<<(N + 255) / 256, 256>>>(dis, N);

    const int mTilesN = (N + 127) / 128;   // 1563
    const int mTilesG = (G + 127) / 128;   // 40

    // ---- conv1 (aggregate-first): A1 = Âx  -> bufC [N,40] ----
    k_rowscale<<<(N * 40 + 255) / 256, 256>>>(x, bufC, dis, N * 40, 40);
    k_scatter<40, 8><<<(int)(((long long)E * 8 + 255) / 256), 256>>>(
        x, bufC, srcIdx, dstIdx, dis, E);
    // GEMM1: P1 = lrelu(A1@W1^T + b1) -> bufA ; A2init = P1*dis^2 -> bufB
    k_mma_gemm<<<dim3(1, mTilesN, 1), 256, SMB>>>(
        bufC, whi + O1, wlo + O1, bufA, bufB, b1, nullptr, dis,
        N, 128, 40, 64, 0, 1, 1);

    // ---- conv2 (aggregate-first): A2 = ÂP1 -> bufB [N,128] ----
    k_scatter<128, 32><<<(int)(((long long)E * 32 + 255) / 256), 256>>>(
        bufA, bufB, srcIdx, dstIdx, dis, E);
    // GEMM2: conv2out(pre-act) = A2@W2^T + b2 -> bufC [N,256]
    k_mma_gemm<<<dim3(2, mTilesN, 1), 256, SMB>>>(
        bufB, whi + O2, wlo + O2, bufC, nullptr, b2, nullptr, dis,
        N, 256, 128, 128, 0, 0, 1);

    // ---- conv3 (transform-first): H3t = lrelu(conv2out)@W3^T -> bufA ----
    //      AGG3init = H3t*dis^2 + b3 -> bufB
    k_mma_gemm<<<dim3(1, mTilesN, 1), 256, SMB>>>(
        bufC, whi + O3, wlo + O3, bufA, bufB, nullptr, b3, dis,
        N, 128, 256, 256, 1, 0, 1);
    k_scatter<128, 32><<<(int)(((long long)E * 32 + 255) / 256), 256>>>(
        bufA, bufB, srcIdx, dstIdx, dis, E);

    // ---- MLP ----
    // L1: lrelu(AGG3).reshape(G,5120) @ L1w^T + L1b -> bufC [G,512], split-K x4
    k_fill_bias<<<(G * 512 + 255) / 256, 256>>>(bufC, L1b, G, 512);
    k_mma_gemm<<<dim3(4, mTilesG, 4), 256, SMB>>>(
        bufB, whi + O4, wlo + O4, bufC, nullptr, nullptr, nullptr, nullptr,
        G, 512, 5120, 1280, 1, 0, 4);
    // L2: lrelu(g1) @ L2w^T + L2b -> bufA [G,128], split-K x4
    k_fill_bias<<<(G * 128 + 255) / 256, 256>>>(bufA, L2b, G, 128);
    k_mma_gemm<<<dim3(1, mTilesG, 4), 256, SMB>>>(
        bufC, whi + O5, wlo + O5, bufA, nullptr, nullptr, nullptr, nullptr,
        G, 128, 512, 128, 1, 0, 4);
    // L3 + sigmoid
    k_mlp_out<<<(G * 32 + 255) / 256, 256>>>(bufA, L3w, L3b, out, G);
}

// round 8
// speedup vs baseline: 3.0889x; 1.3432x over previous
#include <cuda_runtime.h>
#include <cuda_bf16.h>
#include <math.h>
#include <stdint.h>

// ---------------------------------------------------------------------------
// GCN: 3x GCNConv(+lrelu) -> reshape(40/graph) -> 3x Linear -> sigmoid
// GEMMs via mma.sync m16n8k16 bf16 with bf16x3 fp32 emulation.
// Aggregation via dst-CSR gather (no float atomics).
// ---------------------------------------------------------------------------

#define TILE_M 128
#define TILE_N 128
#define KC 32
#define SROW 80
#define STG_BYTES (128 * SROW)

#define OFF_AH 0
#define OFF_AL (2 * STG_BYTES)
#define OFF_WH (4 * STG_BYTES)
#define OFF_WL (6 * STG_BYTES)
#define SMB    (8 * STG_BYTES)     // 81920 bytes

#define NMAX 200000
#define EMAX 1000000

__device__ __align__(256) float g_bufA[(size_t)NMAX * 256];
__device__ __align__(256) float g_bufB[(size_t)NMAX * 256];
__device__ __align__(256) float g_bufC[(size_t)NMAX * 256];
__device__ __align__(256) float g_dis[NMAX];
__device__ __align__(256) __nv_bfloat16 g_whi[2760000];
__device__ __align__(256) __nv_bfloat16 g_wlo[2760000];
__device__ __align__(256) int g_ptr[NMAX + 1];
__device__ __align__(256) int g_cursor[NMAX];
__device__ __align__(256) int g_csr[EMAX];
__device__ __align__(256) int g_bsum[256];

__device__ __forceinline__ float lrelu_f(float v) { return v > 0.f ? v : 0.1f * v; }

__device__ __forceinline__ uint32_t smem_u32(const void* p) {
    uint32_t a;
    asm("{ .reg .u64 t; cvta.to.shared.u64 t, %1; cvt.u32.u64 %0, t; }" : "=r"(a) : "l"(p));
    return a;
}
__device__ __forceinline__ uint32_t lds32(uint32_t a) {
    uint32_t v;
    asm volatile("ld.shared.b32 %0, [%1];" : "=r"(v) : "r"(a));
    return v;
}
__device__ __forceinline__ void mma16816(float* c, const uint32_t* a, const uint32_t* b) {
    asm volatile(
        "mma.sync.aligned.m16n8k16.row.col.f32.bf16.bf16.f32 "
        "{%0,%1,%2,%3}, {%4,%5,%6,%7}, {%8,%9}, {%0,%1,%2,%3};"
        : "+f"(c[0]), "+f"(c[1]), "+f"(c[2]), "+f"(c[3])
        : "r"(a[0]), "r"(a[1]), "r"(a[2]), "r"(a[3]), "r"(b[0]), "r"(b[1]));
}
__device__ __forceinline__ uint32_t packbf(float x, float y) {
    __nv_bfloat16 hx = __float2bfloat16_rn(x), hy = __float2bfloat16_rn(y);
    return (uint32_t)__bfloat16_as_ushort(hx) | ((uint32_t)__bfloat16_as_ushort(hy) << 16);
}

// --------------------------- CSR build kernels ------------------------------
__global__ void k_zero_int(int* p, int n) {
    int i = blockIdx.x * blockDim.x + threadIdx.x;
    if (i < n) p[i] = 0;
}
__global__ void k_hist(int* cnt, const int* __restrict__ dst, int E) {
    int e = blockIdx.x * blockDim.x + threadIdx.x;
    if (e < E) atomicAdd(&cnt[dst[e]], 1);
}
__global__ void k_deg_from_cnt(const int* __restrict__ cnt, float* __restrict__ dis, int n) {
    int i = blockIdx.x * blockDim.x + threadIdx.x;
    if (i < n) dis[i] = rsqrtf((float)cnt[i] + 1.0f);
}
// block-level inclusive scan (1024/block), writes exclusive prefix + block sums
__global__ void k_scan_block(const int* __restrict__ cnt, int* __restrict__ ptr,
                             int* __restrict__ bsum, int n) {
    __shared__ int sm[1024];
    int i = blockIdx.x * 1024 + threadIdx.x;
    int v = (i < n) ? cnt[i] : 0;
    sm[threadIdx.x] = v;
    __syncthreads();
    for (int off = 1; off < 1024; off <<= 1) {
        int t = (threadIdx.x >= off) ? sm[threadIdx.x - off] : 0;
        __syncthreads();
        sm[threadIdx.x] += t;
        __syncthreads();
    }
    if (i < n) ptr[i] = sm[threadIdx.x] - v;
    if (threadIdx.x == 1023) bsum[blockIdx.x] = sm[1023];
}
__global__ void k_scan_bsum(int* bsum, int nb, int* totalOut) {
    __shared__ int sm[256];
    int v = (threadIdx.x < nb) ? bsum[threadIdx.x] : 0;
    sm[threadIdx.x] = v;
    __syncthreads();
    for (int off = 1; off < 256; off <<= 1) {
        int t = (threadIdx.x >= off) ? sm[threadIdx.x - off] : 0;
        __syncthreads();
        sm[threadIdx.x] += t;
        __syncthreads();
    }
    if (threadIdx.x < nb) bsum[threadIdx.x] = sm[threadIdx.x] - v;
    if (threadIdx.x == 255) *totalOut = sm[255];
}
__global__ void k_scan_add(int* __restrict__ ptr, const int* __restrict__ bsum,
                           int* __restrict__ cursor, int n) {
    int i = blockIdx.x * blockDim.x + threadIdx.x;
    if (i < n) {
        int p = ptr[i] + bsum[i >> 10];
        ptr[i] = p;
        cursor[i] = p;
    }
}
__global__ void k_fill_csr(const int* __restrict__ src, const int* __restrict__ dst,
                           int* cursor, int* __restrict__ csr, int E) {
    int e = blockIdx.x * blockDim.x + threadIdx.x;
    if (e < E) {
        int pos = atomicAdd(&cursor[dst[e]], 1);
        csr[pos] = src[e];
    }
}

// ---------------------------- misc small kernels ----------------------------
__global__ void k_fill_bias(float* __restrict__ H, const float* __restrict__ b,
                            int M, int N) {
    int i = blockIdx.x * blockDim.x + threadIdx.x;
    if (i < M * N) H[i] = b[i % N];
}
__global__ void k_rowscale(const float* __restrict__ in, float* __restrict__ out,
                           const float* __restrict__ dis, int total, int F) {
    int i = blockIdx.x * blockDim.x + threadIdx.x;
    if (i < total) { float d = dis[i / F]; out[i] = in[i] * d * d; }
}
__global__ void k_convW(const float* __restrict__ W, __nv_bfloat16* __restrict__ hi,
                        __nv_bfloat16* __restrict__ lo, int n) {
    int i = blockIdx.x * blockDim.x + threadIdx.x;
    if (i < n) {
        float v = W[i];
        __nv_bfloat16 h = __float2bfloat16_rn(v);
        hi[i] = h;
        lo[i] = __float2bfloat16_rn(v - __bfloat162float(h));
    }
}

// ------------------------------ CSR gather ----------------------------------
// One warp per node: AGG[node] (pre-initialized with self-loop+bias) +=
// sum_{e in CSR[node]} H[src_e] * (dis[node]*dis[src_e]).
template <int F>
__global__ void __launch_bounds__(256)
k_gather(const float* __restrict__ H, float* __restrict__ AGG,
         const int* __restrict__ ptr, const int* __restrict__ csr,
         const float* __restrict__ dis, int Nn)
{
    int node = (int)(((long long)blockIdx.x * blockDim.x + threadIdx.x) >> 5);
    int lane = threadIdx.x & 31;
    if (node >= Nn) return;

    int p0 = ptr[node];
    int p1 = ptr[node + 1];
    float dn = dis[node];

    if (F == 128) {
        float4 acc = *(const float4*)(AGG + (long long)node * 128 + lane * 4);
        int p = p0;
        for (; p + 1 < p1; p += 2) {
            int s0 = csr[p], s1 = csr[p + 1];
            float n0 = dn * dis[s0], n1 = dn * dis[s1];
            float4 v0 = *(const float4*)(H + (long long)s0 * 128 + lane * 4);
            float4 v1 = *(const float4*)(H + (long long)s1 * 128 + lane * 4);
            acc.x += v0.x * n0; acc.y += v0.y * n0;
            acc.z += v0.z * n0; acc.w += v0.w * n0;
            acc.x += v1.x * n1; acc.y += v1.y * n1;
            acc.z += v1.z * n1; acc.w += v1.w * n1;
        }
        if (p < p1) {
            int s0 = csr[p];
            float n0 = dn * dis[s0];
            float4 v0 = *(const float4*)(H + (long long)s0 * 128 + lane * 4);
            acc.x += v0.x * n0; acc.y += v0.y * n0;
            acc.z += v0.z * n0; acc.w += v0.w * n0;
        }
        *(float4*)(AGG + (long long)node * 128 + lane * 4) = acc;
    } else {  // F == 40: lane owns col lane, and col 32+lane for lane<8
        long long base = (long long)node * 40;
        float a0 = AGG[base + lane];
        float a1 = (lane < 8) ? AGG[base + 32 + lane] : 0.f;
        for (int p = p0; p < p1; p++) {
            int s = csr[p];
            float nm = dn * dis[s];
            long long hb = (long long)s * 40;
            a0 += H[hb + lane] * nm;
            if (lane < 8) a1 += H[hb + 32 + lane] * nm;
        }
        AGG[base + lane] = a0;
        if (lane < 8) AGG[base + 32 + lane] = a1;
    }
}

// ------------------------ tensor-core bf16x3 GEMM ---------------------------
__global__ void __launch_bounds__(256, 2)
k_mma_gemm(const float* __restrict__ A,
           const __nv_bfloat16* __restrict__ Whi, const __nv_bfloat16* __restrict__ Wlo,
           float* __restrict__ H, float* __restrict__ AGG,
           const float* __restrict__ bias, const float* __restrict__ aggb,
           const float* __restrict__ dis,
           int M, int Nout, int K, int kLen, int applyLrelu, int lreluOut, int kSplit)
{
    extern __shared__ char smem[];
    const uint32_t sb = smem_u32(smem);
    const int tid  = threadIdx.x;
    const int wid  = tid >> 5;
    const int lane = tid & 31;
    const int g    = lane >> 2;
    const int tig  = lane & 3;
    const int warpM = wid >> 1;
    const int warpN = wid & 1;
    const int mBase = blockIdx.y * TILE_M;
    const int nBase = blockIdx.x * TILE_N;
    const long long zOff = (long long)blockIdx.z * kLen;

    float acc[2][8][4];
#pragma unroll
    for (int i = 0; i < 2; i++)
#pragma unroll
        for (int j = 0; j < 8; j++)
#pragma unroll
            for (int q = 0; q < 4; q++) acc[i][j][q] = 0.f;

    auto loadStage = [&](int stg, int kb) {
        const int so = stg * STG_BYTES;
#pragma unroll
        for (int q = tid; q < 1024; q += 256) {
            int row = q >> 3, kq = q & 7;
            long long gk = zOff + kb + kq * 4;
            int gm = mBase + row;
            float4 v = make_float4(0.f, 0.f, 0.f, 0.f);
            if (gm < M && gk + 4 <= (long long)K)
                v = *(const float4*)(A + (long long)gm * K + gk);
            if (applyLrelu) {
                v.x = lrelu_f(v.x); v.y = lrelu_f(v.y);
                v.z = lrelu_f(v.z); v.w = lrelu_f(v.w);
            }
            __nv_bfloat16 h0 = __float2bfloat16_rn(v.x), h1 = __float2bfloat16_rn(v.y);
            __nv_bfloat16 h2 = __float2bfloat16_rn(v.z), h3 = __float2bfloat16_rn(v.w);
            uint32_t hiA = (uint32_t)__bfloat16_as_ushort(h0) | ((uint32_t)__bfloat16_as_ushort(h1) << 16);
            uint32_t hiB = (uint32_t)__bfloat16_as_ushort(h2) | ((uint32_t)__bfloat16_as_ushort(h3) << 16);
            uint32_t loA = packbf(v.x - __bfloat162float(h0), v.y - __bfloat162float(h1));
            uint32_t loB = packbf(v.z - __bfloat162float(h2), v.w - __bfloat162float(h3));
            uint32_t off = so + row * SROW + kq * 8;
            *(uint2*)(smem + OFF_AH + off) = make_uint2(hiA, hiB);
            *(uint2*)(smem + OFF_AL + off) = make_uint2(loA, loB);
        }
#pragma unroll
        for (int q = tid; q < 1024; q += 256) {
            int row = q >> 3, kq = q & 7;
            long long gk = zOff + kb + kq * 4;
            uint2 hv = make_uint2(0u, 0u), lv = make_uint2(0u, 0u);
            if (gk + 4 <= (long long)K) {
                long long woff = (long long)(nBase + row) * K + gk;
                hv = *(const uint2*)(Whi + woff);
                lv = *(const uint2*)(Wlo + woff);
            }
            uint32_t off = so + row * SROW + kq * 8;
            *(uint2*)(smem + OFF_WH + off) = hv;
            *(uint2*)(smem + OFF_WL + off) = lv;
        }
    };

    loadStage(0, 0);
    __syncthreads();

    int s = 0;
    for (int kb = 0; kb < kLen; kb += KC) {
        if (kb + KC < kLen) loadStage(s ^ 1, kb + KC);

        const uint32_t so = (uint32_t)(s * STG_BYTES);
#pragma unroll
        for (int kk = 0; kk < 2; kk++) {
            const uint32_t kcb = (uint32_t)((kk * 16 + 2 * tig) * 2);
            uint32_t ah[2][4], alo[2][4];
#pragma unroll
            for (int ms = 0; ms < 2; ms++) {
                uint32_t base = sb + so + (uint32_t)((warpM * 32 + ms * 16 + g) * SROW) + kcb;
                ah[ms][0]  = lds32(base + OFF_AH);
                ah[ms][1]  = lds32(base + OFF_AH + 8 * SROW);
                ah[ms][2]  = lds32(base + OFF_AH + 16);
                ah[ms][3]  = lds32(base + OFF_AH + 8 * SROW + 16);
                alo[ms][0] = lds32(base + OFF_AL);
                alo[ms][1] = lds32(base + OFF_AL + 8 * SROW);
                alo[ms][2] = lds32(base + OFF_AL + 16);
                alo[ms][3] = lds32(base + OFF_AL + 8 * SROW + 16);
            }
#pragma unroll
            for (int nh = 0; nh < 2; nh++) {
                uint32_t bh[4][2], blo[4][2];
#pragma unroll
                for (int j = 0; j < 4; j++) {
                    int ns = nh * 4 + j;
                    uint32_t base = sb + so + (uint32_t)((warpN * 64 + ns * 8 + g) * SROW) + kcb;
                    bh[j][0]  = lds32(base + OFF_WH);
                    bh[j][1]  = lds32(base + OFF_WH + 16);
                    blo[j][0] = lds32(base + OFF_WL);
                    blo[j][1] = lds32(base + OFF_WL + 16);
                }
#pragma unroll
                for (int ms = 0; ms < 2; ms++)
#pragma unroll
                    for (int j = 0; j < 4; j++) {
                        float* c = acc[ms][nh * 4 + j];
                        mma16816(c, ah[ms],  bh[j]);
                        mma16816(c, ah[ms],  blo[j]);
                        mma16816(c, alo[ms], bh[j]);
                    }
            }
        }
        __syncthreads();
        s ^= 1;
    }

    const int mW = mBase + warpM * 32;
#pragma unroll
    for (int ms = 0; ms < 2; ms++) {
#pragma unroll
        for (int half = 0; half < 2; half++) {
            int row = mW + ms * 16 + g + half * 8;
            if (row >= M) continue;
            float d2 = 0.f;
            if (AGG != nullptr) { float dv = dis[row]; d2 = dv * dv; }
            long long ro = (long long)row * Nout;
#pragma unroll
            for (int ns = 0; ns < 8; ns++) {
                int col = nBase + warpN * 64 + ns * 8 + 2 * tig;
                float c0 = acc[ms][ns][half * 2 + 0];
                float c1 = acc[ms][ns][half * 2 + 1];
                if (kSplit > 1) {
                    atomicAdd(&H[ro + col + 0], c0);
                    atomicAdd(&H[ro + col + 1], c1);
                } else {
                    if (bias) { c0 += __ldg(&bias[col]); c1 += __ldg(&bias[col + 1]); }
                    if (lreluOut) { c0 = lrelu_f(c0); c1 = lrelu_f(c1); }
                    *(float2*)(H + ro + col) = make_float2(c0, c1);
                    if (AGG) {
                        float a0 = c0 * d2, a1 = c1 * d2;
                        if (aggb) { a0 += __ldg(&aggb[col]); a1 += __ldg(&aggb[col + 1]); }
                        *(float2*)(AGG + ro + col) = make_float2(a0, a1);
                    }
                }
            }
        }
    }
}

// --------------------------- final linear + sigmoid -------------------------
__global__ void k_mlp_out(const float* __restrict__ g2, const float* __restrict__ L3w,
                          const float* __restrict__ L3b, float* __restrict__ out, int G)
{
    int w    = (blockIdx.x * blockDim.x + threadIdx.x) >> 5;
    int lane = threadIdx.x & 31;
    if (w >= G) return;
    float s = 0.f;
#pragma unroll
    for (int c = lane; c < 128; c += 32)
        s += lrelu_f(g2[(long long)w * 128 + c]) * __ldg(&L3w[c]);
#pragma unroll
    for (int off = 16; off; off >>= 1) s += __shfl_xor_sync(0xffffffffu, s, off);
    if (lane == 0) out[w] = 1.f / (1.f + expf(-(s + L3b[0])));
}

// ------------------------------- launch ------------------------------------
extern "C" void kernel_launch(void* const* d_in, const int* in_sizes, int n_in,
                              void* d_out, int out_size)
{
    const float* x   = (const float*)d_in[0];
    const int*   ei  = (const int*)d_in[1];
    const float* W1 = (const float*)d_in[2];  const float* b1 = (const float*)d_in[3];
    const float* W2 = (const float*)d_in[4];  const float* b2 = (const float*)d_in[5];
    const float* W3 = (const float*)d_in[6];  const float* b3 = (const float*)d_in[7];
    const float* L1w = (const float*)d_in[8];  const float* L1b = (const float*)d_in[9];
    const float* L2w = (const float*)d_in[10]; const float* L2b = (const float*)d_in[11];
    const float* L3w = (const float*)d_in[12]; const float* L3b = (const float*)d_in[13];
    float* out = (float*)d_out;

    const int C = 40;
    const int N = in_sizes[0] / C;     // 200000
    const int E = in_sizes[1] / 2;     // 1000000
    const int G = N / 40;              // 5000

    const int* srcIdx = ei;
    const int* dstIdx = ei + E;

    float *bufA, *bufB, *bufC, *dis;
    __nv_bfloat16 *whi, *wlo;
    int *ptr, *cursor, *csr, *bsum;
    cudaGetSymbolAddress((void**)&bufA, g_bufA);
    cudaGetSymbolAddress((void**)&bufB, g_bufB);
    cudaGetSymbolAddress((void**)&bufC, g_bufC);
    cudaGetSymbolAddress((void**)&dis,  g_dis);
    cudaGetSymbolAddress((void**)&whi,  g_whi);
    cudaGetSymbolAddress((void**)&wlo,  g_wlo);
    cudaGetSymbolAddress((void**)&ptr,    g_ptr);
    cudaGetSymbolAddress((void**)&cursor, g_cursor);
    cudaGetSymbolAddress((void**)&csr,    g_csr);
    cudaGetSymbolAddress((void**)&bsum,   g_bsum);

    cudaFuncSetAttribute(k_mma_gemm, cudaFuncAttributeMaxDynamicSharedMemorySize, SMB);

    const int O1 = 0;
    const int O2 = O1 + 128 * 40;
    const int O3 = O2 + 256 * 128;
    const int O4 = O3 + 128 * 256;
    const int O5 = O4 + 512 * 5120;

    k_convW<<<(128 * 40   + 255) / 256, 256>>>(W1,  whi + O1, wlo + O1, 128 * 40);
    k_convW<<<(256 * 128  + 255) / 256, 256>>>(W2,  whi + O2, wlo + O2, 256 * 128);
    k_convW<<<(128 * 256  + 255) / 256, 256>>>(W3,  whi + O3, wlo + O3, 128 * 256);
    k_convW<<<(512 * 5120 + 255) / 256, 256>>>(L1w, whi + O4, wlo + O4, 512 * 5120);
    k_convW<<<(128 * 512  + 255) / 256, 256>>>(L2w, whi + O5, wlo + O5, 128 * 512);

    // ---- CSR build + degree normalization ----
    const int nb = (N + 1023) / 1024;            // 196
    k_zero_int <<<(N + 255) / 256, 256>>>(cursor, N);
    k_hist     <<<(E + 255) / 256, 256>>>(cursor, dstIdx, E);
    k_deg_from_cnt<<<(N + 255) / 256, 256>>>(cursor, dis, N);
    k_scan_block<<<nb, 1024>>>(cursor, ptr, bsum, N);
    k_scan_bsum <<<1, 256>>>(bsum, nb, ptr + N);
    k_scan_add  <<<(N + 255) / 256, 256>>>(ptr, bsum, cursor, N);
    k_fill_csr  <<<(E + 255) / 256, 256>>>(srcIdx, dstIdx, cursor, csr, E);

    const int mTilesN = (N + 127) / 128;   // 1563
    const int mTilesG = (G + 127) / 128;   // 40
    const int gatherBlocks = (int)(((long long)N * 32 + 255) / 256);

    // ---- conv1 (aggregate-first): A1 = Âx -> bufC [N,40] ----
    k_rowscale<<<(N * 40 + 255) / 256, 256>>>(x, bufC, dis, N * 40, 40);
    k_gather<40><<<gatherBlocks, 256>>>(x, bufC, ptr, csr, dis, N);
    // GEMM1: P1 = lrelu(A1@W1^T + b1) -> bufA ; A2init = P1*dis^2 -> bufB
    k_mma_gemm<<<dim3(1, mTilesN, 1), 256, SMB>>>(
        bufC, whi + O1, wlo + O1, bufA, bufB, b1, nullptr, dis,
        N, 128, 40, 64, 0, 1, 1);

    // ---- conv2 (aggregate-first): A2 = ÂP1 -> bufB [N,128] ----
    k_gather<128><<<gatherBlocks, 256>>>(bufA, bufB, ptr, csr, dis, N);
    // GEMM2: conv2out(pre-act) = A2@W2^T + b2 -> bufC [N,256]
    k_mma_gemm<<<dim3(2, mTilesN, 1), 256, SMB>>>(
        bufB, whi + O2, wlo + O2, bufC, nullptr, b2, nullptr, dis,
        N, 256, 128, 128, 0, 0, 1);

    // ---- conv3 (transform-first): H3t = lrelu(conv2out)@W3^T -> bufA ----
    //      AGG3init = H3t*dis^2 + b3 -> bufB
    k_mma_gemm<<<dim3(1, mTilesN, 1), 256, SMB>>>(
        bufC, whi + O3, wlo + O3, bufA, bufB, nullptr, b3, dis,
        N, 128, 256, 256, 1, 0, 1);
    k_gather<128><<<gatherBlocks, 256>>>(bufA, bufB, ptr, csr, dis, N);

    // ---- MLP ----
    k_fill_bias<<<(G * 512 + 255) / 256, 256>>>(bufC, L1b, G, 512);
    k_mma_gemm<<<dim3(4, mTilesG, 4), 256, SMB>>>(
        bufB, whi + O4, wlo + O4, bufC, nullptr, nullptr, nullptr, nullptr,
        G, 512, 5120, 1280, 1, 0, 4);
    k_fill_bias<<<(G * 128 + 255) / 256, 256>>>(bufA, L2b, G, 128);
    k_mma_gemm<<<dim3(1, mTilesG, 4), 256, SMB>>>(
        bufC, whi + O5, wlo + O5, bufA, nullptr, nullptr, nullptr, nullptr,
        G, 128, 512, 128, 1, 0, 4);
    k_mlp_out<<<(G * 32 + 255) / 256, 256>>>(bufA, L3w, L3b, out, G);
}

// round 9
// speedup vs baseline: 3.6358x; 1.1771x over previous
#include <cuda_runtime.h>
#include <cuda_bf16.h>
#include <math.h>
#include <stdint.h>

// ---------------------------------------------------------------------------
// GCN: 3x GCNConv(+lrelu) -> reshape(40/graph) -> 3x Linear -> sigmoid
// GEMMs: mma.sync m16n8k16 bf16x3 emulation, ldmatrix fragment loads.
// Aggregation: dst-CSR gather (no float atomics).
// ---------------------------------------------------------------------------

#define TILE_M 128
#define TILE_N 128
#define KC 32
#define SROW 80
#define STG_BYTES (128 * SROW)

#define OFF_AH 0
#define OFF_AL (2 * STG_BYTES)
#define OFF_WH (4 * STG_BYTES)
#define OFF_WL (6 * STG_BYTES)
#define SMB    (8 * STG_BYTES)     // 81920 bytes

#define NMAX 200000
#define EMAX 1000000

__device__ __align__(256) float g_bufA[(size_t)NMAX * 256];
__device__ __align__(256) float g_bufB[(size_t)NMAX * 256];
__device__ __align__(256) float g_bufC[(size_t)NMAX * 256];
__device__ __align__(256) float g_dis[NMAX];
__device__ __align__(256) __nv_bfloat16 g_whi[2760000];
__device__ __align__(256) __nv_bfloat16 g_wlo[2760000];
__device__ __align__(256) int g_ptr[NMAX + 1];
__device__ __align__(256) int g_cursor[NMAX];
__device__ __align__(256) int g_csr[EMAX];
__device__ __align__(256) int g_bsum[256];

__device__ __forceinline__ float lrelu_f(float v) { return v > 0.f ? v : 0.1f * v; }

__device__ __forceinline__ uint32_t smem_u32(const void* p) {
    uint32_t a;
    asm("{ .reg .u64 t; cvta.to.shared.u64 t, %1; cvt.u32.u64 %0, t; }" : "=r"(a) : "l"(p));
    return a;
}
__device__ __forceinline__ void mma16816(float* c, const uint32_t* a, const uint32_t* b) {
    asm volatile(
        "mma.sync.aligned.m16n8k16.row.col.f32.bf16.bf16.f32 "
        "{%0,%1,%2,%3}, {%4,%5,%6,%7}, {%8,%9}, {%0,%1,%2,%3};"
        : "+f"(c[0]), "+f"(c[1]), "+f"(c[2]), "+f"(c[3])
        : "r"(a[0]), "r"(a[1]), "r"(a[2]), "r"(a[3]), "r"(b[0]), "r"(b[1]));
}
#define LDMX4(r, addr) \
    asm volatile("ldmatrix.sync.aligned.m8n8.x4.shared.b16 {%0,%1,%2,%3}, [%4];" \
        : "=r"((r)[0]), "=r"((r)[1]), "=r"((r)[2]), "=r"((r)[3]) : "r"(addr))

__device__ __forceinline__ uint32_t packbf(float x, float y) {
    __nv_bfloat16 hx = __float2bfloat16_rn(x), hy = __float2bfloat16_rn(y);
    return (uint32_t)__bfloat16_as_ushort(hx) | ((uint32_t)__bfloat16_as_ushort(hy) << 16);
}

// --------------------------- CSR build kernels ------------------------------
__global__ void k_zero_int(int* p, int n) {
    int i = blockIdx.x * blockDim.x + threadIdx.x;
    if (i < n) p[i] = 0;
}
__global__ void k_hist(int* cnt, const int* __restrict__ dst, int E) {
    int e = blockIdx.x * blockDim.x + threadIdx.x;
    if (e < E) atomicAdd(&cnt[dst[e]], 1);
}
// block scan + fused degree normalization
__global__ void k_scan_block(const int* __restrict__ cnt, int* __restrict__ ptr,
                             int* __restrict__ bsum, float* __restrict__ dis, int n) {
    __shared__ int sm[1024];
    int i = blockIdx.x * 1024 + threadIdx.x;
    int v = (i < n) ? cnt[i] : 0;
    if (i < n) dis[i] = rsqrtf((float)v + 1.0f);
    sm[threadIdx.x] = v;
    __syncthreads();
    for (int off = 1; off < 1024; off <<= 1) {
        int t = (threadIdx.x >= off) ? sm[threadIdx.x - off] : 0;
        __syncthreads();
        sm[threadIdx.x] += t;
        __syncthreads();
    }
    if (i < n) ptr[i] = sm[threadIdx.x] - v;
    if (threadIdx.x == 1023) bsum[blockIdx.x] = sm[1023];
}
__global__ void k_scan_bsum(int* bsum, int nb, int* totalOut) {
    __shared__ int sm[256];
    int v = (threadIdx.x < nb) ? bsum[threadIdx.x] : 0;
    sm[threadIdx.x] = v;
    __syncthreads();
    for (int off = 1; off < 256; off <<= 1) {
        int t = (threadIdx.x >= off) ? sm[threadIdx.x - off] : 0;
        __syncthreads();
        sm[threadIdx.x] += t;
        __syncthreads();
    }
    if (threadIdx.x < nb) bsum[threadIdx.x] = sm[threadIdx.x] - v;
    if (threadIdx.x == 255) *totalOut = sm[255];
}
__global__ void k_scan_add(int* __restrict__ ptr, const int* __restrict__ bsum,
                           int* __restrict__ cursor, int n) {
    int i = blockIdx.x * blockDim.x + threadIdx.x;
    if (i < n) {
        int p = ptr[i] + bsum[i >> 10];
        ptr[i] = p;
        cursor[i] = p;
    }
}
__global__ void k_fill_csr(const int* __restrict__ src, const int* __restrict__ dst,
                           int* cursor, int* __restrict__ csr, int E) {
    int e = blockIdx.x * blockDim.x + threadIdx.x;
    if (e < E) {
        int pos = atomicAdd(&cursor[dst[e]], 1);
        csr[pos] = src[e];
    }
}

// ---------------------------- misc small kernels ----------------------------
__global__ void k_fill_bias(float* __restrict__ H, const float* __restrict__ b,
                            int M, int N) {
    int i = blockIdx.x * blockDim.x + threadIdx.x;
    if (i < M * N) H[i] = b[i % N];
}
// convert ALL weights fp32 -> bf16 hi/lo in one launch
__global__ void k_convW_all(const float* __restrict__ W1, const float* __restrict__ W2,
                            const float* __restrict__ W3, const float* __restrict__ L1w,
                            const float* __restrict__ L2w,
                            __nv_bfloat16* __restrict__ hi, __nv_bfloat16* __restrict__ lo)
{
    const int n1 = 5120, n2 = n1 + 32768, n3 = n2 + 32768,
              n4 = n3 + 2621440, n5 = n4 + 65536;
    int i = blockIdx.x * blockDim.x + threadIdx.x;
    if (i >= n5) return;
    float v;
    if      (i < n1) v = W1[i];
    else if (i < n2) v = W2[i - n1];
    else if (i < n3) v = W3[i - n2];
    else if (i < n4) v = L1w[i - n3];
    else             v = L2w[i - n4];
    __nv_bfloat16 h = __float2bfloat16_rn(v);
    hi[i] = h;
    lo[i] = __float2bfloat16_rn(v - __bfloat162float(h));
}

// ------------------------------ CSR gather ----------------------------------
// F=128: AGG[node] (pre-initialized) += sum H[src]*norm.
template <int F>
__global__ void __launch_bounds__(256)
k_gather(const float* __restrict__ H, float* __restrict__ AGG,
         const int* __restrict__ ptr, const int* __restrict__ csr,
         const float* __restrict__ dis, int Nn)
{
    int node = (int)(((long long)blockIdx.x * blockDim.x + threadIdx.x) >> 5);
    int lane = threadIdx.x & 31;
    if (node >= Nn) return;

    int p0 = ptr[node];
    int p1 = ptr[node + 1];
    float dn = dis[node];

    float4 acc = *(const float4*)(AGG + (long long)node * 128 + lane * 4);
    int p = p0;
    for (; p + 1 < p1; p += 2) {
        int s0 = csr[p], s1 = csr[p + 1];
        float n0 = dn * dis[s0], n1 = dn * dis[s1];
        float4 v0 = *(const float4*)(H + (long long)s0 * 128 + lane * 4);
        float4 v1 = *(const float4*)(H + (long long)s1 * 128 + lane * 4);
        acc.x += v0.x * n0; acc.y += v0.y * n0;
        acc.z += v0.z * n0; acc.w += v0.w * n0;
        acc.x += v1.x * n1; acc.y += v1.y * n1;
        acc.z += v1.z * n1; acc.w += v1.w * n1;
    }
    if (p < p1) {
        int s0 = csr[p];
        float n0 = dn * dis[s0];
        float4 v0 = *(const float4*)(H + (long long)s0 * 128 + lane * 4);
        acc.x += v0.x * n0; acc.y += v0.y * n0;
        acc.z += v0.z * n0; acc.w += v0.w * n0;
    }
    *(float4*)(AGG + (long long)node * 128 + lane * 4) = acc;
}

// F=40 gather with fused self-loop init: AGG[node] = x[node]*dis^2 + sum x[src]*norm
__global__ void __launch_bounds__(256)
k_gather40(const float* __restrict__ X, float* __restrict__ AGG,
           const int* __restrict__ ptr, const int* __restrict__ csr,
           const float* __restrict__ dis, int Nn)
{
    int node = (int)(((long long)blockIdx.x * blockDim.x + threadIdx.x) >> 5);
    int lane = threadIdx.x & 31;
    if (node >= Nn) return;

    int p0 = ptr[node];
    int p1 = ptr[node + 1];
    float dn = dis[node];
    float d2 = dn * dn;

    long long base = (long long)node * 40;
    float a0 = X[base + lane] * d2;
    float a1 = (lane < 8) ? X[base + 32 + lane] * d2 : 0.f;
    for (int p = p0; p < p1; p++) {
        int s = csr[p];
        float nm = dn * dis[s];
        long long hb = (long long)s * 40;
        a0 += X[hb + lane] * nm;
        if (lane < 8) a1 += X[hb + 32 + lane] * nm;
    }
    AGG[base + lane] = a0;
    if (lane < 8) AGG[base + 32 + lane] = a1;
}

// ------------------------ tensor-core bf16x3 GEMM ---------------------------
__global__ void __launch_bounds__(256, 2)
k_mma_gemm(const float* __restrict__ A,
           const __nv_bfloat16* __restrict__ Whi, const __nv_bfloat16* __restrict__ Wlo,
           float* __restrict__ H, float* __restrict__ AGG,
           const float* __restrict__ bias, const float* __restrict__ aggb,
           const float* __restrict__ dis,
           int M, int Nout, int K, int kLen, int applyLrelu, int lreluOut, int kSplit)
{
    extern __shared__ char smem[];
    const uint32_t sb = smem_u32(smem);
    const int tid  = threadIdx.x;
    const int wid  = tid >> 5;
    const int lane = tid & 31;
    const int g    = lane >> 2;
    const int tig  = lane & 3;
    const int warpM = wid >> 1;
    const int warpN = wid & 1;
    const int mBase = blockIdx.y * TILE_M;
    const int nBase = blockIdx.x * TILE_N;
    const long long zOff = (long long)blockIdx.z * kLen;

    float acc[2][8][4];
#pragma unroll
    for (int i = 0; i < 2; i++)
#pragma unroll
        for (int j = 0; j < 8; j++)
#pragma unroll
            for (int q = 0; q < 4; q++) acc[i][j][q] = 0.f;

    // ---- per-lane ldmatrix addresses (stage/kk offsets added at use) ----
    uint32_t aAddrH[2], aAddrL[2], bAddrH[2][2], bAddrL[2][2];
    {
        uint32_t aRowCol = (uint32_t)((warpM * 32 + (lane & 15)) * SROW + (lane >> 4) * 16);
#pragma unroll
        for (int ms = 0; ms < 2; ms++) {
            uint32_t off = aRowCol + (uint32_t)(ms * 16 * SROW);
            aAddrH[ms] = sb + OFF_AH + off;
            aAddrL[ms] = sb + OFF_AL + off;
        }
        uint32_t bRow = (uint32_t)(warpN * 64 + ((lane >> 4) & 1) * 8 + (lane & 7));
        uint32_t bCol = (uint32_t)(((lane >> 3) & 1) * 16);
#pragma unroll
        for (int nh = 0; nh < 2; nh++)
#pragma unroll
            for (int p = 0; p < 2; p++) {
                uint32_t off = (bRow + (uint32_t)(nh * 32 + p * 16)) * SROW + bCol;
                bAddrH[nh][p] = sb + OFF_WH + off;
                bAddrL[nh][p] = sb + OFF_WL + off;
            }
    }

    auto loadStage = [&](int stg, int kb) {
        const int so = stg * STG_BYTES;
#pragma unroll
        for (int q = tid; q < 1024; q += 256) {
            int row = q >> 3, kq = q & 7;
            long long gk = zOff + kb + kq * 4;
            int gm = mBase + row;
            float4 v = make_float4(0.f, 0.f, 0.f, 0.f);
            if (gm < M && gk + 4 <= (long long)K)
                v = *(const float4*)(A + (long long)gm * K + gk);
            if (applyLrelu) {
                v.x = lrelu_f(v.x); v.y = lrelu_f(v.y);
                v.z = lrelu_f(v.z); v.w = lrelu_f(v.w);
            }
            __nv_bfloat16 h0 = __float2bfloat16_rn(v.x), h1 = __float2bfloat16_rn(v.y);
            __nv_bfloat16 h2 = __float2bfloat16_rn(v.z), h3 = __float2bfloat16_rn(v.w);
            uint32_t hiA = (uint32_t)__bfloat16_as_ushort(h0) | ((uint32_t)__bfloat16_as_ushort(h1) << 16);
            uint32_t hiB = (uint32_t)__bfloat16_as_ushort(h2) | ((uint32_t)__bfloat16_as_ushort(h3) << 16);
            uint32_t loA = packbf(v.x - __bfloat162float(h0), v.y - __bfloat162float(h1));
            uint32_t loB = packbf(v.z - __bfloat162float(h2), v.w - __bfloat162float(h3));
            uint32_t off = so + row * SROW + kq * 8;
            *(uint2*)(smem + OFF_AH + off) = make_uint2(hiA, hiB);
            *(uint2*)(smem + OFF_AL + off) = make_uint2(loA, loB);
        }
#pragma unroll
        for (int q = tid; q < 1024; q += 256) {
            int row = q >> 3, kq = q & 7;
            long long gk = zOff + kb + kq * 4;
            uint2 hv = make_uint2(0u, 0u), lv = make_uint2(0u, 0u);
            if (gk + 4 <= (long long)K) {
                long long woff = (long long)(nBase + row) * K + gk;
                hv = *(const uint2*)(Whi + woff);
                lv = *(const uint2*)(Wlo + woff);
            }
            uint32_t off = so + row * SROW + kq * 8;
            *(uint2*)(smem + OFF_WH + off) = hv;
            *(uint2*)(smem + OFF_WL + off) = lv;
        }
    };

    loadStage(0, 0);
    __syncthreads();

    int s = 0;
    for (int kb = 0; kb < kLen; kb += KC) {
        if (kb + KC < kLen) loadStage(s ^ 1, kb + KC);

        const uint32_t so = (uint32_t)(s * STG_BYTES);
#pragma unroll
        for (int kk = 0; kk < 2; kk++) {
            const uint32_t ko = so + (uint32_t)(kk * 32);
            uint32_t AH[2][4], AL[2][4];
#pragma unroll
            for (int ms = 0; ms < 2; ms++) {
                LDMX4(AH[ms], aAddrH[ms] + ko);
                LDMX4(AL[ms], aAddrL[ms] + ko);
            }
#pragma unroll
            for (int nh = 0; nh < 2; nh++) {
#pragma unroll
                for (int p = 0; p < 2; p++) {
                    uint32_t BH[4], BL[4];
                    LDMX4(BH, bAddrH[nh][p] + ko);
                    LDMX4(BL, bAddrL[nh][p] + ko);
                    const int j0 = nh * 4 + p * 2;
#pragma unroll
                    for (int ms = 0; ms < 2; ms++) {
                        mma16816(acc[ms][j0],     AH[ms], BH);
                        mma16816(acc[ms][j0],     AH[ms], BL);
                        mma16816(acc[ms][j0],     AL[ms], BH);
                        mma16816(acc[ms][j0 + 1], AH[ms], BH + 2);
                        mma16816(acc[ms][j0 + 1], AH[ms], BL + 2);
                        mma16816(acc[ms][j0 + 1], AL[ms], BH + 2);
                    }
                }
            }
        }
        __syncthreads();
        s ^= 1;
    }

    const int mW = mBase + warpM * 32;
#pragma unroll
    for (int ms = 0; ms < 2; ms++) {
#pragma unroll
        for (int half = 0; half < 2; half++) {
            int row = mW + ms * 16 + g + half * 8;
            if (row >= M) continue;
            float d2 = 0.f;
            if (AGG != nullptr) { float dv = dis[row]; d2 = dv * dv; }
            long long ro = (long long)row * Nout;
#pragma unroll
            for (int ns = 0; ns < 8; ns++) {
                int col = nBase + warpN * 64 + ns * 8 + 2 * tig;
                float c0 = acc[ms][ns][half * 2 + 0];
                float c1 = acc[ms][ns][half * 2 + 1];
                if (kSplit > 1) {
                    atomicAdd(&H[ro + col + 0], c0);
                    atomicAdd(&H[ro + col + 1], c1);
                } else {
                    if (bias) { c0 += __ldg(&bias[col]); c1 += __ldg(&bias[col + 1]); }
                    if (lreluOut) { c0 = lrelu_f(c0); c1 = lrelu_f(c1); }
                    *(float2*)(H + ro + col) = make_float2(c0, c1);
                    if (AGG) {
                        float a0 = c0 * d2, a1 = c1 * d2;
                        if (aggb) { a0 += __ldg(&aggb[col]); a1 += __ldg(&aggb[col + 1]); }
                        *(float2*)(AGG + ro + col) = make_float2(a0, a1);
                    }
                }
            }
        }
    }
}

// --------------------------- final linear + sigmoid -------------------------
__global__ void k_mlp_out(const float* __restrict__ g2, const float* __restrict__ L3w,
                          const float* __restrict__ L3b, float* __restrict__ out, int G)
{
    int w    = (blockIdx.x * blockDim.x + threadIdx.x) >> 5;
    int lane = threadIdx.x & 31;
    if (w >= G) return;
    float s = 0.f;
#pragma unroll
    for (int c = lane; c < 128; c += 32)
        s += lrelu_f(g2[(long long)w * 128 + c]) * __ldg(&L3w[c]);
#pragma unroll
    for (int off = 16; off; off >>= 1) s += __shfl_xor_sync(0xffffffffu, s, off);
    if (lane == 0) out[w] = 1.f / (1.f + expf(-(s + L3b[0])));
}

// ------------------------------- launch ------------------------------------
extern "C" void kernel_launch(void* const* d_in, const int* in_sizes, int n_in,
                              void* d_out, int out_size)
{
    const float* x   = (const float*)d_in[0];
    const int*   ei  = (const int*)d_in[1];
    const float* W1 = (const float*)d_in[2];  const float* b1 = (const float*)d_in[3];
    const float* W2 = (const float*)d_in[4];  const float* b2 = (const float*)d_in[5];
    const float* W3 = (const float*)d_in[6];  const float* b3 = (const float*)d_in[7];
    const float* L1w = (const float*)d_in[8];  const float* L1b = (const float*)d_in[9];
    const float* L2w = (const float*)d_in[10]; const float* L2b = (const float*)d_in[11];
    const float* L3w = (const float*)d_in[12]; const float* L3b = (const float*)d_in[13];
    float* out = (float*)d_out;

    const int C = 40;
    const int N = in_sizes[0] / C;     // 200000
    const int E = in_sizes[1] / 2;     // 1000000
    const int G = N / 40;              // 5000

    const int* srcIdx = ei;
    const int* dstIdx = ei + E;

    float *bufA, *bufB, *bufC, *dis;
    __nv_bfloat16 *whi, *wlo;
    int *ptr, *cursor, *csr, *bsum;
    cudaGetSymbolAddress((void**)&bufA, g_bufA);
    cudaGetSymbolAddress((void**)&bufB, g_bufB);
    cudaGetSymbolAddress((void**)&bufC, g_bufC);
    cudaGetSymbolAddress((void**)&dis,  g_dis);
    cudaGetSymbolAddress((void**)&whi,  g_whi);
    cudaGetSymbolAddress((void**)&wlo,  g_wlo);
    cudaGetSymbolAddress((void**)&ptr,    g_ptr);
    cudaGetSymbolAddress((void**)&cursor, g_cursor);
    cudaGetSymbolAddress((void**)&csr,    g_csr);
    cudaGetSymbolAddress((void**)&bsum,   g_bsum);

    cudaFuncSetAttribute(k_mma_gemm, cudaFuncAttributeMaxDynamicSharedMemorySize, SMB);

    const int O1 = 0;
    const int O2 = O1 + 128 * 40;
    const int O3 = O2 + 256 * 128;
    const int O4 = O3 + 128 * 256;
    const int O5 = O4 + 512 * 5120;
    const int WTOT = O5 + 128 * 512;   // 2757632

    k_convW_all<<<(WTOT + 255) / 256, 256>>>(W1, W2, W3, L1w, L2w, whi, wlo);

    // ---- CSR build + degree normalization ----
    const int nb = (N + 1023) / 1024;            // 196
    k_zero_int <<<(N + 255) / 256, 256>>>(cursor, N);
    k_hist     <<<(E + 255) / 256, 256>>>(cursor, dstIdx, E);
    k_scan_block<<<nb, 1024>>>(cursor, ptr, bsum, dis, N);
    k_scan_bsum <<<1, 256>>>(bsum, nb, ptr + N);
    k_scan_add  <<<(N + 255) / 256, 256>>>(ptr, bsum, cursor, N);
    k_fill_csr  <<<(E + 255) / 256, 256>>>(srcIdx, dstIdx, cursor, csr, E);

    const int mTilesN = (N + 127) / 128;   // 1563
    const int mTilesG = (G + 127) / 128;   // 40
    const int gatherBlocks = (int)(((long long)N * 32 + 255) / 256);

    // ---- conv1 (aggregate-first): A1 = Âx -> bufC [N,40] ----
    k_gather40<<<gatherBlocks, 256>>>(x, bufC, ptr, csr, dis, N);
    // GEMM1: P1 = lrelu(A1@W1^T + b1) -> bufA ; A2init = P1*dis^2 -> bufB
    k_mma_gemm<<<dim3(1, mTilesN, 1), 256, SMB>>>(
        bufC, whi + O1, wlo + O1, bufA, bufB, b1, nullptr, dis,
        N, 128, 40, 64, 0, 1, 1);

    // ---- conv2 (aggregate-first): A2 = ÂP1 -> bufB [N,128] ----
    k_gather<128><<<gatherBlocks, 256>>>(bufA, bufB, ptr, csr, dis, N);
    // GEMM2: conv2out(pre-act) = A2@W2^T + b2 -> bufC [N,256]
    k_mma_gemm<<<dim3(2, mTilesN, 1), 256, SMB>>>(
        bufB, whi + O2, wlo + O2, bufC, nullptr, b2, nullptr, dis,
        N, 256, 128, 128, 0, 0, 1);

    // ---- conv3 (transform-first): H3t = lrelu(conv2out)@W3^T -> bufA ----
    //      AGG3init = H3t*dis^2 + b3 -> bufB
    k_mma_gemm<<<dim3(1, mTilesN, 1), 256, SMB>>>(
        bufC, whi + O3, wlo + O3, bufA, bufB, nullptr, b3, dis,
        N, 128, 256, 256, 1, 0, 1);
    k_gather<128><<<gatherBlocks, 256>>>(bufA, bufB, ptr, csr, dis, N);

    // ---- MLP ----
    k_fill_bias<<<(G * 512 + 255) / 256, 256>>>(bufC, L1b, G, 512);
    k_mma_gemm<<<dim3(4, mTilesG, 4), 256, SMB>>>(
        bufB, whi + O4, wlo + O4, bufC, nullptr, nullptr, nullptr, nullptr,
        G, 512, 5120, 1280, 1, 0, 4);
    k_fill_bias<<<(G * 128 + 255) / 256, 256>>>(bufA, L2b, G, 128);
    k_mma_gemm<<<dim3(1, mTilesG, 4), 256, SMB>>>(
        bufC, whi + O5, wlo + O5, bufA, nullptr, nullptr, nullptr, nullptr,
        G, 128, 512, 128, 1, 0, 4);
    k_mlp_out<<<(G * 32 + 255) / 256, 256>>>(bufA, L3w, L3b, out, G);
}

// round 10
// speedup vs baseline: 4.1872x; 1.1516x over previous
#include <cuda_runtime.h>
#include <cuda_bf16.h>
#include <math.h>
#include <stdint.h>

// ---------------------------------------------------------------------------
// GCN: 3x GCNConv(+lrelu) -> reshape(40/graph) -> 3x Linear -> sigmoid
// GEMMs: mma.sync m16n8k16 bf16x3 emulation, ldmatrix fragments, cp.async
// tile loads from PRE-SPLIT (hi,lo) bf16 activations/weights.
// Aggregation: dst-CSR gather (no float atomics), epilogues emit presplit.
// ---------------------------------------------------------------------------

#define TILE_M 128
#define TILE_N 128
#define KC 32
#define SROW 80
#define STG_BYTES (128 * SROW)

#define OFF_AH 0
#define OFF_AL (2 * STG_BYTES)
#define OFF_WH (4 * STG_BYTES)
#define OFF_WL (6 * STG_BYTES)
#define SMB    (8 * STG_BYTES)     // 81920 bytes

#define NMAX 200000
#define EMAX 1000000

__device__ __align__(256) float g_bufA[(size_t)NMAX * 128];
__device__ __align__(256) float g_bufB[(size_t)NMAX * 128];
__device__ __align__(256) float g_bufC[(size_t)NMAX * 16];
__device__ __align__(256) float g_dis[NMAX];
__device__ __align__(256) __nv_bfloat16 g_whi[2760000];
__device__ __align__(256) __nv_bfloat16 g_wlo[2760000];
__device__ __align__(256) __nv_bfloat16 g_hiA[(size_t)NMAX * 256];
__device__ __align__(256) __nv_bfloat16 g_loA[(size_t)NMAX * 256];
__device__ __align__(256) __nv_bfloat16 g_hiB[(size_t)NMAX * 128];
__device__ __align__(256) __nv_bfloat16 g_loB[(size_t)NMAX * 128];
__device__ __align__(256) int g_ptr[NMAX + 1];
__device__ __align__(256) int g_cursor[NMAX];
__device__ __align__(256) int g_csr[EMAX];
__device__ __align__(256) int g_bsum[256];

__device__ __forceinline__ float lrelu_f(float v) { return v > 0.f ? v : 0.1f * v; }

__device__ __forceinline__ uint32_t smem_u32(const void* p) {
    uint32_t a;
    asm("{ .reg .u64 t; cvta.to.shared.u64 t, %1; cvt.u32.u64 %0, t; }" : "=r"(a) : "l"(p));
    return a;
}
__device__ __forceinline__ void mma16816(float* c, const uint32_t* a, const uint32_t* b) {
    asm volatile(
        "mma.sync.aligned.m16n8k16.row.col.f32.bf16.bf16.f32 "
        "{%0,%1,%2,%3}, {%4,%5,%6,%7}, {%8,%9}, {%0,%1,%2,%3};"
        : "+f"(c[0]), "+f"(c[1]), "+f"(c[2]), "+f"(c[3])
        : "r"(a[0]), "r"(a[1]), "r"(a[2]), "r"(a[3]), "r"(b[0]), "r"(b[1]));
}
#define LDMX4(r, addr) \
    asm volatile("ldmatrix.sync.aligned.m8n8.x4.shared.b16 {%0,%1,%2,%3}, [%4];" \
        : "=r"((r)[0]), "=r"((r)[1]), "=r"((r)[2]), "=r"((r)[3]) : "r"(addr))
__device__ __forceinline__ void cp16(uint32_t dst, const void* src, int srcsize) {
    asm volatile("cp.async.cg.shared.global [%0], [%1], 16, %2;"
                 :: "r"(dst), "l"(src), "r"(srcsize) : "memory");
}
#define CP_COMMIT() asm volatile("cp.async.commit_group;" ::: "memory")
#define CP_WAIT0()  asm volatile("cp.async.wait_group 0;" ::: "memory")
#define CP_WAIT1()  asm volatile("cp.async.wait_group 1;" ::: "memory")

__device__ __forceinline__ void split2(float c0, float c1, uint32_t& hp, uint32_t& lp) {
    __nv_bfloat16 h0 = __float2bfloat16_rn(c0), h1 = __float2bfloat16_rn(c1);
    __nv_bfloat16 l0 = __float2bfloat16_rn(c0 - __bfloat162float(h0));
    __nv_bfloat16 l1 = __float2bfloat16_rn(c1 - __bfloat162float(h1));
    hp = (uint32_t)__bfloat16_as_ushort(h0) | ((uint32_t)__bfloat16_as_ushort(h1) << 16);
    lp = (uint32_t)__bfloat16_as_ushort(l0) | ((uint32_t)__bfloat16_as_ushort(l1) << 16);
}

// --------------------------- CSR build kernels ------------------------------
__global__ void k_zero_int(int* p, int n) {
    int i = blockIdx.x * blockDim.x + threadIdx.x;
    if (i < n) p[i] = 0;
}
__global__ void k_hist(int* cnt, const int* __restrict__ dst, int E) {
    int e = blockIdx.x * blockDim.x + threadIdx.x;
    if (e < E) atomicAdd(&cnt[dst[e]], 1);
}
__global__ void k_scan_block(const int* __restrict__ cnt, int* __restrict__ ptr,
                             int* __restrict__ bsum, float* __restrict__ dis, int n) {
    __shared__ int sm[1024];
    int i = blockIdx.x * 1024 + threadIdx.x;
    int v = (i < n) ? cnt[i] : 0;
    if (i < n) dis[i] = rsqrtf((float)v + 1.0f);
    sm[threadIdx.x] = v;
    __syncthreads();
    for (int off = 1; off < 1024; off <<= 1) {
        int t = (threadIdx.x >= off) ? sm[threadIdx.x - off] : 0;
        __syncthreads();
        sm[threadIdx.x] += t;
        __syncthreads();
    }
    if (i < n) ptr[i] = sm[threadIdx.x] - v;
    if (threadIdx.x == 1023) bsum[blockIdx.x] = sm[1023];
}
__global__ void k_scan_bsum(int* bsum, int nb, int* totalOut) {
    __shared__ int sm[256];
    int v = (threadIdx.x < nb) ? bsum[threadIdx.x] : 0;
    sm[threadIdx.x] = v;
    __syncthreads();
    for (int off = 1; off < 256; off <<= 1) {
        int t = (threadIdx.x >= off) ? sm[threadIdx.x - off] : 0;
        __syncthreads();
        sm[threadIdx.x] += t;
        __syncthreads();
    }
    if (threadIdx.x < nb) bsum[threadIdx.x] = sm[threadIdx.x] - v;
    if (threadIdx.x == 255) *totalOut = sm[255];
}
__global__ void k_scan_add(int* __restrict__ ptr, const int* __restrict__ bsum,
                           int* __restrict__ cursor, int n) {
    int i = blockIdx.x * blockDim.x + threadIdx.x;
    if (i < n) {
        int p = ptr[i] + bsum[i >> 10];
        ptr[i] = p;
        cursor[i] = p;
    }
}
__global__ void k_fill_csr(const int* __restrict__ src, const int* __restrict__ dst,
                           int* cursor, int* __restrict__ csr, int E) {
    int e = blockIdx.x * blockDim.x + threadIdx.x;
    if (e < E) {
        int pos = atomicAdd(&cursor[dst[e]], 1);
        csr[pos] = src[e];
    }
}

// ---------------------------- misc small kernels ----------------------------
__global__ void k_fill_bias(float* __restrict__ H, const float* __restrict__ b,
                            int M, int N) {
    int i = blockIdx.x * blockDim.x + threadIdx.x;
    if (i < M * N) H[i] = b[i % N];
}
__global__ void k_convW_all(const float* __restrict__ W1, const float* __restrict__ W2,
                            const float* __restrict__ W3, const float* __restrict__ L1w,
                            const float* __restrict__ L2w,
                            __nv_bfloat16* __restrict__ hi, __nv_bfloat16* __restrict__ lo)
{
    const int n1 = 5120, n2 = n1 + 32768, n3 = n2 + 32768,
              n4 = n3 + 2621440, n5 = n4 + 65536;
    int i = blockIdx.x * blockDim.x + threadIdx.x;
    if (i >= n5) return;
    float v;
    if      (i < n1) v = W1[i];
    else if (i < n2) v = W2[i - n1];
    else if (i < n3) v = W3[i - n2];
    else if (i < n4) v = L1w[i - n3];
    else             v = L2w[i - n4];
    __nv_bfloat16 h = __float2bfloat16_rn(v);
    hi[i] = h;
    lo[i] = __float2bfloat16_rn(v - __bfloat162float(h));
}
// lrelu + split [G,512] fp32 -> hi/lo bf16
__global__ void k_split512(const float* __restrict__ in, __nv_bfloat16* __restrict__ hi,
                           __nv_bfloat16* __restrict__ lo, int total) {
    int i = blockIdx.x * blockDim.x + threadIdx.x;
    if (i < total) {
        float v = lrelu_f(in[i]);
        __nv_bfloat16 h = __float2bfloat16_rn(v);
        hi[i] = h;
        lo[i] = __float2bfloat16_rn(v - __bfloat162float(h));
    }
}

// ------------------------------ CSR gathers ---------------------------------
// F=128 gather: acc = AGGinit[node] + sum H[src]*norm; optional lrelu; emits presplit.
__global__ void __launch_bounds__(256)
k_gather128(const float* __restrict__ H, const float* __restrict__ AGGinit,
            __nv_bfloat16* __restrict__ Ohi, __nv_bfloat16* __restrict__ Olo,
            const int* __restrict__ ptr, const int* __restrict__ csr,
            const float* __restrict__ dis, int Nn, int doLrelu)
{
    int node = (int)(((long long)blockIdx.x * blockDim.x + threadIdx.x) >> 5);
    int lane = threadIdx.x & 31;
    if (node >= Nn) return;

    int p0 = ptr[node];
    int p1 = ptr[node + 1];
    float dn = dis[node];

    float4 acc = *(const float4*)(AGGinit + (long long)node * 128 + lane * 4);
    int p = p0;
    for (; p + 1 < p1; p += 2) {
        int s0 = csr[p], s1 = csr[p + 1];
        float n0 = dn * dis[s0], n1 = dn * dis[s1];
        float4 v0 = *(const float4*)(H + (long long)s0 * 128 + lane * 4);
        float4 v1 = *(const float4*)(H + (long long)s1 * 128 + lane * 4);
        acc.x += v0.x * n0; acc.y += v0.y * n0;
        acc.z += v0.z * n0; acc.w += v0.w * n0;
        acc.x += v1.x * n1; acc.y += v1.y * n1;
        acc.z += v1.z * n1; acc.w += v1.w * n1;
    }
    if (p < p1) {
        int s0 = csr[p];
        float n0 = dn * dis[s0];
        float4 v0 = *(const float4*)(H + (long long)s0 * 128 + lane * 4);
        acc.x += v0.x * n0; acc.y += v0.y * n0;
        acc.z += v0.z * n0; acc.w += v0.w * n0;
    }
    if (doLrelu) {
        acc.x = lrelu_f(acc.x); acc.y = lrelu_f(acc.y);
        acc.z = lrelu_f(acc.z); acc.w = lrelu_f(acc.w);
    }
    uint32_t h0, l0, h1, l1;
    split2(acc.x, acc.y, h0, l0);
    split2(acc.z, acc.w, h1, l1);
    long long o = (long long)node * 128 + lane * 4;
    *(uint2*)(Ohi + o) = make_uint2(h0, h1);
    *(uint2*)(Olo + o) = make_uint2(l0, l1);
}

// F=40 gather with fused self-loop; emits presplit [N,40].
__global__ void __launch_bounds__(256)
k_gather40(const float* __restrict__ X,
           __nv_bfloat16* __restrict__ Ohi, __nv_bfloat16* __restrict__ Olo,
           const int* __restrict__ ptr, const int* __restrict__ csr,
           const float* __restrict__ dis, int Nn)
{
    int node = (int)(((long long)blockIdx.x * blockDim.x + threadIdx.x) >> 5);
    int lane = threadIdx.x & 31;
    if (node >= Nn) return;

    int p0 = ptr[node];
    int p1 = ptr[node + 1];
    float dn = dis[node];
    float d2 = dn * dn;

    long long base = (long long)node * 40;
    float a0 = X[base + lane] * d2;
    float a1 = (lane < 8) ? X[base + 32 + lane] * d2 : 0.f;
    for (int p = p0; p < p1; p++) {
        int s = csr[p];
        float nm = dn * dis[s];
        long long hb = (long long)s * 40;
        a0 += X[hb + lane] * nm;
        if (lane < 8) a1 += X[hb + 32 + lane] * nm;
    }
    __nv_bfloat16 h = __float2bfloat16_rn(a0);
    Ohi[base + lane] = h;
    Olo[base + lane] = __float2bfloat16_rn(a0 - __bfloat162float(h));
    if (lane < 8) {
        __nv_bfloat16 h1 = __float2bfloat16_rn(a1);
        Ohi[base + 32 + lane] = h1;
        Olo[base + 32 + lane] = __float2bfloat16_rn(a1 - __bfloat162float(h1));
    }
}

// ------------------------ tensor-core bf16x3 GEMM ---------------------------
// C = A @ W^T ; A presplit (Ahi,Alo) [M,K] bf16; W presplit [Nout,K].
// kSplit>1: atomicAdd into pre-initialized H.
// else if Ohi: store presplit of (lreluOut? lrelu: id)(c + bias).
// else: H = (lreluOut? lrelu: id)(c+bias); if AGG: AGG = h*dis^2 + aggb.
__global__ void __launch_bounds__(256, 2)
k_mma_gemm(const __nv_bfloat16* __restrict__ Ahi, const __nv_bfloat16* __restrict__ Alo,
           const __nv_bfloat16* __restrict__ Whi, const __nv_bfloat16* __restrict__ Wlo,
           float* __restrict__ H, float* __restrict__ AGG,
           __nv_bfloat16* __restrict__ Ohi, __nv_bfloat16* __restrict__ Olo,
           const float* __restrict__ bias, const float* __restrict__ aggb,
           const float* __restrict__ dis,
           int M, int Nout, int K, int kLen, int lreluOut, int kSplit)
{
    extern __shared__ char smem[];
    const uint32_t sb = smem_u32(smem);
    const int tid  = threadIdx.x;
    const int wid  = tid >> 5;
    const int lane = tid & 31;
    const int g    = lane >> 2;
    const int tig  = lane & 3;
    const int warpM = wid >> 1;
    const int warpN = wid & 1;
    const int mBase = blockIdx.y * TILE_M;
    const int nBase = blockIdx.x * TILE_N;
    const long long zOff = (long long)blockIdx.z * kLen;

    float acc[2][8][4];
#pragma unroll
    for (int i = 0; i < 2; i++)
#pragma unroll
        for (int j = 0; j < 8; j++)
#pragma unroll
            for (int q = 0; q < 4; q++) acc[i][j][q] = 0.f;

    // ---- per-lane ldmatrix addresses ----
    uint32_t aAddrH[2], aAddrL[2], bAddrH[2][2], bAddrL[2][2];
    {
        uint32_t aRowCol = (uint32_t)((warpM * 32 + (lane & 15)) * SROW + (lane >> 4) * 16);
#pragma unroll
        for (int ms = 0; ms < 2; ms++) {
            uint32_t off = aRowCol + (uint32_t)(ms * 16 * SROW);
            aAddrH[ms] = sb + OFF_AH + off;
            aAddrL[ms] = sb + OFF_AL + off;
        }
        uint32_t bRow = (uint32_t)(warpN * 64 + ((lane >> 4) & 1) * 8 + (lane & 7));
        uint32_t bCol = (uint32_t)(((lane >> 3) & 1) * 16);
#pragma unroll
        for (int nh = 0; nh < 2; nh++)
#pragma unroll
            for (int p = 0; p < 2; p++) {
                uint32_t off = (bRow + (uint32_t)(nh * 32 + p * 16)) * SROW + bCol;
                bAddrH[nh][p] = sb + OFF_WH + off;
                bAddrL[nh][p] = sb + OFF_WL + off;
            }
    }

    // ---- cp.async stage issue: 512 iterations of 8-col (16B) groups ----
    auto issueStage = [&](int stg, int kb) {
        const uint32_t so = sb + (uint32_t)(stg * STG_BYTES);
#pragma unroll
        for (int q = tid; q < 512; q += 256) {
            int row = q >> 2, kg = q & 3;
            long long gk = zOff + kb + kg * 8;
            uint32_t doff = (uint32_t)(row * SROW + kg * 16);
            // A
            {
                int gm = mBase + row;
                bool ok = (gm < M) && (gk + 8 <= (long long)K);
                long long aoff = ok ? ((long long)gm * K + gk) : 0;
                int ss = ok ? 16 : 0;
                cp16(so + OFF_AH + doff, Ahi + aoff, ss);
                cp16(so + OFF_AL + doff, Alo + aoff, ss);
            }
            // W (rows always valid: Nout % 128 == 0)
            {
                bool ok = (gk + 8 <= (long long)K);
                long long woff = ok ? ((long long)(nBase + row) * K + gk) : 0;
                int ss = ok ? 16 : 0;
                cp16(so + OFF_WH + doff, Whi + woff, ss);
                cp16(so + OFF_WL + doff, Wlo + woff, ss);
            }
        }
    };

    issueStage(0, 0);
    CP_COMMIT();

    int s = 0;
    for (int kb = 0; kb < kLen; kb += KC) {
        const bool more = (kb + KC) < kLen;
        if (more) { issueStage(s ^ 1, kb + KC); CP_COMMIT(); }
        if (more) CP_WAIT1(); else CP_WAIT0();
        __syncthreads();

        const uint32_t so = (uint32_t)(s * STG_BYTES);
#pragma unroll
        for (int kk = 0; kk < 2; kk++) {
            const uint32_t ko = so + (uint32_t)(kk * 32);
            uint32_t AH[2][4], AL[2][4];
#pragma unroll
            for (int ms = 0; ms < 2; ms++) {
                LDMX4(AH[ms], aAddrH[ms] + ko);
                LDMX4(AL[ms], aAddrL[ms] + ko);
            }
#pragma unroll
            for (int nh = 0; nh < 2; nh++) {
#pragma unroll
                for (int p = 0; p < 2; p++) {
                    uint32_t BH[4], BL[4];
                    LDMX4(BH, bAddrH[nh][p] + ko);
                    LDMX4(BL, bAddrL[nh][p] + ko);
                    const int j0 = nh * 4 + p * 2;
#pragma unroll
                    for (int ms = 0; ms < 2; ms++) {
                        mma16816(acc[ms][j0],     AH[ms], BH);
                        mma16816(acc[ms][j0],     AH[ms], BL);
                        mma16816(acc[ms][j0],     AL[ms], BH);
                        mma16816(acc[ms][j0 + 1], AH[ms], BH + 2);
                        mma16816(acc[ms][j0 + 1], AH[ms], BL + 2);
                        mma16816(acc[ms][j0 + 1], AL[ms], BH + 2);
                    }
                }
            }
        }
        __syncthreads();
        s ^= 1;
    }

    const int mW = mBase + warpM * 32;
#pragma unroll
    for (int ms = 0; ms < 2; ms++) {
#pragma unroll
        for (int half = 0; half < 2; half++) {
            int row = mW + ms * 16 + g + half * 8;
            if (row >= M) continue;
            float d2 = 0.f;
            if (AGG != nullptr) { float dv = dis[row]; d2 = dv * dv; }
            long long ro = (long long)row * Nout;
#pragma unroll
            for (int ns = 0; ns < 8; ns++) {
                int col = nBase + warpN * 64 + ns * 8 + 2 * tig;
                float c0 = acc[ms][ns][half * 2 + 0];
                float c1 = acc[ms][ns][half * 2 + 1];
                if (kSplit > 1) {
                    atomicAdd(&H[ro + col + 0], c0);
                    atomicAdd(&H[ro + col + 1], c1);
                } else {
                    if (bias) { c0 += __ldg(&bias[col]); c1 += __ldg(&bias[col + 1]); }
                    if (lreluOut) { c0 = lrelu_f(c0); c1 = lrelu_f(c1); }
                    if (Ohi) {
                        uint32_t hp, lp;
                        split2(c0, c1, hp, lp);
                        *(uint32_t*)(Ohi + ro + col) = hp;
                        *(uint32_t*)(Olo + ro + col) = lp;
                    } else {
                        *(float2*)(H + ro + col) = make_float2(c0, c1);
                        if (AGG) {
                            float a0 = c0 * d2, a1 = c1 * d2;
                            if (aggb) { a0 += __ldg(&aggb[col]); a1 += __ldg(&aggb[col + 1]); }
                            *(float2*)(AGG + ro + col) = make_float2(a0, a1);
                        }
                    }
                }
            }
        }
    }
}

// --------------------------- final linear + sigmoid -------------------------
__global__ void k_mlp_out(const float* __restrict__ g2, const float* __restrict__ L3w,
                          const float* __restrict__ L3b, float* __restrict__ out, int G)
{
    int w    = (blockIdx.x * blockDim.x + threadIdx.x) >> 5;
    int lane = threadIdx.x & 31;
    if (w >= G) return;
    float s = 0.f;
#pragma unroll
    for (int c = lane; c < 128; c += 32)
        s += lrelu_f(g2[(long long)w * 128 + c]) * __ldg(&L3w[c]);
#pragma unroll
    for (int off = 16; off; off >>= 1) s += __shfl_xor_sync(0xffffffffu, s, off);
    if (lane == 0) out[w] = 1.f / (1.f + expf(-(s + L3b[0])));
}

// ------------------------------- launch ------------------------------------
extern "C" void kernel_launch(void* const* d_in, const int* in_sizes, int n_in,
                              void* d_out, int out_size)
{
    const float* x   = (const float*)d_in[0];
    const int*   ei  = (const int*)d_in[1];
    const float* b1 = (const float*)d_in[3];
    const float* b2 = (const float*)d_in[5];
    const float* b3 = (const float*)d_in[7];
    const float* L1b = (const float*)d_in[9];
    const float* L2b = (const float*)d_in[11];
    const float* L3w = (const float*)d_in[12]; const float* L3b = (const float*)d_in[13];
    float* out = (float*)d_out;

    const int C = 40;
    const int N = in_sizes[0] / C;     // 200000
    const int E = in_sizes[1] / 2;     // 1000000
    const int G = N / 40;              // 5000

    const int* srcIdx = ei;
    const int* dstIdx = ei + E;

    float *bufA, *bufB, *bufC, *dis;
    __nv_bfloat16 *whi, *wlo, *hiA, *loA, *hiB, *loB;
    int *ptr, *cursor, *csr, *bsum;
    cudaGetSymbolAddress((void**)&bufA, g_bufA);
    cudaGetSymbolAddress((void**)&bufB, g_bufB);
    cudaGetSymbolAddress((void**)&bufC, g_bufC);
    cudaGetSymbolAddress((void**)&dis,  g_dis);
    cudaGetSymbolAddress((void**)&whi,  g_whi);
    cudaGetSymbolAddress((void**)&wlo,  g_wlo);
    cudaGetSymbolAddress((void**)&hiA,  g_hiA);
    cudaGetSymbolAddress((void**)&loA,  g_loA);
    cudaGetSymbolAddress((void**)&hiB,  g_hiB);
    cudaGetSymbolAddress((void**)&loB,  g_loB);
    cudaGetSymbolAddress((void**)&ptr,    g_ptr);
    cudaGetSymbolAddress((void**)&cursor, g_cursor);
    cudaGetSymbolAddress((void**)&csr,    g_csr);
    cudaGetSymbolAddress((void**)&bsum,   g_bsum);

    cudaFuncSetAttribute(k_mma_gemm, cudaFuncAttributeMaxDynamicSharedMemorySize, SMB);

    const int O1 = 0;
    const int O2 = O1 + 128 * 40;
    const int O3 = O2 + 256 * 128;
    const int O4 = O3 + 128 * 256;
    const int O5 = O4 + 512 * 5120;
    const int WTOT = O5 + 128 * 512;

    k_convW_all<<<(WTOT + 255) / 256, 256>>>(
        (const float*)d_in[2], (const float*)d_in[4], (const float*)d_in[6],
        (const float*)d_in[8], (const float*)d_in[10], whi, wlo);

    // ---- CSR build + degree normalization ----
    const int nb = (N + 1023) / 1024;
    k_zero_int <<<(N + 255) / 256, 256>>>(cursor, N);
    k_hist     <<<(E + 255) / 256, 256>>>(cursor, dstIdx, E);
    k_scan_block<<<nb, 1024>>>(cursor, ptr, bsum, dis, N);
    k_scan_bsum <<<1, 256>>>(bsum, nb, ptr + N);
    k_scan_add  <<<(N + 255) / 256, 256>>>(ptr, bsum, cursor, N);
    k_fill_csr  <<<(E + 255) / 256, 256>>>(srcIdx, dstIdx, cursor, csr, E);

    const int mTilesN = (N + 127) / 128;   // 1563
    const int mTilesG = (G + 127) / 128;   // 40
    const int gatherBlocks = (int)(((long long)N * 32 + 255) / 256);

    // ---- conv1 (aggregate-first): A1 = Âx -> presplit hiA/loA [N,40] ----
    k_gather40<<<gatherBlocks, 256>>>(x, hiA, loA, ptr, csr, dis, N);
    // GEMM1: P1 = lrelu(A1@W1^T + b1) -> bufA fp32 ; AGG init = P1*d^2 -> bufB
    k_mma_gemm<<<dim3(1, mTilesN, 1), 256, SMB>>>(
        hiA, loA, whi + O1, wlo + O1, bufA, bufB, nullptr, nullptr,
        b1, nullptr, dis, N, 128, 40, 64, 1, 1);

    // ---- conv2 (aggregate-first): A2 = ÂP1 -> presplit hiB/loB [N,128] ----
    k_gather128<<<gatherBlocks, 256>>>(bufA, bufB, hiB, loB, ptr, csr, dis, N, 0);
    // GEMM2: lrelu(A2@W2^T + b2) -> presplit hiA/loA [N,256]
    k_mma_gemm<<<dim3(2, mTilesN, 1), 256, SMB>>>(
        hiB, loB, whi + O2, wlo + O2, nullptr, nullptr, hiA, loA,
        b2, nullptr, dis, N, 256, 128, 128, 1, 1);

    // ---- conv3 (transform-first): H3t = in@W3^T -> bufA ; AGG = H3t*d^2+b3 -> bufB
    k_mma_gemm<<<dim3(1, mTilesN, 1), 256, SMB>>>(
        hiA, loA, whi + O3, wlo + O3, bufA, bufB, nullptr, nullptr,
        nullptr, b3, dis, N, 128, 256, 256, 0, 1);
    // gather + lrelu -> presplit hiB/loB [N,128] = [G,5120]
    k_gather128<<<gatherBlocks, 256>>>(bufA, bufB, hiB, loB, ptr, csr, dis, N, 1);

    // ---- MLP ----
    k_fill_bias<<<(G * 512 + 255) / 256, 256>>>(bufC, L1b, G, 512);
    k_mma_gemm<<<dim3(4, mTilesG, 4), 256, SMB>>>(
        hiB, loB, whi + O4, wlo + O4, bufC, nullptr, nullptr, nullptr,
        nullptr, nullptr, nullptr, G, 512, 5120, 1280, 0, 4);
    // lrelu + split L1 out -> hiA/loA [G,512]
    k_split512<<<(G * 512 + 255) / 256, 256>>>(bufC, hiA, loA, G * 512);
    k_fill_bias<<<(G * 128 + 255) / 256, 256>>>(bufA, L2b, G, 128);
    k_mma_gemm<<<dim3(1, mTilesG, 4), 256, SMB>>>(
        hiA, loA, whi + O5, wlo + O5, bufA, nullptr, nullptr, nullptr,
        nullptr, nullptr, nullptr, G, 128, 512, 128, 0, 4);
    k_mlp_out<<<(G * 32 + 255) / 256, 256>>>(bufA, L3w, L3b, out, G);
}

// round 11
// speedup vs baseline: 4.4546x; 1.0639x over previous
#include <cuda_runtime.h>
#include <cuda_bf16.h>
#include <math.h>
#include <stdint.h>

// ---------------------------------------------------------------------------
// GCN: 3x GCNConv(+lrelu) -> reshape(40/graph) -> 3x Linear -> sigmoid
// GEMMs: mma.sync m16n8k16 bf16x3 emulation, ldmatrix fragments, cp.async
// tile loads from PRE-SPLIT (hi,lo) bf16 activations/weights.
// Aggregation: dst-CSR gather; self-loop + agg-bias fused INTO the gather.
// ---------------------------------------------------------------------------

#define TILE_M 128
#define TILE_N 128
#define KC 32
#define SROW 80
#define STG_BYTES (128 * SROW)

#define OFF_AH 0
#define OFF_AL (2 * STG_BYTES)
#define OFF_WH (4 * STG_BYTES)
#define OFF_WL (6 * STG_BYTES)
#define SMB    (8 * STG_BYTES)     // 81920 bytes

#define NMAX 200000
#define EMAX 1000000

__device__ __align__(256) float g_bufA[(size_t)NMAX * 128];
__device__ __align__(256) float g_bufC[(size_t)NMAX * 16];
__device__ __align__(256) float g_dis[NMAX];
__device__ __align__(256) __nv_bfloat16 g_whi[2760000];
__device__ __align__(256) __nv_bfloat16 g_wlo[2760000];
__device__ __align__(256) __nv_bfloat16 g_hiA[(size_t)NMAX * 256];
__device__ __align__(256) __nv_bfloat16 g_loA[(size_t)NMAX * 256];
__device__ __align__(256) __nv_bfloat16 g_hiB[(size_t)NMAX * 128];
__device__ __align__(256) __nv_bfloat16 g_loB[(size_t)NMAX * 128];
__device__ __align__(256) int g_ptr[NMAX + 1];
__device__ __align__(256) int g_cursor[NMAX];
__device__ __align__(256) int g_csr[EMAX];
__device__ __align__(256) int g_bsum[256];

__device__ __forceinline__ float lrelu_f(float v) { return v > 0.f ? v : 0.1f * v; }

__device__ __forceinline__ uint32_t smem_u32(const void* p) {
    uint32_t a;
    asm("{ .reg .u64 t; cvta.to.shared.u64 t, %1; cvt.u32.u64 %0, t; }" : "=r"(a) : "l"(p));
    return a;
}
__device__ __forceinline__ void mma16816(float* c, const uint32_t* a, const uint32_t* b) {
    asm volatile(
        "mma.sync.aligned.m16n8k16.row.col.f32.bf16.bf16.f32 "
        "{%0,%1,%2,%3}, {%4,%5,%6,%7}, {%8,%9}, {%0,%1,%2,%3};"
        : "+f"(c[0]), "+f"(c[1]), "+f"(c[2]), "+f"(c[3])
        : "r"(a[0]), "r"(a[1]), "r"(a[2]), "r"(a[3]), "r"(b[0]), "r"(b[1]));
}
#define LDMX4(r, addr) \
    asm volatile("ldmatrix.sync.aligned.m8n8.x4.shared.b16 {%0,%1,%2,%3}, [%4];" \
        : "=r"((r)[0]), "=r"((r)[1]), "=r"((r)[2]), "=r"((r)[3]) : "r"(addr))
__device__ __forceinline__ void cp16(uint32_t dst, const void* src, int srcsize) {
    asm volatile("cp.async.cg.shared.global [%0], [%1], 16, %2;"
                 :: "r"(dst), "l"(src), "r"(srcsize) : "memory");
}
#define CP_COMMIT() asm volatile("cp.async.commit_group;" ::: "memory")
#define CP_WAIT0()  asm volatile("cp.async.wait_group 0;" ::: "memory")
#define CP_WAIT1()  asm volatile("cp.async.wait_group 1;" ::: "memory")

__device__ __forceinline__ void split2(float c0, float c1, uint32_t& hp, uint32_t& lp) {
    __nv_bfloat16 h0 = __float2bfloat16_rn(c0), h1 = __float2bfloat16_rn(c1);
    __nv_bfloat16 l0 = __float2bfloat16_rn(c0 - __bfloat162float(h0));
    __nv_bfloat16 l1 = __float2bfloat16_rn(c1 - __bfloat162float(h1));
    hp = (uint32_t)__bfloat16_as_ushort(h0) | ((uint32_t)__bfloat16_as_ushort(h1) << 16);
    lp = (uint32_t)__bfloat16_as_ushort(l0) | ((uint32_t)__bfloat16_as_ushort(l1) << 16);
}

// --------------------------- CSR build kernels ------------------------------
__global__ void k_zero_int(int* p, int n) {
    int i = blockIdx.x * blockDim.x + threadIdx.x;
    if (i < n) p[i] = 0;
}
__global__ void k_hist(int* cnt, const int* __restrict__ dst, int E) {
    int e = blockIdx.x * blockDim.x + threadIdx.x;
    if (e < E) atomicAdd(&cnt[dst[e]], 1);
}
__global__ void k_scan_block(const int* __restrict__ cnt, int* __restrict__ ptr,
                             int* __restrict__ bsum, float* __restrict__ dis, int n) {
    __shared__ int sm[1024];
    int i = blockIdx.x * 1024 + threadIdx.x;
    int v = (i < n) ? cnt[i] : 0;
    if (i < n) dis[i] = rsqrtf((float)v + 1.0f);
    sm[threadIdx.x] = v;
    __syncthreads();
    for (int off = 1; off < 1024; off <<= 1) {
        int t = (threadIdx.x >= off) ? sm[threadIdx.x - off] : 0;
        __syncthreads();
        sm[threadIdx.x] += t;
        __syncthreads();
    }
    if (i < n) ptr[i] = sm[threadIdx.x] - v;
    if (threadIdx.x == 1023) bsum[blockIdx.x] = sm[1023];
}
__global__ void k_scan_bsum(int* bsum, int nb, int* totalOut) {
    __shared__ int sm[256];
    int v = (threadIdx.x < nb) ? bsum[threadIdx.x] : 0;
    sm[threadIdx.x] = v;
    __syncthreads();
    for (int off = 1; off < 256; off <<= 1) {
        int t = (threadIdx.x >= off) ? sm[threadIdx.x - off] : 0;
        __syncthreads();
        sm[threadIdx.x] += t;
        __syncthreads();
    }
    if (threadIdx.x < nb) bsum[threadIdx.x] = sm[threadIdx.x] - v;
    if (threadIdx.x == 255) *totalOut = sm[255];
}
__global__ void k_scan_add(int* __restrict__ ptr, const int* __restrict__ bsum,
                           int* __restrict__ cursor, int n) {
    int i = blockIdx.x * blockDim.x + threadIdx.x;
    if (i < n) {
        int p = ptr[i] + bsum[i >> 10];
        ptr[i] = p;
        cursor[i] = p;
    }
}
__global__ void k_fill_csr(const int* __restrict__ src, const int* __restrict__ dst,
                           int* cursor, int* __restrict__ csr, int E) {
    int e = blockIdx.x * blockDim.x + threadIdx.x;
    if (e < E) {
        int pos = atomicAdd(&cursor[dst[e]], 1);
        csr[pos] = src[e];
    }
}

// ---------------------------- misc small kernels ----------------------------
__global__ void k_fill_bias(float* __restrict__ H, const float* __restrict__ b,
                            int M, int N) {
    int i = blockIdx.x * blockDim.x + threadIdx.x;
    if (i < M * N) H[i] = b[i % N];
}
__global__ void k_convW_all(const float* __restrict__ W1, const float* __restrict__ W2,
                            const float* __restrict__ W3, const float* __restrict__ L1w,
                            const float* __restrict__ L2w,
                            __nv_bfloat16* __restrict__ hi, __nv_bfloat16* __restrict__ lo)
{
    const int n1 = 5120, n2 = n1 + 32768, n3 = n2 + 32768,
              n4 = n3 + 2621440, n5 = n4 + 65536;
    int i = blockIdx.x * blockDim.x + threadIdx.x;
    if (i >= n5) return;
    float v;
    if      (i < n1) v = W1[i];
    else if (i < n2) v = W2[i - n1];
    else if (i < n3) v = W3[i - n2];
    else if (i < n4) v = L1w[i - n3];
    else             v = L2w[i - n4];
    __nv_bfloat16 h = __float2bfloat16_rn(v);
    hi[i] = h;
    lo[i] = __float2bfloat16_rn(v - __bfloat162float(h));
}
__global__ void k_split512(const float* __restrict__ in, __nv_bfloat16* __restrict__ hi,
                           __nv_bfloat16* __restrict__ lo, int total) {
    int i = blockIdx.x * blockDim.x + threadIdx.x;
    if (i < total) {
        float v = lrelu_f(in[i]);
        __nv_bfloat16 h = __float2bfloat16_rn(v);
        hi[i] = h;
        lo[i] = __float2bfloat16_rn(v - __bfloat162float(h));
    }
}

// ------------------------------ CSR gathers ---------------------------------
// F=128 gather with FUSED self-loop init:
//   acc = H[node]*d2 (+ aggb[col]) + sum H[src]*norm ; opt lrelu ; presplit out.
__global__ void __launch_bounds__(256)
k_gather128(const float* __restrict__ H, const float* __restrict__ aggb,
            __nv_bfloat16* __restrict__ Ohi, __nv_bfloat16* __restrict__ Olo,
            const int* __restrict__ ptr, const int* __restrict__ csr,
            const float* __restrict__ dis, int Nn, int doLrelu)
{
    int node = (int)(((long long)blockIdx.x * blockDim.x + threadIdx.x) >> 5);
    int lane = threadIdx.x & 31;
    if (node >= Nn) return;

    int p0 = ptr[node];
    int p1 = ptr[node + 1];
    float dn = dis[node];
    float d2 = dn * dn;

    float4 acc = *(const float4*)(H + (long long)node * 128 + lane * 4);
    acc.x *= d2; acc.y *= d2; acc.z *= d2; acc.w *= d2;
    if (aggb) {
        float4 bv = *(const float4*)(aggb + lane * 4);
        acc.x += bv.x; acc.y += bv.y; acc.z += bv.z; acc.w += bv.w;
    }
    int p = p0;
    for (; p + 1 < p1; p += 2) {
        int s0 = csr[p], s1 = csr[p + 1];
        float n0 = dn * dis[s0], n1 = dn * dis[s1];
        float4 v0 = *(const float4*)(H + (long long)s0 * 128 + lane * 4);
        float4 v1 = *(const float4*)(H + (long long)s1 * 128 + lane * 4);
        acc.x += v0.x * n0; acc.y += v0.y * n0;
        acc.z += v0.z * n0; acc.w += v0.w * n0;
        acc.x += v1.x * n1; acc.y += v1.y * n1;
        acc.z += v1.z * n1; acc.w += v1.w * n1;
    }
    if (p < p1) {
        int s0 = csr[p];
        float n0 = dn * dis[s0];
        float4 v0 = *(const float4*)(H + (long long)s0 * 128 + lane * 4);
        acc.x += v0.x * n0; acc.y += v0.y * n0;
        acc.z += v0.z * n0; acc.w += v0.w * n0;
    }
    if (doLrelu) {
        acc.x = lrelu_f(acc.x); acc.y = lrelu_f(acc.y);
        acc.z = lrelu_f(acc.z); acc.w = lrelu_f(acc.w);
    }
    uint32_t h0, l0, h1, l1;
    split2(acc.x, acc.y, h0, l0);
    split2(acc.z, acc.w, h1, l1);
    long long o = (long long)node * 128 + lane * 4;
    *(uint2*)(Ohi + o) = make_uint2(h0, h1);
    *(uint2*)(Olo + o) = make_uint2(l0, l1);
}

// F=40 gather with fused self-loop; emits presplit [N,40].
__global__ void __launch_bounds__(256)
k_gather40(const float* __restrict__ X,
           __nv_bfloat16* __restrict__ Ohi, __nv_bfloat16* __restrict__ Olo,
           const int* __restrict__ ptr, const int* __restrict__ csr,
           const float* __restrict__ dis, int Nn)
{
    int node = (int)(((long long)blockIdx.x * blockDim.x + threadIdx.x) >> 5);
    int lane = threadIdx.x & 31;
    if (node >= Nn) return;

    int p0 = ptr[node];
    int p1 = ptr[node + 1];
    float dn = dis[node];
    float d2 = dn * dn;

    long long base = (long long)node * 40;
    float a0 = X[base + lane] * d2;
    float a1 = (lane < 8) ? X[base + 32 + lane] * d2 : 0.f;
    for (int p = p0; p < p1; p++) {
        int s = csr[p];
        float nm = dn * dis[s];
        long long hb = (long long)s * 40;
        a0 += X[hb + lane] * nm;
        if (lane < 8) a1 += X[hb + 32 + lane] * nm;
    }
    __nv_bfloat16 h = __float2bfloat16_rn(a0);
    Ohi[base + lane] = h;
    Olo[base + lane] = __float2bfloat16_rn(a0 - __bfloat162float(h));
    if (lane < 8) {
        __nv_bfloat16 h1 = __float2bfloat16_rn(a1);
        Ohi[base + 32 + lane] = h1;
        Olo[base + 32 + lane] = __float2bfloat16_rn(a1 - __bfloat162float(h1));
    }
}

// ------------------------ tensor-core bf16x3 GEMM ---------------------------
// C = A @ W^T ; A presplit (Ahi,Alo) [M,K] bf16; W presplit [Nout,K].
// kSplit>1: atomicAdd into pre-initialized H.
// else if Ohi: store presplit of (lreluOut? lrelu: id)(c + bias).
// else: H = (lreluOut? lrelu: id)(c + bias).
__global__ void __launch_bounds__(256, 2)
k_mma_gemm(const __nv_bfloat16* __restrict__ Ahi, const __nv_bfloat16* __restrict__ Alo,
           const __nv_bfloat16* __restrict__ Whi, const __nv_bfloat16* __restrict__ Wlo,
           float* __restrict__ H,
           __nv_bfloat16* __restrict__ Ohi, __nv_bfloat16* __restrict__ Olo,
           const float* __restrict__ bias,
           int M, int Nout, int K, int kLen, int lreluOut, int kSplit)
{
    extern __shared__ char smem[];
    const uint32_t sb = smem_u32(smem);
    const int tid  = threadIdx.x;
    const int wid  = tid >> 5;
    const int lane = tid & 31;
    const int g    = lane >> 2;
    const int tig  = lane & 3;
    const int warpM = wid >> 1;
    const int warpN = wid & 1;
    const int mBase = blockIdx.y * TILE_M;
    const int nBase = blockIdx.x * TILE_N;
    const long long zOff = (long long)blockIdx.z * kLen;

    float acc[2][8][4];
#pragma unroll
    for (int i = 0; i < 2; i++)
#pragma unroll
        for (int j = 0; j < 8; j++)
#pragma unroll
            for (int q = 0; q < 4; q++) acc[i][j][q] = 0.f;

    uint32_t aAddrH[2], aAddrL[2], bAddrH[2][2], bAddrL[2][2];
    {
        uint32_t aRowCol = (uint32_t)((warpM * 32 + (lane & 15)) * SROW + (lane >> 4) * 16);
#pragma unroll
        for (int ms = 0; ms < 2; ms++) {
            uint32_t off = aRowCol + (uint32_t)(ms * 16 * SROW);
            aAddrH[ms] = sb + OFF_AH + off;
            aAddrL[ms] = sb + OFF_AL + off;
        }
        uint32_t bRow = (uint32_t)(warpN * 64 + ((lane >> 4) & 1) * 8 + (lane & 7));
        uint32_t bCol = (uint32_t)(((lane >> 3) & 1) * 16);
#pragma unroll
        for (int nh = 0; nh < 2; nh++)
#pragma unroll
            for (int p = 0; p < 2; p++) {
                uint32_t off = (bRow + (uint32_t)(nh * 32 + p * 16)) * SROW + bCol;
                bAddrH[nh][p] = sb + OFF_WH + off;
                bAddrL[nh][p] = sb + OFF_WL + off;
            }
    }

    auto issueStage = [&](int stg, int kb) {
        const uint32_t so = sb + (uint32_t)(stg * STG_BYTES);
#pragma unroll
        for (int q = tid; q < 512; q += 256) {
            int row = q >> 2, kg = q & 3;
            long long gk = zOff + kb + kg * 8;
            uint32_t doff = (uint32_t)(row * SROW + kg * 16);
            {
                int gm = mBase + row;
                bool ok = (gm < M) && (gk + 8 <= (long long)K);
                long long aoff = ok ? ((long long)gm * K + gk) : 0;
                int ss = ok ? 16 : 0;
                cp16(so + OFF_AH + doff, Ahi + aoff, ss);
                cp16(so + OFF_AL + doff, Alo + aoff, ss);
            }
            {
                bool ok = (gk + 8 <= (long long)K);
                long long woff = ok ? ((long long)(nBase + row) * K + gk) : 0;
                int ss = ok ? 16 : 0;
                cp16(so + OFF_WH + doff, Whi + woff, ss);
                cp16(so + OFF_WL + doff, Wlo + woff, ss);
            }
        }
    };

    issueStage(0, 0);
    CP_COMMIT();

    int s = 0;
    for (int kb = 0; kb < kLen; kb += KC) {
        const bool more = (kb + KC) < kLen;
        if (more) { issueStage(s ^ 1, kb + KC); CP_COMMIT(); }
        if (more) CP_WAIT1(); else CP_WAIT0();
        __syncthreads();

        const uint32_t so = (uint32_t)(s * STG_BYTES);
#pragma unroll
        for (int kk = 0; kk < 2; kk++) {
            const uint32_t ko = so + (uint32_t)(kk * 32);
            uint32_t AH[2][4], AL[2][4];
#pragma unroll
            for (int ms = 0; ms < 2; ms++) {
                LDMX4(AH[ms], aAddrH[ms] + ko);
                LDMX4(AL[ms], aAddrL[ms] + ko);
            }
#pragma unroll
            for (int nh = 0; nh < 2; nh++) {
#pragma unroll
                for (int p = 0; p < 2; p++) {
                    uint32_t BH[4], BL[4];
                    LDMX4(BH, bAddrH[nh][p] + ko);
                    LDMX4(BL, bAddrL[nh][p] + ko);
                    const int j0 = nh * 4 + p * 2;
#pragma unroll
                    for (int ms = 0; ms < 2; ms++) {
                        mma16816(acc[ms][j0],     AH[ms], BH);
                        mma16816(acc[ms][j0],     AH[ms], BL);
                        mma16816(acc[ms][j0],     AL[ms], BH);
                        mma16816(acc[ms][j0 + 1], AH[ms], BH + 2);
                        mma16816(acc[ms][j0 + 1], AH[ms], BL + 2);
                        mma16816(acc[ms][j0 + 1], AL[ms], BH + 2);
                    }
                }
            }
        }
        __syncthreads();
        s ^= 1;
    }

    const int mW = mBase + warpM * 32;
#pragma unroll
    for (int ms = 0; ms < 2; ms++) {
#pragma unroll
        for (int half = 0; half < 2; half++) {
            int row = mW + ms * 16 + g + half * 8;
            if (row >= M) continue;
            long long ro = (long long)row * Nout;
#pragma unroll
            for (int ns = 0; ns < 8; ns++) {
                int col = nBase + warpN * 64 + ns * 8 + 2 * tig;
                float c0 = acc[ms][ns][half * 2 + 0];
                float c1 = acc[ms][ns][half * 2 + 1];
                if (kSplit > 1) {
                    atomicAdd(&H[ro + col + 0], c0);
                    atomicAdd(&H[ro + col + 1], c1);
                } else {
                    if (bias) { c0 += __ldg(&bias[col]); c1 += __ldg(&bias[col + 1]); }
                    if (lreluOut) { c0 = lrelu_f(c0); c1 = lrelu_f(c1); }
                    if (Ohi) {
                        uint32_t hp, lp;
                        split2(c0, c1, hp, lp);
                        *(uint32_t*)(Ohi + ro + col) = hp;
                        *(uint32_t*)(Olo + ro + col) = lp;
                    } else {
                        *(float2*)(H + ro + col) = make_float2(c0, c1);
                    }
                }
            }
        }
    }
}

// --------------------------- final linear + sigmoid -------------------------
__global__ void k_mlp_out(const float* __restrict__ g2, const float* __restrict__ L3w,
                          const float* __restrict__ L3b, float* __restrict__ out, int G)
{
    int w    = (blockIdx.x * blockDim.x + threadIdx.x) >> 5;
    int lane = threadIdx.x & 31;
    if (w >= G) return;
    float s = 0.f;
#pragma unroll
    for (int c = lane; c < 128; c += 32)
        s += lrelu_f(g2[(long long)w * 128 + c]) * __ldg(&L3w[c]);
#pragma unroll
    for (int off = 16; off; off >>= 1) s += __shfl_xor_sync(0xffffffffu, s, off);
    if (lane == 0) out[w] = 1.f / (1.f + expf(-(s + L3b[0])));
}

// ------------------------------- launch ------------------------------------
extern "C" void kernel_launch(void* const* d_in, const int* in_sizes, int n_in,
                              void* d_out, int out_size)
{
    const float* x   = (const float*)d_in[0];
    const int*   ei  = (const int*)d_in[1];
    const float* b1 = (const float*)d_in[3];
    const float* b2 = (const float*)d_in[5];
    const float* b3 = (const float*)d_in[7];
    const float* L1b = (const float*)d_in[9];
    const float* L2b = (const float*)d_in[11];
    const float* L3w = (const float*)d_in[12]; const float* L3b = (const float*)d_in[13];
    float* out = (float*)d_out;

    const int C = 40;
    const int N = in_sizes[0] / C;     // 200000
    const int E = in_sizes[1] / 2;     // 1000000
    const int G = N / 40;              // 5000

    const int* srcIdx = ei;
    const int* dstIdx = ei + E;

    float *bufA, *bufC, *dis;
    __nv_bfloat16 *whi, *wlo, *hiA, *loA, *hiB, *loB;
    int *ptr, *cursor, *csr, *bsum;
    cudaGetSymbolAddress((void**)&bufA, g_bufA);
    cudaGetSymbolAddress((void**)&bufC, g_bufC);
    cudaGetSymbolAddress((void**)&dis,  g_dis);
    cudaGetSymbolAddress((void**)&whi,  g_whi);
    cudaGetSymbolAddress((void**)&wlo,  g_wlo);
    cudaGetSymbolAddress((void**)&hiA,  g_hiA);
    cudaGetSymbolAddress((void**)&loA,  g_loA);
    cudaGetSymbolAddress((void**)&hiB,  g_hiB);
    cudaGetSymbolAddress((void**)&loB,  g_loB);
    cudaGetSymbolAddress((void**)&ptr,    g_ptr);
    cudaGetSymbolAddress((void**)&cursor, g_cursor);
    cudaGetSymbolAddress((void**)&csr,    g_csr);
    cudaGetSymbolAddress((void**)&bsum,   g_bsum);

    cudaFuncSetAttribute(k_mma_gemm, cudaFuncAttributeMaxDynamicSharedMemorySize, SMB);

    const int O1 = 0;
    const int O2 = O1 + 128 * 40;
    const int O3 = O2 + 256 * 128;
    const int O4 = O3 + 128 * 256;
    const int O5 = O4 + 512 * 5120;
    const int WTOT = O5 + 128 * 512;

    k_convW_all<<<(WTOT + 255) / 256, 256>>>(
        (const float*)d_in[2], (const float*)d_in[4], (const float*)d_in[6],
        (const float*)d_in[8], (const float*)d_in[10], whi, wlo);

    // ---- CSR build + degree normalization ----
    const int nb = (N + 1023) / 1024;
    k_zero_int <<<(N + 255) / 256, 256>>>(cursor, N);
    k_hist     <<<(E + 255) / 256, 256>>>(cursor, dstIdx, E);
    k_scan_block<<<nb, 1024>>>(cursor, ptr, bsum, dis, N);
    k_scan_bsum <<<1, 256>>>(bsum, nb, ptr + N);
    k_scan_add  <<<(N + 255) / 256, 256>>>(ptr, bsum, cursor, N);
    k_fill_csr  <<<(E + 255) / 256, 256>>>(srcIdx, dstIdx, cursor, csr, E);

    const int mTilesN = (N + 127) / 128;   // 1563
    const int mTilesG = (G + 127) / 128;   // 40
    const int gatherBlocks = (int)(((long long)N * 32 + 255) / 256);

    // ---- conv1 (aggregate-first): A1 = Âx -> presplit hiA/loA [N,40] ----
    k_gather40<<<gatherBlocks, 256>>>(x, hiA, loA, ptr, csr, dis, N);
    // GEMM1: P1 = lrelu(A1@W1^T + b1) -> bufA fp32 [N,128]
    k_mma_gemm<<<dim3(1, mTilesN, 1), 256, SMB>>>(
        hiA, loA, whi + O1, wlo + O1, bufA, nullptr, nullptr,
        b1, N, 128, 40, 64, 1, 1);

    // ---- conv2 (aggregate-first): A2 = ÂP1 (self-loop fused) -> hiB/loB ----
    k_gather128<<<gatherBlocks, 256>>>(bufA, nullptr, hiB, loB, ptr, csr, dis, N, 0);
    // GEMM2: lrelu(A2@W2^T + b2) -> presplit hiA/loA [N,256]
    k_mma_gemm<<<dim3(2, mTilesN, 1), 256, SMB>>>(
        hiB, loB, whi + O2, wlo + O2, nullptr, hiA, loA,
        b2, N, 256, 128, 128, 1, 1);

    // ---- conv3 (transform-first): H3t = in@W3^T -> bufA fp32 [N,128] ----
    k_mma_gemm<<<dim3(1, mTilesN, 1), 256, SMB>>>(
        hiA, loA, whi + O3, wlo + O3, bufA, nullptr, nullptr,
        nullptr, N, 128, 256, 256, 0, 1);
    // gather: AGG3 = ÂH3t + b3 (self-loop + bias fused), lrelu, presplit
    k_gather128<<<gatherBlocks, 256>>>(bufA, b3, hiB, loB, ptr, csr, dis, N, 1);

    // ---- MLP ----
    k_fill_bias<<<(G * 512 + 255) / 256, 256>>>(bufC, L1b, G, 512);
    k_mma_gemm<<<dim3(4, mTilesG, 4), 256, SMB>>>(
        hiB, loB, whi + O4, wlo + O4, bufC, nullptr, nullptr,
        nullptr, G, 512, 5120, 1280, 0, 4);
    k_split512<<<(G * 512 + 255) / 256, 256>>>(bufC, hiA, loA, G * 512);
    k_fill_bias<<<(G * 128 + 255) / 256, 256>>>(bufA, L2b, G, 128);
    k_mma_gemm<<<dim3(1, mTilesG, 4), 256, SMB>>>(
        hiA, loA, whi + O5, wlo + O5, bufA, nullptr, nullptr,
        nullptr, G, 128, 512, 128, 0, 4);
    k_mlp_out<<<(G * 32 + 255) / 256, 256>>>(bufA, L3w, L3b, out, G);
}

// round 12
// speedup vs baseline: 4.4852x; 1.0069x over previous
#include <cuda_runtime.h>
#include <cuda_bf16.h>
#include <math.h>
#include <stdint.h>

// ---------------------------------------------------------------------------
// GCN: 3x GCNConv(+lrelu) -> reshape(40/graph) -> 3x Linear -> sigmoid
// GEMMs: mma.sync m16n8k16 bf16x3 emulation, ldmatrix fragments, cp.async
// tile loads from PRE-SPLIT (hi,lo) bf16 activations/weights.
// Aggregation: dst-CSR gather; self-loop + agg-bias fused INTO the gather.
// Split-K via deterministic partial buffers + fused reduce (no float atomics).
// ---------------------------------------------------------------------------

#define TILE_M 128
#define TILE_N 128
#define KC 32
#define SROW 80
#define STG_BYTES (128 * SROW)

#define OFF_AH 0
#define OFF_AL (2 * STG_BYTES)
#define OFF_WH (4 * STG_BYTES)
#define OFF_WL (6 * STG_BYTES)
#define SMB    (8 * STG_BYTES)     // 81920 bytes

#define NMAX 200000
#define EMAX 1000000

__device__ __align__(256) float g_bufA[(size_t)NMAX * 128];
__device__ __align__(256) float g_bufC[(size_t)NMAX * 16];
__device__ __align__(256) float g_dis[NMAX];
__device__ __align__(256) __nv_bfloat16 g_whi[2760000];
__device__ __align__(256) __nv_bfloat16 g_wlo[2760000];
__device__ __align__(256) __nv_bfloat16 g_hiA[(size_t)NMAX * 256];
__device__ __align__(256) __nv_bfloat16 g_loA[(size_t)NMAX * 256];
__device__ __align__(256) __nv_bfloat16 g_hiB[(size_t)NMAX * 128];
__device__ __align__(256) __nv_bfloat16 g_loB[(size_t)NMAX * 128];
__device__ __align__(256) int g_ptr[NMAX + 1];
__device__ __align__(256) int g_cursor[NMAX];
__device__ __align__(256) int g_csr[EMAX];
__device__ __align__(256) int g_bsum[256];

__device__ __forceinline__ float lrelu_f(float v) { return v > 0.f ? v : 0.1f * v; }

__device__ __forceinline__ uint32_t smem_u32(const void* p) {
    uint32_t a;
    asm("{ .reg .u64 t; cvta.to.shared.u64 t, %1; cvt.u32.u64 %0, t; }" : "=r"(a) : "l"(p));
    return a;
}
__device__ __forceinline__ void mma16816(float* c, const uint32_t* a, const uint32_t* b) {
    asm volatile(
        "mma.sync.aligned.m16n8k16.row.col.f32.bf16.bf16.f32 "
        "{%0,%1,%2,%3}, {%4,%5,%6,%7}, {%8,%9}, {%0,%1,%2,%3};"
        : "+f"(c[0]), "+f"(c[1]), "+f"(c[2]), "+f"(c[3])
        : "r"(a[0]), "r"(a[1]), "r"(a[2]), "r"(a[3]), "r"(b[0]), "r"(b[1]));
}
#define LDMX4(r, addr) \
    asm volatile("ldmatrix.sync.aligned.m8n8.x4.shared.b16 {%0,%1,%2,%3}, [%4];" \
        : "=r"((r)[0]), "=r"((r)[1]), "=r"((r)[2]), "=r"((r)[3]) : "r"(addr))
__device__ __forceinline__ void cp16(uint32_t dst, const void* src, int srcsize) {
    asm volatile("cp.async.cg.shared.global [%0], [%1], 16, %2;"
                 :: "r"(dst), "l"(src), "r"(srcsize) : "memory");
}
#define CP_COMMIT() asm volatile("cp.async.commit_group;" ::: "memory")
#define CP_WAIT0()  asm volatile("cp.async.wait_group 0;" ::: "memory")
#define CP_WAIT1()  asm volatile("cp.async.wait_group 1;" ::: "memory")

__device__ __forceinline__ void split2(float c0, float c1, uint32_t& hp, uint32_t& lp) {
    __nv_bfloat16 h0 = __float2bfloat16_rn(c0), h1 = __float2bfloat16_rn(c1);
    __nv_bfloat16 l0 = __float2bfloat16_rn(c0 - __bfloat162float(h0));
    __nv_bfloat16 l1 = __float2bfloat16_rn(c1 - __bfloat162float(h1));
    hp = (uint32_t)__bfloat16_as_ushort(h0) | ((uint32_t)__bfloat16_as_ushort(h1) << 16);
    lp = (uint32_t)__bfloat16_as_ushort(l0) | ((uint32_t)__bfloat16_as_ushort(l1) << 16);
}

// --------------------------- CSR build kernels ------------------------------
__global__ void k_zero_int(int* p, int n) {
    int i = blockIdx.x * blockDim.x + threadIdx.x;
    if (i < n) p[i] = 0;
}
__global__ void k_hist(int* cnt, const int* __restrict__ dst, int E) {
    int e = blockIdx.x * blockDim.x + threadIdx.x;
    if (e < E) atomicAdd(&cnt[dst[e]], 1);
}
__global__ void k_scan_block(const int* __restrict__ cnt, int* __restrict__ ptr,
                             int* __restrict__ bsum, float* __restrict__ dis, int n) {
    __shared__ int sm[1024];
    int i = blockIdx.x * 1024 + threadIdx.x;
    int v = (i < n) ? cnt[i] : 0;
    if (i < n) dis[i] = rsqrtf((float)v + 1.0f);
    sm[threadIdx.x] = v;
    __syncthreads();
    for (int off = 1; off < 1024; off <<= 1) {
        int t = (threadIdx.x >= off) ? sm[threadIdx.x - off] : 0;
        __syncthreads();
        sm[threadIdx.x] += t;
        __syncthreads();
    }
    if (i < n) ptr[i] = sm[threadIdx.x] - v;
    if (threadIdx.x == 1023) bsum[blockIdx.x] = sm[1023];
}
__global__ void k_scan_bsum(int* bsum, int nb, int* totalOut) {
    __shared__ int sm[256];
    int v = (threadIdx.x < nb) ? bsum[threadIdx.x] : 0;
    sm[threadIdx.x] = v;
    __syncthreads();
    for (int off = 1; off < 256; off <<= 1) {
        int t = (threadIdx.x >= off) ? sm[threadIdx.x - off] : 0;
        __syncthreads();
        sm[threadIdx.x] += t;
        __syncthreads();
    }
    if (threadIdx.x < nb) bsum[threadIdx.x] = sm[threadIdx.x] - v;
    if (threadIdx.x == 255) *totalOut = sm[255];
}
__global__ void k_scan_add(int* __restrict__ ptr, const int* __restrict__ bsum,
                           int* __restrict__ cursor, int n) {
    int i = blockIdx.x * blockDim.x + threadIdx.x;
    if (i < n) {
        int p = ptr[i] + bsum[i >> 10];
        ptr[i] = p;
        cursor[i] = p;
    }
}
__global__ void k_fill_csr(const int* __restrict__ src, const int* __restrict__ dst,
                           int* cursor, int* __restrict__ csr, int E) {
    int e = blockIdx.x * blockDim.x + threadIdx.x;
    if (e < E) {
        int pos = atomicAdd(&cursor[dst[e]], 1);
        csr[pos] = src[e];
    }
}

// ---------------------------- misc small kernels ----------------------------
__global__ void k_convW_all(const float* __restrict__ W1, const float* __restrict__ W2,
                            const float* __restrict__ W3, const float* __restrict__ L1w,
                            const float* __restrict__ L2w,
                            __nv_bfloat16* __restrict__ hi, __nv_bfloat16* __restrict__ lo)
{
    const int n1 = 5120, n2 = n1 + 32768, n3 = n2 + 32768,
              n4 = n3 + 2621440, n5 = n4 + 65536;
    int i = blockIdx.x * blockDim.x + threadIdx.x;
    if (i >= n5) return;
    float v;
    if      (i < n1) v = W1[i];
    else if (i < n2) v = W2[i - n1];
    else if (i < n3) v = W3[i - n2];
    else if (i < n4) v = L1w[i - n3];
    else             v = L2w[i - n4];
    __nv_bfloat16 h = __float2bfloat16_rn(v);
    hi[i] = h;
    lo[i] = __float2bfloat16_rn(v - __bfloat162float(h));
}

// Deterministic split-K reduce: s = bias[col] + sum_z P[z][i].
// If Ohi: lrelu + presplit bf16 out. Else: fp32 out (no activation).
__global__ void k_reduce_split(const float* __restrict__ P, const float* __restrict__ bias,
                               __nv_bfloat16* __restrict__ Ohi, __nv_bfloat16* __restrict__ Olo,
                               float* __restrict__ Ofp, int total, int ncols, int nsplit)
{
    int i = blockIdx.x * blockDim.x + threadIdx.x;
    if (i >= total) return;
    float s = bias ? bias[i % ncols] : 0.f;
    for (int z = 0; z < nsplit; z++) s += P[(long long)z * total + i];
    if (Ohi) {
        float v = lrelu_f(s);
        __nv_bfloat16 h = __float2bfloat16_rn(v);
        Ohi[i] = h;
        Olo[i] = __float2bfloat16_rn(v - __bfloat162float(h));
    } else {
        Ofp[i] = s;
    }
}

// ------------------------------ CSR gathers ---------------------------------
// F=128 gather with FUSED self-loop init:
//   acc = H[node]*d2 (+ aggb[col]) + sum H[src]*norm ; opt lrelu ; presplit out.
__global__ void __launch_bounds__(256)
k_gather128(const float* __restrict__ H, const float* __restrict__ aggb,
            __nv_bfloat16* __restrict__ Ohi, __nv_bfloat16* __restrict__ Olo,
            const int* __restrict__ ptr, const int* __restrict__ csr,
            const float* __restrict__ dis, int Nn, int doLrelu)
{
    int node = (int)(((long long)blockIdx.x * blockDim.x + threadIdx.x) >> 5);
    int lane = threadIdx.x & 31;
    if (node >= Nn) return;

    int p0 = ptr[node];
    int p1 = ptr[node + 1];
    float dn = dis[node];
    float d2 = dn * dn;

    float4 acc = *(const float4*)(H + (long long)node * 128 + lane * 4);
    acc.x *= d2; acc.y *= d2; acc.z *= d2; acc.w *= d2;
    if (aggb) {
        float4 bv = *(const float4*)(aggb + lane * 4);
        acc.x += bv.x; acc.y += bv.y; acc.z += bv.z; acc.w += bv.w;
    }
    int p = p0;
    for (; p + 1 < p1; p += 2) {
        int s0 = csr[p], s1 = csr[p + 1];
        float n0 = dn * dis[s0], n1 = dn * dis[s1];
        float4 v0 = *(const float4*)(H + (long long)s0 * 128 + lane * 4);
        float4 v1 = *(const float4*)(H + (long long)s1 * 128 + lane * 4);
        acc.x += v0.x * n0; acc.y += v0.y * n0;
        acc.z += v0.z * n0; acc.w += v0.w * n0;
        acc.x += v1.x * n1; acc.y += v1.y * n1;
        acc.z += v1.z * n1; acc.w += v1.w * n1;
    }
    if (p < p1) {
        int s0 = csr[p];
        float n0 = dn * dis[s0];
        float4 v0 = *(const float4*)(H + (long long)s0 * 128 + lane * 4);
        acc.x += v0.x * n0; acc.y += v0.y * n0;
        acc.z += v0.z * n0; acc.w += v0.w * n0;
    }
    if (doLrelu) {
        acc.x = lrelu_f(acc.x); acc.y = lrelu_f(acc.y);
        acc.z = lrelu_f(acc.z); acc.w = lrelu_f(acc.w);
    }
    uint32_t h0, l0, h1, l1;
    split2(acc.x, acc.y, h0, l0);
    split2(acc.z, acc.w, h1, l1);
    long long o = (long long)node * 128 + lane * 4;
    *(uint2*)(Ohi + o) = make_uint2(h0, h1);
    *(uint2*)(Olo + o) = make_uint2(l0, l1);
}

// F=40 gather with fused self-loop; emits presplit [N,40].
__global__ void __launch_bounds__(256)
k_gather40(const float* __restrict__ X,
           __nv_bfloat16* __restrict__ Ohi, __nv_bfloat16* __restrict__ Olo,
           const int* __restrict__ ptr, const int* __restrict__ csr,
           const float* __restrict__ dis, int Nn)
{
    int node = (int)(((long long)blockIdx.x * blockDim.x + threadIdx.x) >> 5);
    int lane = threadIdx.x & 31;
    if (node >= Nn) return;

    int p0 = ptr[node];
    int p1 = ptr[node + 1];
    float dn = dis[node];
    float d2 = dn * dn;

    long long base = (long long)node * 40;
    float a0 = X[base + lane] * d2;
    float a1 = (lane < 8) ? X[base + 32 + lane] * d2 : 0.f;
    for (int p = p0; p < p1; p++) {
        int s = csr[p];
        float nm = dn * dis[s];
        long long hb = (long long)s * 40;
        a0 += X[hb + lane] * nm;
        if (lane < 8) a1 += X[hb + 32 + lane] * nm;
    }
    __nv_bfloat16 h = __float2bfloat16_rn(a0);
    Ohi[base + lane] = h;
    Olo[base + lane] = __float2bfloat16_rn(a0 - __bfloat162float(h));
    if (lane < 8) {
        __nv_bfloat16 h1 = __float2bfloat16_rn(a1);
        Ohi[base + 32 + lane] = h1;
        Olo[base + 32 + lane] = __float2bfloat16_rn(a1 - __bfloat162float(h1));
    }
}

// ------------------------ tensor-core bf16x3 GEMM ---------------------------
// C = A @ W^T ; A presplit (Ahi,Alo) [M,K] bf16; W presplit [Nout,K].
// kSplit>1: plain-store partial to H + z*M*Nout (deterministic split-K).
// else if Ohi: store presplit of (lreluOut? lrelu: id)(c + bias).
// else: H = (lreluOut? lrelu: id)(c + bias).
__global__ void __launch_bounds__(256, 2)
k_mma_gemm(const __nv_bfloat16* __restrict__ Ahi, const __nv_bfloat16* __restrict__ Alo,
           const __nv_bfloat16* __restrict__ Whi, const __nv_bfloat16* __restrict__ Wlo,
           float* __restrict__ H,
           __nv_bfloat16* __restrict__ Ohi, __nv_bfloat16* __restrict__ Olo,
           const float* __restrict__ bias,
           int M, int Nout, int K, int kLen, int lreluOut, int kSplit)
{
    extern __shared__ char smem[];
    const uint32_t sb = smem_u32(smem);
    const int tid  = threadIdx.x;
    const int wid  = tid >> 5;
    const int lane = tid & 31;
    const int g    = lane >> 2;
    const int tig  = lane & 3;
    const int warpM = wid >> 1;
    const int warpN = wid & 1;
    const int mBase = blockIdx.y * TILE_M;
    const int nBase = blockIdx.x * TILE_N;
    const long long zOff = (long long)blockIdx.z * kLen;

    float acc[2][8][4];
#pragma unroll
    for (int i = 0; i < 2; i++)
#pragma unroll
        for (int j = 0; j < 8; j++)
#pragma unroll
            for (int q = 0; q < 4; q++) acc[i][j][q] = 0.f;

    uint32_t aAddrH[2], aAddrL[2], bAddrH[2][2], bAddrL[2][2];
    {
        uint32_t aRowCol = (uint32_t)((warpM * 32 + (lane & 15)) * SROW + (lane >> 4) * 16);
#pragma unroll
        for (int ms = 0; ms < 2; ms++) {
            uint32_t off = aRowCol + (uint32_t)(ms * 16 * SROW);
            aAddrH[ms] = sb + OFF_AH + off;
            aAddrL[ms] = sb + OFF_AL + off;
        }
        uint32_t bRow = (uint32_t)(warpN * 64 + ((lane >> 4) & 1) * 8 + (lane & 7));
        uint32_t bCol = (uint32_t)(((lane >> 3) & 1) * 16);
#pragma unroll
        for (int nh = 0; nh < 2; nh++)
#pragma unroll
            for (int p = 0; p < 2; p++) {
                uint32_t off = (bRow + (uint32_t)(nh * 32 + p * 16)) * SROW + bCol;
                bAddrH[nh][p] = sb + OFF_WH + off;
                bAddrL[nh][p] = sb + OFF_WL + off;
            }
    }

    auto issueStage = [&](int stg, int kb) {
        const uint32_t so = sb + (uint32_t)(stg * STG_BYTES);
#pragma unroll
        for (int q = tid; q < 512; q += 256) {
            int row = q >> 2, kg = q & 3;
            long long gk = zOff + kb + kg * 8;
            uint32_t doff = (uint32_t)(row * SROW + kg * 16);
            {
                int gm = mBase + row;
                bool ok = (gm < M) && (gk + 8 <= (long long)K);
                long long aoff = ok ? ((long long)gm * K + gk) : 0;
                int ss = ok ? 16 : 0;
                cp16(so + OFF_AH + doff, Ahi + aoff, ss);
                cp16(so + OFF_AL + doff, Alo + aoff, ss);
            }
            {
                bool ok = (gk + 8 <= (long long)K);
                long long woff = ok ? ((long long)(nBase + row) * K + gk) : 0;
                int ss = ok ? 16 : 0;
                cp16(so + OFF_WH + doff, Whi + woff, ss);
                cp16(so + OFF_WL + doff, Wlo + woff, ss);
            }
        }
    };

    issueStage(0, 0);
    CP_COMMIT();

    int s = 0;
    for (int kb = 0; kb < kLen; kb += KC) {
        const bool more = (kb + KC) < kLen;
        if (more) { issueStage(s ^ 1, kb + KC); CP_COMMIT(); }
        if (more) CP_WAIT1(); else CP_WAIT0();
        __syncthreads();

        const uint32_t so = (uint32_t)(s * STG_BYTES);
#pragma unroll
        for (int kk = 0; kk < 2; kk++) {
            const uint32_t ko = so + (uint32_t)(kk * 32);
            uint32_t AH[2][4], AL[2][4];
#pragma unroll
            for (int ms = 0; ms < 2; ms++) {
                LDMX4(AH[ms], aAddrH[ms] + ko);
                LDMX4(AL[ms], aAddrL[ms] + ko);
            }
#pragma unroll
            for (int nh = 0; nh < 2; nh++) {
#pragma unroll
                for (int p = 0; p < 2; p++) {
                    uint32_t BH[4], BL[4];
                    LDMX4(BH, bAddrH[nh][p] + ko);
                    LDMX4(BL, bAddrL[nh][p] + ko);
                    const int j0 = nh * 4 + p * 2;
#pragma unroll
                    for (int ms = 0; ms < 2; ms++) {
                        mma16816(acc[ms][j0],     AH[ms], BH);
                        mma16816(acc[ms][j0],     AH[ms], BL);
                        mma16816(acc[ms][j0],     AL[ms], BH);
                        mma16816(acc[ms][j0 + 1], AH[ms], BH + 2);
                        mma16816(acc[ms][j0 + 1], AH[ms], BL + 2);
                        mma16816(acc[ms][j0 + 1], AL[ms], BH + 2);
                    }
                }
            }
        }
        __syncthreads();
        s ^= 1;
    }

    const int mW = mBase + warpM * 32;
    const long long zPart = (long long)blockIdx.z * M * Nout;
#pragma unroll
    for (int ms = 0; ms < 2; ms++) {
#pragma unroll
        for (int half = 0; half < 2; half++) {
            int row = mW + ms * 16 + g + half * 8;
            if (row >= M) continue;
            long long ro = (long long)row * Nout;
#pragma unroll
            for (int ns = 0; ns < 8; ns++) {
                int col = nBase + warpN * 64 + ns * 8 + 2 * tig;
                float c0 = acc[ms][ns][half * 2 + 0];
                float c1 = acc[ms][ns][half * 2 + 1];
                if (kSplit > 1) {
                    *(float2*)(H + zPart + ro + col) = make_float2(c0, c1);
                } else {
                    if (bias) { c0 += __ldg(&bias[col]); c1 += __ldg(&bias[col + 1]); }
                    if (lreluOut) { c0 = lrelu_f(c0); c1 = lrelu_f(c1); }
                    if (Ohi) {
                        uint32_t hp, lp;
                        split2(c0, c1, hp, lp);
                        *(uint32_t*)(Ohi + ro + col) = hp;
                        *(uint32_t*)(Olo + ro + col) = lp;
                    } else {
                        *(float2*)(H + ro + col) = make_float2(c0, c1);
                    }
                }
            }
        }
    }
}

// --------------------------- final linear + sigmoid -------------------------
__global__ void k_mlp_out(const float* __restrict__ g2, const float* __restrict__ L3w,
                          const float* __restrict__ L3b, float* __restrict__ out, int G)
{
    int w    = (blockIdx.x * blockDim.x + threadIdx.x) >> 5;
    int lane = threadIdx.x & 31;
    if (w >= G) return;
    float s = 0.f;
#pragma unroll
    for (int c = lane; c < 128; c += 32)
        s += lrelu_f(g2[(long long)w * 128 + c]) * __ldg(&L3w[c]);
#pragma unroll
    for (int off = 16; off; off >>= 1) s += __shfl_xor_sync(0xffffffffu, s, off);
    if (lane == 0) out[w] = 1.f / (1.f + expf(-(s + L3b[0])));
}

// ------------------------------- launch ------------------------------------
extern "C" void kernel_launch(void* const* d_in, const int* in_sizes, int n_in,
                              void* d_out, int out_size)
{
    const float* x   = (const float*)d_in[0];
    const int*   ei  = (const int*)d_in[1];
    const float* b1 = (const float*)d_in[3];
    const float* b2 = (const float*)d_in[5];
    const float* b3 = (const float*)d_in[7];
    const float* L1b = (const float*)d_in[9];
    const float* L2b = (const float*)d_in[11];
    const float* L3w = (const float*)d_in[12]; const float* L3b = (const float*)d_in[13];
    float* out = (float*)d_out;

    const int C = 40;
    const int N = in_sizes[0] / C;     // 200000
    const int E = in_sizes[1] / 2;     // 1000000
    const int G = N / 40;              // 5000

    const int* srcIdx = ei;
    const int* dstIdx = ei + E;

    float *bufA, *bufC, *dis;
    __nv_bfloat16 *whi, *wlo, *hiA, *loA, *hiB, *loB;
    int *ptr, *cursor, *csr, *bsum;
    cudaGetSymbolAddress((void**)&bufA, g_bufA);
    cudaGetSymbolAddress((void**)&bufC, g_bufC);
    cudaGetSymbolAddress((void**)&dis,  g_dis);
    cudaGetSymbolAddress((void**)&whi,  g_whi);
    cudaGetSymbolAddress((void**)&wlo,  g_wlo);
    cudaGetSymbolAddress((void**)&hiA,  g_hiA);
    cudaGetSymbolAddress((void**)&loA,  g_loA);
    cudaGetSymbolAddress((void**)&hiB,  g_hiB);
    cudaGetSymbolAddress((void**)&loB,  g_loB);
    cudaGetSymbolAddress((void**)&ptr,    g_ptr);
    cudaGetSymbolAddress((void**)&cursor, g_cursor);
    cudaGetSymbolAddress((void**)&csr,    g_csr);
    cudaGetSymbolAddress((void**)&bsum,   g_bsum);

    cudaFuncSetAttribute(k_mma_gemm, cudaFuncAttributeMaxDynamicSharedMemorySize, SMB);

    const int O1 = 0;
    const int O2 = O1 + 128 * 40;
    const int O3 = O2 + 256 * 128;
    const int O4 = O3 + 128 * 256;
    const int O5 = O4 + 512 * 5120;
    const int WTOT = O5 + 128 * 512;

    k_convW_all<<<(WTOT + 255) / 256, 256>>>(
        (const float*)d_in[2], (const float*)d_in[4], (const float*)d_in[6],
        (const float*)d_in[8], (const float*)d_in[10], whi, wlo);

    // ---- CSR build + degree normalization ----
    const int nb = (N + 1023) / 1024;
    k_zero_int <<<(N + 255) / 256, 256>>>(cursor, N);
    k_hist     <<<(E + 255) / 256, 256>>>(cursor, dstIdx, E);
    k_scan_block<<<nb, 1024>>>(cursor, ptr, bsum, dis, N);
    k_scan_bsum <<<1, 256>>>(bsum, nb, ptr + N);
    k_scan_add  <<<(N + 255) / 256, 256>>>(ptr, bsum, cursor, N);
    k_fill_csr  <<<(E + 255) / 256, 256>>>(srcIdx, dstIdx, cursor, csr, E);

    const int mTilesN = (N + 127) / 128;   // 1563
    const int mTilesG = (G + 127) / 128;   // 40
    const int gatherBlocks = (int)(((long long)N * 32 + 255) / 256);

    // ---- conv1 (aggregate-first): A1 = Âx -> presplit hiA/loA [N,40] ----
    k_gather40<<<gatherBlocks, 256>>>(x, hiA, loA, ptr, csr, dis, N);
    // GEMM1: P1 = lrelu(A1@W1^T + b1) -> bufA fp32 [N,128]
    k_mma_gemm<<<dim3(1, mTilesN, 1), 256, SMB>>>(
        hiA, loA, whi + O1, wlo + O1, bufA, nullptr, nullptr,
        b1, N, 128, 40, 64, 1, 1);

    // ---- conv2 (aggregate-first): A2 = ÂP1 (self-loop fused) -> hiB/loB ----
    k_gather128<<<gatherBlocks, 256>>>(bufA, nullptr, hiB, loB, ptr, csr, dis, N, 0);
    // GEMM2: lrelu(A2@W2^T + b2) -> presplit hiA/loA [N,256]
    k_mma_gemm<<<dim3(2, mTilesN, 1), 256, SMB>>>(
        hiB, loB, whi + O2, wlo + O2, nullptr, hiA, loA,
        b2, N, 256, 128, 128, 1, 1);

    // ---- conv3 (transform-first): H3t = in@W3^T -> bufA fp32 [N,128] ----
    k_mma_gemm<<<dim3(1, mTilesN, 1), 256, SMB>>>(
        hiA, loA, whi + O3, wlo + O3, bufA, nullptr, nullptr,
        nullptr, N, 128, 256, 256, 0, 1);
    // gather: AGG3 = ÂH3t + b3 (self-loop + bias fused), lrelu, presplit
    k_gather128<<<gatherBlocks, 256>>>(bufA, b3, hiB, loB, ptr, csr, dis, N, 1);

    // ---- MLP ----
    // L1 split-K x4 -> partials in bufA [4][G,512]; reduce -> presplit hiA/loA
    k_mma_gemm<<<dim3(4, mTilesG, 4), 256, SMB>>>(
        hiB, loB, whi + O4, wlo + O4, bufA, nullptr, nullptr,
        nullptr, G, 512, 5120, 1280, 0, 4);
    k_reduce_split<<<(G * 512 + 255) / 256, 256>>>(
        bufA, L1b, hiA, loA, nullptr, G * 512, 512, 4);
    // L2 split-K x4 -> partials in bufC [4][G,128]; reduce -> fp32 bufA
    k_mma_gemm<<<dim3(1, mTilesG, 4), 256, SMB>>>(
        hiA, loA, whi + O5, wlo + O5, bufC, nullptr, nullptr,
        nullptr, G, 128, 512, 128, 0, 4);
    k_reduce_split<<<(G * 128 + 255) / 256, 256>>>(
        bufC, L2b, nullptr, nullptr, bufA, G * 128, 128, 4);
    // L3 + sigmoid
    k_mlp_out<<<(G * 32 + 255) / 256, 256>>>(bufA, L3w, L3b, out, G);
}

// round 13
// speedup vs baseline: 4.5391x; 1.0120x over previous
#include <cuda_runtime.h>
#include <cuda_bf16.h>
#include <math.h>
#include <stdint.h>

// ---------------------------------------------------------------------------
// GCN: 3x GCNConv(+lrelu) -> reshape(40/graph) -> 3x Linear -> sigmoid
// GEMMs: mma.sync m16n8k16 bf16x3 emulation, ldmatrix fragments, cp.async
// tile loads from PRE-SPLIT (hi,lo) bf16 activations/weights.
// Aggregation: dst-CSR gather with NORM FOLDING (H pre-scaled by dis[row]
// in the GEMM epilogue -> gather inner loop is pure row adds).
// Split-K via deterministic partial buffers + fused reduce (no float atomics).
// ---------------------------------------------------------------------------

#define TILE_M 128
#define TILE_N 128
#define KC 32
#define SROW 80
#define STG_BYTES (128 * SROW)

#define OFF_AH 0
#define OFF_AL (2 * STG_BYTES)
#define OFF_WH (4 * STG_BYTES)
#define OFF_WL (6 * STG_BYTES)
#define SMB    (8 * STG_BYTES)     // 81920 bytes

#define NMAX 200000
#define EMAX 1000000

__device__ __align__(256) float g_bufA[(size_t)NMAX * 128];
__device__ __align__(256) float g_bufC[(size_t)NMAX * 16];
__device__ __align__(256) float g_dis[NMAX];
__device__ __align__(256) __nv_bfloat16 g_whi[2760000];
__device__ __align__(256) __nv_bfloat16 g_wlo[2760000];
__device__ __align__(256) __nv_bfloat16 g_hiA[(size_t)NMAX * 256];
__device__ __align__(256) __nv_bfloat16 g_loA[(size_t)NMAX * 256];
__device__ __align__(256) __nv_bfloat16 g_hiB[(size_t)NMAX * 128];
__device__ __align__(256) __nv_bfloat16 g_loB[(size_t)NMAX * 128];
__device__ __align__(256) int g_ptr[NMAX + 1];
__device__ __align__(256) int g_cursor[NMAX];
__device__ __align__(256) int g_csr[EMAX];
__device__ __align__(256) int g_bsum[256];

__device__ __forceinline__ float lrelu_f(float v) { return v > 0.f ? v : 0.1f * v; }

__device__ __forceinline__ uint32_t smem_u32(const void* p) {
    uint32_t a;
    asm("{ .reg .u64 t; cvta.to.shared.u64 t, %1; cvt.u32.u64 %0, t; }" : "=r"(a) : "l"(p));
    return a;
}
__device__ __forceinline__ void mma16816(float* c, const uint32_t* a, const uint32_t* b) {
    asm volatile(
        "mma.sync.aligned.m16n8k16.row.col.f32.bf16.bf16.f32 "
        "{%0,%1,%2,%3}, {%4,%5,%6,%7}, {%8,%9}, {%0,%1,%2,%3};"
        : "+f"(c[0]), "+f"(c[1]), "+f"(c[2]), "+f"(c[3])
        : "r"(a[0]), "r"(a[1]), "r"(a[2]), "r"(a[3]), "r"(b[0]), "r"(b[1]));
}
#define LDMX4(r, addr) \
    asm volatile("ldmatrix.sync.aligned.m8n8.x4.shared.b16 {%0,%1,%2,%3}, [%4];" \
        : "=r"((r)[0]), "=r"((r)[1]), "=r"((r)[2]), "=r"((r)[3]) : "r"(addr))
__device__ __forceinline__ void cp16(uint32_t dst, const void* src, int srcsize) {
    asm volatile("cp.async.cg.shared.global [%0], [%1], 16, %2;"
                 :: "r"(dst), "l"(src), "r"(srcsize) : "memory");
}
#define CP_COMMIT() asm volatile("cp.async.commit_group;" ::: "memory")
#define CP_WAIT0()  asm volatile("cp.async.wait_group 0;" ::: "memory")
#define CP_WAIT1()  asm volatile("cp.async.wait_group 1;" ::: "memory")

__device__ __forceinline__ void split2(float c0, float c1, uint32_t& hp, uint32_t& lp) {
    __nv_bfloat16 h0 = __float2bfloat16_rn(c0), h1 = __float2bfloat16_rn(c1);
    __nv_bfloat16 l0 = __float2bfloat16_rn(c0 - __bfloat162float(h0));
    __nv_bfloat16 l1 = __float2bfloat16_rn(c1 - __bfloat162float(h1));
    hp = (uint32_t)__bfloat16_as_ushort(h0) | ((uint32_t)__bfloat16_as_ushort(h1) << 16);
    lp = (uint32_t)__bfloat16_as_ushort(l0) | ((uint32_t)__bfloat16_as_ushort(l1) << 16);
}

// --------------------------- CSR build kernels ------------------------------
__global__ void k_zero_int(int* p, int n) {
    int i = blockIdx.x * blockDim.x + threadIdx.x;
    if (i < n) p[i] = 0;
}
__global__ void k_hist(int* cnt, const int* __restrict__ dst, int E) {
    int e = blockIdx.x * blockDim.x + threadIdx.x;
    if (e < E) atomicAdd(&cnt[dst[e]], 1);
}
__global__ void k_scan_block(const int* __restrict__ cnt, int* __restrict__ ptr,
                             int* __restrict__ bsum, float* __restrict__ dis, int n) {
    __shared__ int sm[1024];
    int i = blockIdx.x * 1024 + threadIdx.x;
    int v = (i < n) ? cnt[i] : 0;
    if (i < n) dis[i] = rsqrtf((float)v + 1.0f);
    sm[threadIdx.x] = v;
    __syncthreads();
    for (int off = 1; off < 1024; off <<= 1) {
        int t = (threadIdx.x >= off) ? sm[threadIdx.x - off] : 0;
        __syncthreads();
        sm[threadIdx.x] += t;
        __syncthreads();
    }
    if (i < n) ptr[i] = sm[threadIdx.x] - v;
    if (threadIdx.x == 1023) bsum[blockIdx.x] = sm[1023];
}
__global__ void k_scan_bsum(int* bsum, int nb, int* totalOut) {
    __shared__ int sm[256];
    int v = (threadIdx.x < nb) ? bsum[threadIdx.x] : 0;
    sm[threadIdx.x] = v;
    __syncthreads();
    for (int off = 1; off < 256; off <<= 1) {
        int t = (threadIdx.x >= off) ? sm[threadIdx.x - off] : 0;
        __syncthreads();
        sm[threadIdx.x] += t;
        __syncthreads();
    }
    if (threadIdx.x < nb) bsum[threadIdx.x] = sm[threadIdx.x] - v;
    if (threadIdx.x == 255) *totalOut = sm[255];
}
__global__ void k_scan_add(int* __restrict__ ptr, const int* __restrict__ bsum,
                           int* __restrict__ cursor, int n) {
    int i = blockIdx.x * blockDim.x + threadIdx.x;
    if (i < n) {
        int p = ptr[i] + bsum[i >> 10];
        ptr[i] = p;
        cursor[i] = p;
    }
}
__global__ void k_fill_csr(const int* __restrict__ src, const int* __restrict__ dst,
                           int* cursor, int* __restrict__ csr, int E) {
    int e = blockIdx.x * blockDim.x + threadIdx.x;
    if (e < E) {
        int pos = atomicAdd(&cursor[dst[e]], 1);
        csr[pos] = src[e];
    }
}

// ---------------------------- misc small kernels ----------------------------
__global__ void k_convW_all(const float* __restrict__ W1, const float* __restrict__ W2,
                            const float* __restrict__ W3, const float* __restrict__ L1w,
                            const float* __restrict__ L2w,
                            __nv_bfloat16* __restrict__ hi, __nv_bfloat16* __restrict__ lo)
{
    const int n1 = 5120, n2 = n1 + 32768, n3 = n2 + 32768,
              n4 = n3 + 2621440, n5 = n4 + 65536;
    int i = blockIdx.x * blockDim.x + threadIdx.x;
    if (i >= n5) return;
    float v;
    if      (i < n1) v = W1[i];
    else if (i < n2) v = W2[i - n1];
    else if (i < n3) v = W3[i - n2];
    else if (i < n4) v = L1w[i - n3];
    else             v = L2w[i - n4];
    __nv_bfloat16 h = __float2bfloat16_rn(v);
    hi[i] = h;
    lo[i] = __float2bfloat16_rn(v - __bfloat162float(h));
}

// Deterministic split-K reduce: s = bias[col] + sum_z P[z][i]; lrelu; presplit.
__global__ void k_reduce_split(const float* __restrict__ P, const float* __restrict__ bias,
                               __nv_bfloat16* __restrict__ Ohi, __nv_bfloat16* __restrict__ Olo,
                               int total, int ncols, int nsplit)
{
    int i = blockIdx.x * blockDim.x + threadIdx.x;
    if (i >= total) return;
    float s = bias[i % ncols];
    for (int z = 0; z < nsplit; z++) s += P[(long long)z * total + i];
    float v = lrelu_f(s);
    __nv_bfloat16 h = __float2bfloat16_rn(v);
    Ohi[i] = h;
    Olo[i] = __float2bfloat16_rn(v - __bfloat162float(h));
}

// ------------------------------ CSR gathers ---------------------------------
// F=128 gather, norm-folded: input H' is already scaled by dis[row].
//   acc = dis[node]*(H'[node] + sum H'[src]) (+ aggb[col]) ; opt lrelu ; presplit.
__global__ void __launch_bounds__(256)
k_gather128(const float* __restrict__ H, const float* __restrict__ aggb,
            __nv_bfloat16* __restrict__ Ohi, __nv_bfloat16* __restrict__ Olo,
            const int* __restrict__ ptr, const int* __restrict__ csr,
            const float* __restrict__ dis, int Nn, int doLrelu)
{
    int node = (int)(((long long)blockIdx.x * blockDim.x + threadIdx.x) >> 5);
    int lane = threadIdx.x & 31;
    if (node >= Nn) return;

    int p0 = ptr[node];
    int p1 = ptr[node + 1];
    float dn = dis[node];

    float4 acc = *(const float4*)(H + (long long)node * 128 + lane * 4);
    int p = p0;
    for (; p + 1 < p1; p += 2) {
        int s0 = csr[p], s1 = csr[p + 1];
        float4 v0 = *(const float4*)(H + (long long)s0 * 128 + lane * 4);
        float4 v1 = *(const float4*)(H + (long long)s1 * 128 + lane * 4);
        acc.x += v0.x + v1.x; acc.y += v0.y + v1.y;
        acc.z += v0.z + v1.z; acc.w += v0.w + v1.w;
    }
    if (p < p1) {
        int s0 = csr[p];
        float4 v0 = *(const float4*)(H + (long long)s0 * 128 + lane * 4);
        acc.x += v0.x; acc.y += v0.y; acc.z += v0.z; acc.w += v0.w;
    }
    acc.x *= dn; acc.y *= dn; acc.z *= dn; acc.w *= dn;
    if (aggb) {
        float4 bv = *(const float4*)(aggb + lane * 4);
        acc.x += bv.x; acc.y += bv.y; acc.z += bv.z; acc.w += bv.w;
    }
    if (doLrelu) {
        acc.x = lrelu_f(acc.x); acc.y = lrelu_f(acc.y);
        acc.z = lrelu_f(acc.z); acc.w = lrelu_f(acc.w);
    }
    uint32_t h0, l0, h1, l1;
    split2(acc.x, acc.y, h0, l0);
    split2(acc.z, acc.w, h1, l1);
    long long o = (long long)node * 128 + lane * 4;
    *(uint2*)(Ohi + o) = make_uint2(h0, h1);
    *(uint2*)(Olo + o) = make_uint2(l0, l1);
}

// F=40 gather with fused self-loop (x unscaled); emits presplit [N,40].
__global__ void __launch_bounds__(256)
k_gather40(const float* __restrict__ X,
           __nv_bfloat16* __restrict__ Ohi, __nv_bfloat16* __restrict__ Olo,
           const int* __restrict__ ptr, const int* __restrict__ csr,
           const float* __restrict__ dis, int Nn)
{
    int node = (int)(((long long)blockIdx.x * blockDim.x + threadIdx.x) >> 5);
    int lane = threadIdx.x & 31;
    if (node >= Nn) return;

    int p0 = ptr[node];
    int p1 = ptr[node + 1];
    float dn = dis[node];
    float d2 = dn * dn;

    long long base = (long long)node * 40;
    float a0 = X[base + lane] * d2;
    float a1 = (lane < 8) ? X[base + 32 + lane] * d2 : 0.f;
    for (int p = p0; p < p1; p++) {
        int s = csr[p];
        float nm = dn * dis[s];
        long long hb = (long long)s * 40;
        a0 += X[hb + lane] * nm;
        if (lane < 8) a1 += X[hb + 32 + lane] * nm;
    }
    __nv_bfloat16 h = __float2bfloat16_rn(a0);
    Ohi[base + lane] = h;
    Olo[base + lane] = __float2bfloat16_rn(a0 - __bfloat162float(h));
    if (lane < 8) {
        __nv_bfloat16 h1 = __float2bfloat16_rn(a1);
        Ohi[base + 32 + lane] = h1;
        Olo[base + 32 + lane] = __float2bfloat16_rn(a1 - __bfloat162float(h1));
    }
}

// ------------------------ tensor-core bf16x3 GEMM ---------------------------
// C = A @ W^T ; A presplit (Ahi,Alo) [M,K] bf16; W presplit [Nout,K].
// kSplit>1: plain-store partial to H + z*M*Nout (deterministic split-K).
// else if Ohi: store presplit of (lreluOut? lrelu: id)(c + bias).
// else: H = (lreluOut? lrelu: id)(c + bias) * (rowScale ? rowScale[row] : 1).
__global__ void __launch_bounds__(256, 2)
k_mma_gemm(const __nv_bfloat16* __restrict__ Ahi, const __nv_bfloat16* __restrict__ Alo,
           const __nv_bfloat16* __restrict__ Whi, const __nv_bfloat16* __restrict__ Wlo,
           float* __restrict__ H,
           __nv_bfloat16* __restrict__ Ohi, __nv_bfloat16* __restrict__ Olo,
           const float* __restrict__ bias, const float* __restrict__ rowScale,
           int M, int Nout, int K, int kLen, int lreluOut, int kSplit)
{
    extern __shared__ char smem[];
    const uint32_t sb = smem_u32(smem);
    const int tid  = threadIdx.x;
    const int wid  = tid >> 5;
    const int lane = tid & 31;
    const int g    = lane >> 2;
    const int tig  = lane & 3;
    const int warpM = wid >> 1;
    const int warpN = wid & 1;
    const int mBase = blockIdx.y * TILE_M;
    const int nBase = blockIdx.x * TILE_N;
    const long long zOff = (long long)blockIdx.z * kLen;

    float acc[2][8][4];
#pragma unroll
    for (int i = 0; i < 2; i++)
#pragma unroll
        for (int j = 0; j < 8; j++)
#pragma unroll
            for (int q = 0; q < 4; q++) acc[i][j][q] = 0.f;

    uint32_t aAddrH[2], aAddrL[2], bAddrH[2][2], bAddrL[2][2];
    {
        uint32_t aRowCol = (uint32_t)((warpM * 32 + (lane & 15)) * SROW + (lane >> 4) * 16);
#pragma unroll
        for (int ms = 0; ms < 2; ms++) {
            uint32_t off = aRowCol + (uint32_t)(ms * 16 * SROW);
            aAddrH[ms] = sb + OFF_AH + off;
            aAddrL[ms] = sb + OFF_AL + off;
        }
        uint32_t bRow = (uint32_t)(warpN * 64 + ((lane >> 4) & 1) * 8 + (lane & 7));
        uint32_t bCol = (uint32_t)(((lane >> 3) & 1) * 16);
#pragma unroll
        for (int nh = 0; nh < 2; nh++)
#pragma unroll
            for (int p = 0; p < 2; p++) {
                uint32_t off = (bRow + (uint32_t)(nh * 32 + p * 16)) * SROW + bCol;
                bAddrH[nh][p] = sb + OFF_WH + off;
                bAddrL[nh][p] = sb + OFF_WL + off;
            }
    }

    auto issueStage = [&](int stg, int kb) {
        const uint32_t so = sb + (uint32_t)(stg * STG_BYTES);
#pragma unroll
        for (int q = tid; q < 512; q += 256) {
            int row = q >> 2, kg = q & 3;
            long long gk = zOff + kb + kg * 8;
            uint32_t doff = (uint32_t)(row * SROW + kg * 16);
            {
                int gm = mBase + row;
                bool ok = (gm < M) && (gk + 8 <= (long long)K);
                long long aoff = ok ? ((long long)gm * K + gk) : 0;
                int ss = ok ? 16 : 0;
                cp16(so + OFF_AH + doff, Ahi + aoff, ss);
                cp16(so + OFF_AL + doff, Alo + aoff, ss);
            }
            {
                bool ok = (gk + 8 <= (long long)K);
                long long woff = ok ? ((long long)(nBase + row) * K + gk) : 0;
                int ss = ok ? 16 : 0;
                cp16(so + OFF_WH + doff, Whi + woff, ss);
                cp16(so + OFF_WL + doff, Wlo + woff, ss);
            }
        }
    };

    issueStage(0, 0);
    CP_COMMIT();

    int s = 0;
    for (int kb = 0; kb < kLen; kb += KC) {
        const bool more = (kb + KC) < kLen;
        if (more) { issueStage(s ^ 1, kb + KC); CP_COMMIT(); }
        if (more) CP_WAIT1(); else CP_WAIT0();
        __syncthreads();

        const uint32_t so = (uint32_t)(s * STG_BYTES);
#pragma unroll
        for (int kk = 0; kk < 2; kk++) {
            const uint32_t ko = so + (uint32_t)(kk * 32);
            uint32_t AH[2][4], AL[2][4];
#pragma unroll
            for (int ms = 0; ms < 2; ms++) {
                LDMX4(AH[ms], aAddrH[ms] + ko);
                LDMX4(AL[ms], aAddrL[ms] + ko);
            }
#pragma unroll
            for (int nh = 0; nh < 2; nh++) {
#pragma unroll
                for (int p = 0; p < 2; p++) {
                    uint32_t BH[4], BL[4];
                    LDMX4(BH, bAddrH[nh][p] + ko);
                    LDMX4(BL, bAddrL[nh][p] + ko);
                    const int j0 = nh * 4 + p * 2;
#pragma unroll
                    for (int ms = 0; ms < 2; ms++) {
                        mma16816(acc[ms][j0],     AH[ms], BH);
                        mma16816(acc[ms][j0],     AH[ms], BL);
                        mma16816(acc[ms][j0],     AL[ms], BH);
                        mma16816(acc[ms][j0 + 1], AH[ms], BH + 2);
                        mma16816(acc[ms][j0 + 1], AH[ms], BL + 2);
                        mma16816(acc[ms][j0 + 1], AL[ms], BH + 2);
                    }
                }
            }
        }
        __syncthreads();
        s ^= 1;
    }

    const int mW = mBase + warpM * 32;
    const long long zPart = (long long)blockIdx.z * M * Nout;
#pragma unroll
    for (int ms = 0; ms < 2; ms++) {
#pragma unroll
        for (int half = 0; half < 2; half++) {
            int row = mW + ms * 16 + g + half * 8;
            if (row >= M) continue;
            long long ro = (long long)row * Nout;
            float rs = 1.f;
            if (rowScale) rs = rowScale[row];
#pragma unroll
            for (int ns = 0; ns < 8; ns++) {
                int col = nBase + warpN * 64 + ns * 8 + 2 * tig;
                float c0 = acc[ms][ns][half * 2 + 0];
                float c1 = acc[ms][ns][half * 2 + 1];
                if (kSplit > 1) {
                    *(float2*)(H + zPart + ro + col) = make_float2(c0, c1);
                } else {
                    if (bias) { c0 += __ldg(&bias[col]); c1 += __ldg(&bias[col + 1]); }
                    if (lreluOut) { c0 = lrelu_f(c0); c1 = lrelu_f(c1); }
                    if (Ohi) {
                        uint32_t hp, lp;
                        split2(c0, c1, hp, lp);
                        *(uint32_t*)(Ohi + ro + col) = hp;
                        *(uint32_t*)(Olo + ro + col) = lp;
                    } else {
                        *(float2*)(H + ro + col) = make_float2(c0 * rs, c1 * rs);
                    }
                }
            }
        }
    }
}

// ---------------- final linear + sigmoid (fused L2 split-K reduce) -----------
// g2[w][c] = lrelu(L2b[c] + sum_z P[z][w*128+c]); out = sigmoid(g2 . L3w + L3b)
__global__ void k_mlp_out(const float* __restrict__ P, const float* __restrict__ L2b,
                          const float* __restrict__ L3w, const float* __restrict__ L3b,
                          float* __restrict__ out, int G, int nsplit)
{
    int w    = (blockIdx.x * blockDim.x + threadIdx.x) >> 5;
    int lane = threadIdx.x & 31;
    if (w >= G) return;
    const int total = G * 128;
    float s = 0.f;
#pragma unroll
    for (int c = lane; c < 128; c += 32) {
        float v = __ldg(&L2b[c]);
        long long idx = (long long)w * 128 + c;
        for (int z = 0; z < nsplit; z++) v += P[(long long)z * total + idx];
        s += lrelu_f(v) * __ldg(&L3w[c]);
    }
#pragma unroll
    for (int off = 16; off; off >>= 1) s += __shfl_xor_sync(0xffffffffu, s, off);
    if (lane == 0) out[w] = 1.f / (1.f + expf(-(s + L3b[0])));
}

// ------------------------------- launch ------------------------------------
extern "C" void kernel_launch(void* const* d_in, const int* in_sizes, int n_in,
                              void* d_out, int out_size)
{
    const float* x   = (const float*)d_in[0];
    const int*   ei  = (const int*)d_in[1];
    const float* b1 = (const float*)d_in[3];
    const float* b2 = (const float*)d_in[5];
    const float* b3 = (const float*)d_in[7];
    const float* L1b = (const float*)d_in[9];
    const float* L2b = (const float*)d_in[11];
    const float* L3w = (const float*)d_in[12]; const float* L3b = (const float*)d_in[13];
    float* out = (float*)d_out;

    const int C = 40;
    const int N = in_sizes[0] / C;     // 200000
    const int E = in_sizes[1] / 2;     // 1000000
    const int G = N / 40;              // 5000

    const int* srcIdx = ei;
    const int* dstIdx = ei + E;

    float *bufA, *bufC, *dis;
    __nv_bfloat16 *whi, *wlo, *hiA, *loA, *hiB, *loB;
    int *ptr, *cursor, *csr, *bsum;
    cudaGetSymbolAddress((void**)&bufA, g_bufA);
    cudaGetSymbolAddress((void**)&bufC, g_bufC);
    cudaGetSymbolAddress((void**)&dis,  g_dis);
    cudaGetSymbolAddress((void**)&whi,  g_whi);
    cudaGetSymbolAddress((void**)&wlo,  g_wlo);
    cudaGetSymbolAddress((void**)&hiA,  g_hiA);
    cudaGetSymbolAddress((void**)&loA,  g_loA);
    cudaGetSymbolAddress((void**)&hiB,  g_hiB);
    cudaGetSymbolAddress((void**)&loB,  g_loB);
    cudaGetSymbolAddress((void**)&ptr,    g_ptr);
    cudaGetSymbolAddress((void**)&cursor, g_cursor);
    cudaGetSymbolAddress((void**)&csr,    g_csr);
    cudaGetSymbolAddress((void**)&bsum,   g_bsum);

    cudaFuncSetAttribute(k_mma_gemm, cudaFuncAttributeMaxDynamicSharedMemorySize, SMB);

    const int O1 = 0;
    const int O2 = O1 + 128 * 40;
    const int O3 = O2 + 256 * 128;
    const int O4 = O3 + 128 * 256;
    const int O5 = O4 + 512 * 5120;
    const int WTOT = O5 + 128 * 512;

    k_convW_all<<<(WTOT + 255) / 256, 256>>>(
        (const float*)d_in[2], (const float*)d_in[4], (const float*)d_in[6],
        (const float*)d_in[8], (const float*)d_in[10], whi, wlo);

    // ---- CSR build + degree normalization ----
    const int nb = (N + 1023) / 1024;
    k_zero_int <<<(N + 255) / 256, 256>>>(cursor, N);
    k_hist     <<<(E + 255) / 256, 256>>>(cursor, dstIdx, E);
    k_scan_block<<<nb, 1024>>>(cursor, ptr, bsum, dis, N);
    k_scan_bsum <<<1, 256>>>(bsum, nb, ptr + N);
    k_scan_add  <<<(N + 255) / 256, 256>>>(ptr, bsum, cursor, N);
    k_fill_csr  <<<(E + 255) / 256, 256>>>(srcIdx, dstIdx, cursor, csr, E);

    const int mTilesN = (N + 127) / 128;   // 1563
    const int mTilesG = (G + 127) / 128;   // 40
    const int gatherBlocks = (int)(((long long)N * 32 + 255) / 256);

    // ---- conv1 (aggregate-first): A1 = Âx -> presplit hiA/loA [N,40] ----
    k_gather40<<<gatherBlocks, 256>>>(x, hiA, loA, ptr, csr, dis, N);
    // GEMM1: P1' = lrelu(A1@W1^T + b1) * dis -> bufA fp32 [N,128]  (norm-folded)
    k_mma_gemm<<<dim3(1, mTilesN, 1), 256, SMB>>>(
        hiA, loA, whi + O1, wlo + O1, bufA, nullptr, nullptr,
        b1, dis, N, 128, 40, 64, 1, 1);

    // ---- conv2 (aggregate-first): A2 = dis*(P1'[d] + sum P1'[s]) -> hiB/loB ----
    k_gather128<<<gatherBlocks, 256>>>(bufA, nullptr, hiB, loB, ptr, csr, dis, N, 0);
    // GEMM2: lrelu(A2@W2^T + b2) -> presplit hiA/loA [N,256]
    k_mma_gemm<<<dim3(2, mTilesN, 1), 256, SMB>>>(
        hiB, loB, whi + O2, wlo + O2, nullptr, hiA, loA,
        b2, nullptr, N, 256, 128, 128, 1, 1);

    // ---- conv3 (transform-first): H3' = (in@W3^T)*dis -> bufA fp32 [N,128] ----
    k_mma_gemm<<<dim3(1, mTilesN, 1), 256, SMB>>>(
        hiA, loA, whi + O3, wlo + O3, bufA, nullptr, nullptr,
        nullptr, dis, N, 128, 256, 256, 0, 1);
    // gather: AGG3 = dis*(H3'[d] + sum H3'[s]) + b3, lrelu, presplit
    k_gather128<<<gatherBlocks, 256>>>(bufA, b3, hiB, loB, ptr, csr, dis, N, 1);

    // ---- MLP ----
    // L1 split-K x4 -> partials in bufA [4][G,512]; reduce -> presplit hiA/loA
    k_mma_gemm<<<dim3(4, mTilesG, 4), 256, SMB>>>(
        hiB, loB, whi + O4, wlo + O4, bufA, nullptr, nullptr,
        nullptr, nullptr, G, 512, 5120, 1280, 0, 4);
    k_reduce_split<<<(G * 512 + 255) / 256, 256>>>(
        bufA, L1b, hiA, loA, G * 512, 512, 4);
    // L2 split-K x4 -> partials in bufC [4][G,128]; reduce fused into mlp_out
    k_mma_gemm<<<dim3(1, mTilesG, 4), 256, SMB>>>(
        hiA, loA, whi + O5, wlo + O5, bufC, nullptr, nullptr,
        nullptr, nullptr, G, 128, 512, 128, 0, 4);
    k_mlp_out<<<(G * 32 + 255) / 256, 256>>>(bufC, L2b, L3w, L3b, out, G, 4);
}

// round 14
// speedup vs baseline: 4.9947x; 1.1004x over previous
#include <cuda_runtime.h>
#include <cuda_bf16.h>
#include <math.h>
#include <stdint.h>

// ---------------------------------------------------------------------------
// GCN: 3x GCNConv(+lrelu) -> reshape(40/graph) -> 3x Linear -> sigmoid
// GEMMs: mma.sync m16n8k16 bf16x3 emulation, ldmatrix fragments, cp.async,
// 3-stage smem ring with XOR swizzle (SROW=64), one barrier per k-chunk.
// Aggregation: dst-CSR gather with norm folding. Deterministic split-K.
// ---------------------------------------------------------------------------

#define TILE_M 128
#define TILE_N 128
#define KC 32
#define SROW 64
#define ARR_BYTES (128 * SROW)        // 8192 per array per stage
#define SOFF_AH 0
#define SOFF_AL (1 * ARR_BYTES)
#define SOFF_WH (2 * ARR_BYTES)
#define SOFF_WL (3 * ARR_BYTES)
#define STAGE_STRIDE (4 * ARR_BYTES)  // 32768
#define SMB (3 * STAGE_STRIDE)        // 98304

#define NMAX 200000
#define EMAX 1000000

__device__ __align__(256) float g_bufA[(size_t)NMAX * 128];
__device__ __align__(256) float g_bufC[(size_t)NMAX * 16];
__device__ __align__(256) float g_dis[NMAX];
__device__ __align__(256) __nv_bfloat16 g_whi[2760000];
__device__ __align__(256) __nv_bfloat16 g_wlo[2760000];
__device__ __align__(256) __nv_bfloat16 g_hiA[(size_t)NMAX * 256];
__device__ __align__(256) __nv_bfloat16 g_loA[(size_t)NMAX * 256];
__device__ __align__(256) __nv_bfloat16 g_hiB[(size_t)NMAX * 128];
__device__ __align__(256) __nv_bfloat16 g_loB[(size_t)NMAX * 128];
__device__ __align__(256) int g_ptr[NMAX + 1];
__device__ __align__(256) int g_cursor[NMAX];
__device__ __align__(256) int g_csr[EMAX];
__device__ __align__(256) int g_bsum[256];

__device__ __forceinline__ float lrelu_f(float v) { return v > 0.f ? v : 0.1f * v; }

__device__ __forceinline__ uint32_t smem_u32(const void* p) {
    uint32_t a;
    asm("{ .reg .u64 t; cvta.to.shared.u64 t, %1; cvt.u32.u64 %0, t; }" : "=r"(a) : "l"(p));
    return a;
}
__device__ __forceinline__ void mma16816(float* c, const uint32_t* a, const uint32_t* b) {
    asm volatile(
        "mma.sync.aligned.m16n8k16.row.col.f32.bf16.bf16.f32 "
        "{%0,%1,%2,%3}, {%4,%5,%6,%7}, {%8,%9}, {%0,%1,%2,%3};"
        : "+f"(c[0]), "+f"(c[1]), "+f"(c[2]), "+f"(c[3])
        : "r"(a[0]), "r"(a[1]), "r"(a[2]), "r"(a[3]), "r"(b[0]), "r"(b[1]));
}
#define LDMX4(r, addr) \
    asm volatile("ldmatrix.sync.aligned.m8n8.x4.shared.b16 {%0,%1,%2,%3}, [%4];" \
        : "=r"((r)[0]), "=r"((r)[1]), "=r"((r)[2]), "=r"((r)[3]) : "r"(addr))
__device__ __forceinline__ void cp16(uint32_t dst, const void* src, int srcsize) {
    asm volatile("cp.async.cg.shared.global [%0], [%1], 16, %2;"
                 :: "r"(dst), "l"(src), "r"(srcsize) : "memory");
}
#define CP_COMMIT() asm volatile("cp.async.commit_group;" ::: "memory")
#define CP_WAIT0()  asm volatile("cp.async.wait_group 0;" ::: "memory")
#define CP_WAIT1()  asm volatile("cp.async.wait_group 1;" ::: "memory")

__device__ __forceinline__ void split2(float c0, float c1, uint32_t& hp, uint32_t& lp) {
    __nv_bfloat16 h0 = __float2bfloat16_rn(c0), h1 = __float2bfloat16_rn(c1);
    __nv_bfloat16 l0 = __float2bfloat16_rn(c0 - __bfloat162float(h0));
    __nv_bfloat16 l1 = __float2bfloat16_rn(c1 - __bfloat162float(h1));
    hp = (uint32_t)__bfloat16_as_ushort(h0) | ((uint32_t)__bfloat16_as_ushort(h1) << 16);
    lp = (uint32_t)__bfloat16_as_ushort(l0) | ((uint32_t)__bfloat16_as_ushort(l1) << 16);
}

// --------------------------- CSR build kernels ------------------------------
__global__ void k_zero_int(int* p, int n) {
    int i = blockIdx.x * blockDim.x + threadIdx.x;
    if (i < n) p[i] = 0;
}
__global__ void k_hist(int* cnt, const int* __restrict__ dst, int E) {
    int e = blockIdx.x * blockDim.x + threadIdx.x;
    if (e < E) atomicAdd(&cnt[dst[e]], 1);
}
__global__ void k_scan_block(const int* __restrict__ cnt, int* __restrict__ ptr,
                             int* __restrict__ bsum, float* __restrict__ dis, int n) {
    __shared__ int sm[1024];
    int i = blockIdx.x * 1024 + threadIdx.x;
    int v = (i < n) ? cnt[i] : 0;
    if (i < n) dis[i] = rsqrtf((float)v + 1.0f);
    sm[threadIdx.x] = v;
    __syncthreads();
    for (int off = 1; off < 1024; off <<= 1) {
        int t = (threadIdx.x >= off) ? sm[threadIdx.x - off] : 0;
        __syncthreads();
        sm[threadIdx.x] += t;
        __syncthreads();
    }
    if (i < n) ptr[i] = sm[threadIdx.x] - v;
    if (threadIdx.x == 1023) bsum[blockIdx.x] = sm[1023];
}
__global__ void k_scan_bsum(int* bsum, int nb, int* totalOut) {
    __shared__ int sm[256];
    int v = (threadIdx.x < nb) ? bsum[threadIdx.x] : 0;
    sm[threadIdx.x] = v;
    __syncthreads();
    for (int off = 1; off < 256; off <<= 1) {
        int t = (threadIdx.x >= off) ? sm[threadIdx.x - off] : 0;
        __syncthreads();
        sm[threadIdx.x] += t;
        __syncthreads();
    }
    if (threadIdx.x < nb) bsum[threadIdx.x] = sm[threadIdx.x] - v;
    if (threadIdx.x == 255) *totalOut = sm[255];
}
__global__ void k_scan_add(int* __restrict__ ptr, const int* __restrict__ bsum,
                           int* __restrict__ cursor, int n) {
    int i = blockIdx.x * blockDim.x + threadIdx.x;
    if (i < n) {
        int p = ptr[i] + bsum[i >> 10];
        ptr[i] = p;
        cursor[i] = p;
    }
}
__global__ void k_fill_csr(const int* __restrict__ src, const int* __restrict__ dst,
                           int* cursor, int* __restrict__ csr, int E) {
    int e = blockIdx.x * blockDim.x + threadIdx.x;
    if (e < E) {
        int pos = atomicAdd(&cursor[dst[e]], 1);
        csr[pos] = src[e];
    }
}

// ---------------------------- misc small kernels ----------------------------
__global__ void k_convW_all(const float* __restrict__ W1, const float* __restrict__ W2,
                            const float* __restrict__ W3, const float* __restrict__ L1w,
                            const float* __restrict__ L2w,
                            __nv_bfloat16* __restrict__ hi, __nv_bfloat16* __restrict__ lo)
{
    const int n1 = 5120, n2 = n1 + 32768, n3 = n2 + 32768,
              n4 = n3 + 2621440, n5 = n4 + 65536;
    int i = blockIdx.x * blockDim.x + threadIdx.x;
    if (i >= n5) return;
    float v;
    if      (i < n1) v = W1[i];
    else if (i < n2) v = W2[i - n1];
    else if (i < n3) v = W3[i - n2];
    else if (i < n4) v = L1w[i - n3];
    else             v = L2w[i - n4];
    __nv_bfloat16 h = __float2bfloat16_rn(v);
    hi[i] = h;
    lo[i] = __float2bfloat16_rn(v - __bfloat162float(h));
}

__global__ void k_reduce_split(const float* __restrict__ P, const float* __restrict__ bias,
                               __nv_bfloat16* __restrict__ Ohi, __nv_bfloat16* __restrict__ Olo,
                               int total, int ncols, int nsplit)
{
    int i = blockIdx.x * blockDim.x + threadIdx.x;
    if (i >= total) return;
    float s = bias[i % ncols];
    for (int z = 0; z < nsplit; z++) s += P[(long long)z * total + i];
    float v = lrelu_f(s);
    __nv_bfloat16 h = __float2bfloat16_rn(v);
    Ohi[i] = h;
    Olo[i] = __float2bfloat16_rn(v - __bfloat162float(h));
}

// ------------------------------ CSR gathers ---------------------------------
__global__ void __launch_bounds__(256)
k_gather128(const float* __restrict__ H, const float* __restrict__ aggb,
            __nv_bfloat16* __restrict__ Ohi, __nv_bfloat16* __restrict__ Olo,
            const int* __restrict__ ptr, const int* __restrict__ csr,
            const float* __restrict__ dis, int Nn, int doLrelu)
{
    int node = (int)(((long long)blockIdx.x * blockDim.x + threadIdx.x) >> 5);
    int lane = threadIdx.x & 31;
    if (node >= Nn) return;

    int p0 = ptr[node];
    int p1 = ptr[node + 1];
    float dn = dis[node];

    float4 acc = *(const float4*)(H + (long long)node * 128 + lane * 4);
    int p = p0;
    for (; p + 1 < p1; p += 2) {
        int s0 = csr[p], s1 = csr[p + 1];
        float4 v0 = *(const float4*)(H + (long long)s0 * 128 + lane * 4);
        float4 v1 = *(const float4*)(H + (long long)s1 * 128 + lane * 4);
        acc.x += v0.x + v1.x; acc.y += v0.y + v1.y;
        acc.z += v0.z + v1.z; acc.w += v0.w + v1.w;
    }
    if (p < p1) {
        int s0 = csr[p];
        float4 v0 = *(const float4*)(H + (long long)s0 * 128 + lane * 4);
        acc.x += v0.x; acc.y += v0.y; acc.z += v0.z; acc.w += v0.w;
    }
    acc.x *= dn; acc.y *= dn; acc.z *= dn; acc.w *= dn;
    if (aggb) {
        float4 bv = *(const float4*)(aggb + lane * 4);
        acc.x += bv.x; acc.y += bv.y; acc.z += bv.z; acc.w += bv.w;
    }
    if (doLrelu) {
        acc.x = lrelu_f(acc.x); acc.y = lrelu_f(acc.y);
        acc.z = lrelu_f(acc.z); acc.w = lrelu_f(acc.w);
    }
    uint32_t h0, l0, h1, l1;
    split2(acc.x, acc.y, h0, l0);
    split2(acc.z, acc.w, h1, l1);
    long long o = (long long)node * 128 + lane * 4;
    *(uint2*)(Ohi + o) = make_uint2(h0, h1);
    *(uint2*)(Olo + o) = make_uint2(l0, l1);
}

__global__ void __launch_bounds__(256)
k_gather40(const float* __restrict__ X,
           __nv_bfloat16* __restrict__ Ohi, __nv_bfloat16* __restrict__ Olo,
           const int* __restrict__ ptr, const int* __restrict__ csr,
           const float* __restrict__ dis, int Nn)
{
    int node = (int)(((long long)blockIdx.x * blockDim.x + threadIdx.x) >> 5);
    int lane = threadIdx.x & 31;
    if (node >= Nn) return;

    int p0 = ptr[node];
    int p1 = ptr[node + 1];
    float dn = dis[node];
    float d2 = dn * dn;

    long long base = (long long)node * 40;
    float a0 = X[base + lane] * d2;
    float a1 = (lane < 8) ? X[base + 32 + lane] * d2 : 0.f;
    for (int p = p0; p < p1; p++) {
        int s = csr[p];
        float nm = dn * dis[s];
        long long hb = (long long)s * 40;
        a0 += X[hb + lane] * nm;
        if (lane < 8) a1 += X[hb + 32 + lane] * nm;
    }
    __nv_bfloat16 h = __float2bfloat16_rn(a0);
    Ohi[base + lane] = h;
    Olo[base + lane] = __float2bfloat16_rn(a0 - __bfloat162float(h));
    if (lane < 8) {
        __nv_bfloat16 h1 = __float2bfloat16_rn(a1);
        Ohi[base + 32 + lane] = h1;
        Olo[base + 32 + lane] = __float2bfloat16_rn(a1 - __bfloat162float(h1));
    }
}

// ------------------------ tensor-core bf16x3 GEMM ---------------------------
// 3-stage cp.async ring, XOR-swizzled smem (SROW=64), 1 barrier per chunk.
// kSplit>1: plain-store partial to H + z*M*Nout.
// else if Ohi: presplit of (lreluOut? lrelu: id)(c + bias).
// else: H = (lreluOut? lrelu: id)(c + bias) * (rowScale ? rowScale[row] : 1).
__global__ void __launch_bounds__(256, 2)
k_mma_gemm(const __nv_bfloat16* __restrict__ Ahi, const __nv_bfloat16* __restrict__ Alo,
           const __nv_bfloat16* __restrict__ Whi, const __nv_bfloat16* __restrict__ Wlo,
           float* __restrict__ H,
           __nv_bfloat16* __restrict__ Ohi, __nv_bfloat16* __restrict__ Olo,
           const float* __restrict__ bias, const float* __restrict__ rowScale,
           int M, int Nout, int K, int kLen, int lreluOut, int kSplit)
{
    extern __shared__ __align__(128) char smem[];
    const uint32_t sb = smem_u32(smem);
    const int tid  = threadIdx.x;
    const int wid  = tid >> 5;
    const int lane = tid & 31;
    const int g    = lane >> 2;
    const int tig  = lane & 3;
    const int warpM = wid >> 1;
    const int warpN = wid & 1;
    const int mBase = blockIdx.y * TILE_M;
    const int nBase = blockIdx.x * TILE_N;
    const long long zOff = (long long)blockIdx.z * kLen;

    float acc[2][8][4];
#pragma unroll
    for (int i = 0; i < 2; i++)
#pragma unroll
        for (int j = 0; j < 8; j++)
#pragma unroll
            for (int q = 0; q < 4; q++) acc[i][j][q] = 0.f;

    // per-lane ldmatrix addresses for stage 0, kk=0 (XOR-swizzled)
    uint32_t aAddrH[2], aAddrL[2], bAddrH[2][2], bAddrL[2][2];
    {
#pragma unroll
        for (int ms = 0; ms < 2; ms++) {
            uint32_t row = (uint32_t)(warpM * 32 + ms * 16 + (lane & 15));
            uint32_t sw  = (row >> 1) & 3;
            uint32_t off = row * SROW + (((lane >> 4) ^ sw) << 4);
            aAddrH[ms] = sb + SOFF_AH + off;
            aAddrL[ms] = sb + SOFF_AL + off;
        }
        uint32_t bR0 = (uint32_t)(warpN * 64 + ((lane >> 4) & 1) * 8 + (lane & 7));
        uint32_t g0  = (lane >> 3) & 1;
#pragma unroll
        for (int nh = 0; nh < 2; nh++)
#pragma unroll
            for (int p = 0; p < 2; p++) {
                uint32_t row = bR0 + (uint32_t)(nh * 32 + p * 16);
                uint32_t sw  = (row >> 1) & 3;
                uint32_t off = row * SROW + ((g0 ^ sw) << 4);
                bAddrH[nh][p] = sb + SOFF_WH + off;
                bAddrL[nh][p] = sb + SOFF_WL + off;
            }
    }

    auto issueStage = [&](int stg, int kb) {
        const uint32_t so = sb + (uint32_t)(stg * STAGE_STRIDE);
#pragma unroll
        for (int q = tid; q < 512; q += 256) {
            int row = q >> 2, kg = q & 3;
            long long gk = zOff + kb + kg * 8;
            uint32_t sw   = ((uint32_t)row >> 1) & 3;
            uint32_t doff = (uint32_t)(row * SROW) + (((uint32_t)kg ^ sw) << 4);
            {
                int gm = mBase + row;
                bool ok = (gm < M) && (gk + 8 <= (long long)K);
                long long aoff = ok ? ((long long)gm * K + gk) : 0;
                int ss = ok ? 16 : 0;
                cp16(so + SOFF_AH + doff, Ahi + aoff, ss);
                cp16(so + SOFF_AL + doff, Alo + aoff, ss);
            }
            {
                bool ok = (gk + 8 <= (long long)K);
                long long woff = ok ? ((long long)(nBase + row) * K + gk) : 0;
                int ss = ok ? 16 : 0;
                cp16(so + SOFF_WH + doff, Whi + woff, ss);
                cp16(so + SOFF_WL + doff, Wlo + woff, ss);
            }
        }
    };

    issueStage(0, 0);
    CP_COMMIT();
    if (KC < kLen) { issueStage(1, KC); CP_COMMIT(); }

    int s = 0;
    for (int kb = 0; kb < kLen; kb += KC) {
        if (kb + KC >= kLen) CP_WAIT0(); else CP_WAIT1();
        __syncthreads();

        const int kn = kb + 2 * KC;
        if (kn < kLen) {
            int s2 = s + 2; if (s2 >= 3) s2 -= 3;
            issueStage(s2, kn);
            CP_COMMIT();
        }

        const uint32_t so = (uint32_t)(s * STAGE_STRIDE);
#pragma unroll
        for (int kk = 0; kk < 2; kk++) {
            const uint32_t kx = (uint32_t)(kk << 5);   // toggles g bit1 via XOR
            uint32_t AH[2][4], AL[2][4];
#pragma unroll
            for (int ms = 0; ms < 2; ms++) {
                LDMX4(AH[ms], (aAddrH[ms] + so) ^ kx);
                LDMX4(AL[ms], (aAddrL[ms] + so) ^ kx);
            }
#pragma unroll
            for (int nh = 0; nh < 2; nh++) {
#pragma unroll
                for (int p = 0; p < 2; p++) {
                    uint32_t BH[4], BL[4];
                    LDMX4(BH, (bAddrH[nh][p] + so) ^ kx);
                    LDMX4(BL, (bAddrL[nh][p] + so) ^ kx);
                    const int j0 = nh * 4 + p * 2;
#pragma unroll
                    for (int ms = 0; ms < 2; ms++) {
                        mma16816(acc[ms][j0],     AH[ms], BH);
                        mma16816(acc[ms][j0],     AH[ms], BL);
                        mma16816(acc[ms][j0],     AL[ms], BH);
                        mma16816(acc[ms][j0 + 1], AH[ms], BH + 2);
                        mma16816(acc[ms][j0 + 1], AH[ms], BL + 2);
                        mma16816(acc[ms][j0 + 1], AL[ms], BH + 2);
                    }
                }
            }
        }
        s = (s == 2) ? 0 : s + 1;
    }

    const int mW = mBase + warpM * 32;
    const long long zPart = (long long)blockIdx.z * M * Nout;
#pragma unroll
    for (int ms = 0; ms < 2; ms++) {
#pragma unroll
        for (int half = 0; half < 2; half++) {
            int row = mW + ms * 16 + g + half * 8;
            if (row >= M) continue;
            long long ro = (long long)row * Nout;
            float rs = 1.f;
            if (rowScale) rs = rowScale[row];
#pragma unroll
            for (int ns = 0; ns < 8; ns++) {
                int col = nBase + warpN * 64 + ns * 8 + 2 * tig;
                float c0 = acc[ms][ns][half * 2 + 0];
                float c1 = acc[ms][ns][half * 2 + 1];
                if (kSplit > 1) {
                    *(float2*)(H + zPart + ro + col) = make_float2(c0, c1);
                } else {
                    if (bias) { c0 += __ldg(&bias[col]); c1 += __ldg(&bias[col + 1]); }
                    if (lreluOut) { c0 = lrelu_f(c0); c1 = lrelu_f(c1); }
                    if (Ohi) {
                        uint32_t hp, lp;
                        split2(c0, c1, hp, lp);
                        *(uint32_t*)(Ohi + ro + col) = hp;
                        *(uint32_t*)(Olo + ro + col) = lp;
                    } else {
                        *(float2*)(H + ro + col) = make_float2(c0 * rs, c1 * rs);
                    }
                }
            }
        }
    }
}

// ---------------- final linear + sigmoid (fused L2 split-K reduce) -----------
__global__ void k_mlp_out(const float* __restrict__ P, const float* __restrict__ L2b,
                          const float* __restrict__ L3w, const float* __restrict__ L3b,
                          float* __restrict__ out, int G, int nsplit)
{
    int w    = (blockIdx.x * blockDim.x + threadIdx.x) >> 5;
    int lane = threadIdx.x & 31;
    if (w >= G) return;
    const int total = G * 128;
    float s = 0.f;
#pragma unroll
    for (int c = lane; c < 128; c += 32) {
        float v = __ldg(&L2b[c]);
        long long idx = (long long)w * 128 + c;
        for (int z = 0; z < nsplit; z++) v += P[(long long)z * total + idx];
        s += lrelu_f(v) * __ldg(&L3w[c]);
    }
#pragma unroll
    for (int off = 16; off; off >>= 1) s += __shfl_xor_sync(0xffffffffu, s, off);
    if (lane == 0) out[w] = 1.f / (1.f + expf(-(s + L3b[0])));
}

// ------------------------------- launch ------------------------------------
extern "C" void kernel_launch(void* const* d_in, const int* in_sizes, int n_in,
                              void* d_out, int out_size)
{
    const float* x   = (const float*)d_in[0];
    const int*   ei  = (const int*)d_in[1];
    const float* b1 = (const float*)d_in[3];
    const float* b2 = (const float*)d_in[5];
    const float* b3 = (const float*)d_in[7];
    const float* L1b = (const float*)d_in[9];
    const float* L2b = (const float*)d_in[11];
    const float* L3w = (const float*)d_in[12]; const float* L3b = (const float*)d_in[13];
    float* out = (float*)d_out;

    const int C = 40;
    const int N = in_sizes[0] / C;     // 200000
    const int E = in_sizes[1] / 2;     // 1000000
    const int G = N / 40;              // 5000

    const int* srcIdx = ei;
    const int* dstIdx = ei + E;

    float *bufA, *bufC, *dis;
    __nv_bfloat16 *whi, *wlo, *hiA, *loA, *hiB, *loB;
    int *ptr, *cursor, *csr, *bsum;
    cudaGetSymbolAddress((void**)&bufA, g_bufA);
    cudaGetSymbolAddress((void**)&bufC, g_bufC);
    cudaGetSymbolAddress((void**)&dis,  g_dis);
    cudaGetSymbolAddress((void**)&whi,  g_whi);
    cudaGetSymbolAddress((void**)&wlo,  g_wlo);
    cudaGetSymbolAddress((void**)&hiA,  g_hiA);
    cudaGetSymbolAddress((void**)&loA,  g_loA);
    cudaGetSymbolAddress((void**)&hiB,  g_hiB);
    cudaGetSymbolAddress((void**)&loB,  g_loB);
    cudaGetSymbolAddress((void**)&ptr,    g_ptr);
    cudaGetSymbolAddress((void**)&cursor, g_cursor);
    cudaGetSymbolAddress((void**)&csr,    g_csr);
    cudaGetSymbolAddress((void**)&bsum,   g_bsum);

    cudaFuncSetAttribute(k_mma_gemm, cudaFuncAttributeMaxDynamicSharedMemorySize, SMB);

    const int O1 = 0;
    const int O2 = O1 + 128 * 40;
    const int O3 = O2 + 256 * 128;
    const int O4 = O3 + 128 * 256;
    const int O5 = O4 + 512 * 5120;
    const int WTOT = O5 + 128 * 512;

    k_convW_all<<<(WTOT + 255) / 256, 256>>>(
        (const float*)d_in[2], (const float*)d_in[4], (const float*)d_in[6],
        (const float*)d_in[8], (const float*)d_in[10], whi, wlo);

    // ---- CSR build + degree normalization ----
    const int nb = (N + 1023) / 1024;
    k_zero_int <<<(N + 255) / 256, 256>>>(cursor, N);
    k_hist     <<<(E + 255) / 256, 256>>>(cursor, dstIdx, E);
    k_scan_block<<<nb, 1024>>>(cursor, ptr, bsum, dis, N);
    k_scan_bsum <<<1, 256>>>(bsum, nb, ptr + N);
    k_scan_add  <<<(N + 255) / 256, 256>>>(ptr, bsum, cursor, N);
    k_fill_csr  <<<(E + 255) / 256, 256>>>(srcIdx, dstIdx, cursor, csr, E);

    const int mTilesN = (N + 127) / 128;   // 1563
    const int mTilesG = (G + 127) / 128;   // 40
    const int gatherBlocks = (int)(((long long)N * 32 + 255) / 256);

    // ---- conv1 (aggregate-first): A1 = Âx -> presplit hiA/loA [N,40] ----
    k_gather40<<<gatherBlocks, 256>>>(x, hiA, loA, ptr, csr, dis, N);
    // GEMM1: P1' = lrelu(A1@W1^T + b1) * dis -> bufA fp32 [N,128]  (norm-folded)
    k_mma_gemm<<<dim3(1, mTilesN, 1), 256, SMB>>>(
        hiA, loA, whi + O1, wlo + O1, bufA, nullptr, nullptr,
        b1, dis, N, 128, 40, 64, 1, 1);

    // ---- conv2: A2 = dis*(P1'[d] + sum P1'[s]) -> hiB/loB ----
    k_gather128<<<gatherBlocks, 256>>>(bufA, nullptr, hiB, loB, ptr, csr, dis, N, 0);
    // GEMM2: lrelu(A2@W2^T + b2) -> presplit hiA/loA [N,256]
    k_mma_gemm<<<dim3(2, mTilesN, 1), 256, SMB>>>(
        hiB, loB, whi + O2, wlo + O2, nullptr, hiA, loA,
        b2, nullptr, N, 256, 128, 128, 1, 1);

    // ---- conv3 (transform-first): H3' = (in@W3^T)*dis -> bufA fp32 [N,128] ----
    k_mma_gemm<<<dim3(1, mTilesN, 1), 256, SMB>>>(
        hiA, loA, whi + O3, wlo + O3, bufA, nullptr, nullptr,
        nullptr, dis, N, 128, 256, 256, 0, 1);
    // gather: AGG3 = dis*(H3'[d] + sum H3'[s]) + b3, lrelu, presplit
    k_gather128<<<gatherBlocks, 256>>>(bufA, b3, hiB, loB, ptr, csr, dis, N, 1);

    // ---- MLP ----
    k_mma_gemm<<<dim3(4, mTilesG, 4), 256, SMB>>>(
        hiB, loB, whi + O4, wlo + O4, bufA, nullptr, nullptr,
        nullptr, nullptr, G, 512, 5120, 1280, 0, 4);
    k_reduce_split<<<(G * 512 + 255) / 256, 256>>>(
        bufA, L1b, hiA, loA, G * 512, 512, 4);
    k_mma_gemm<<<dim3(1, mTilesG, 4), 256, SMB>>>(
        hiA, loA, whi + O5, wlo + O5, bufC, nullptr, nullptr,
        nullptr, nullptr, G, 128, 512, 128, 0, 4);
    k_mlp_out<<<(G * 32 + 255) / 256, 256>>>(bufC, L2b, L3w, L3b, out, G, 4);
}

// round 15
// speedup vs baseline: 5.1059x; 1.0223x over previous
#include <cuda_runtime.h>
#include <cuda_bf16.h>
#include <math.h>
#include <stdint.h>

// ---------------------------------------------------------------------------
// GCN: 3x GCNConv(+lrelu) -> reshape(40/graph) -> 3x Linear -> sigmoid
// GEMMs: mma.sync m16n8k16 bf16x3 emulation, ldmatrix fragments, cp.async,
// 3-stage smem ring with XOR swizzle (SROW=64), one barrier per k-chunk.
// Aggregation: dst-CSR gather with norm folding. Deterministic split-K (z=8).
// ---------------------------------------------------------------------------

#define TILE_M 128
#define TILE_N 128
#define KC 32
#define SROW 64
#define ARR_BYTES (128 * SROW)        // 8192 per array per stage
#define SOFF_AH 0
#define SOFF_AL (1 * ARR_BYTES)
#define SOFF_WH (2 * ARR_BYTES)
#define SOFF_WL (3 * ARR_BYTES)
#define STAGE_STRIDE (4 * ARR_BYTES)  // 32768
#define SMB (3 * STAGE_STRIDE)        // 98304

#define NMAX 200000
#define EMAX 1000000

__device__ __align__(256) float g_bufA[(size_t)NMAX * 128];
__device__ __align__(256) float g_bufC[(size_t)NMAX * 32];
__device__ __align__(256) float g_dis[NMAX];
__device__ __align__(256) __nv_bfloat16 g_whi[2760000];
__device__ __align__(256) __nv_bfloat16 g_wlo[2760000];
__device__ __align__(256) __nv_bfloat16 g_hiA[(size_t)NMAX * 256];
__device__ __align__(256) __nv_bfloat16 g_loA[(size_t)NMAX * 256];
__device__ __align__(256) __nv_bfloat16 g_hiB[(size_t)NMAX * 128];
__device__ __align__(256) __nv_bfloat16 g_loB[(size_t)NMAX * 128];
__device__ __align__(256) int g_ptr[NMAX + 1];
__device__ __align__(256) int g_cursor[NMAX];
__device__ __align__(256) int g_csr[EMAX];
__device__ __align__(256) int g_bsum[256];

__device__ __forceinline__ float lrelu_f(float v) { return v > 0.f ? v : 0.1f * v; }

__device__ __forceinline__ uint32_t smem_u32(const void* p) {
    uint32_t a;
    asm("{ .reg .u64 t; cvta.to.shared.u64 t, %1; cvt.u32.u64 %0, t; }" : "=r"(a) : "l"(p));
    return a;
}
__device__ __forceinline__ void mma16816(float* c, const uint32_t* a, const uint32_t* b) {
    asm volatile(
        "mma.sync.aligned.m16n8k16.row.col.f32.bf16.bf16.f32 "
        "{%0,%1,%2,%3}, {%4,%5,%6,%7}, {%8,%9}, {%0,%1,%2,%3};"
        : "+f"(c[0]), "+f"(c[1]), "+f"(c[2]), "+f"(c[3])
        : "r"(a[0]), "r"(a[1]), "r"(a[2]), "r"(a[3]), "r"(b[0]), "r"(b[1]));
}
#define LDMX4(r, addr) \
    asm volatile("ldmatrix.sync.aligned.m8n8.x4.shared.b16 {%0,%1,%2,%3}, [%4];" \
        : "=r"((r)[0]), "=r"((r)[1]), "=r"((r)[2]), "=r"((r)[3]) : "r"(addr))
__device__ __forceinline__ void cp16(uint32_t dst, const void* src, int srcsize) {
    asm volatile("cp.async.cg.shared.global [%0], [%1], 16, %2;"
                 :: "r"(dst), "l"(src), "r"(srcsize) : "memory");
}
#define CP_COMMIT() asm volatile("cp.async.commit_group;" ::: "memory")
#define CP_WAIT0()  asm volatile("cp.async.wait_group 0;" ::: "memory")
#define CP_WAIT1()  asm volatile("cp.async.wait_group 1;" ::: "memory")

__device__ __forceinline__ void split2(float c0, float c1, uint32_t& hp, uint32_t& lp) {
    __nv_bfloat16 h0 = __float2bfloat16_rn(c0), h1 = __float2bfloat16_rn(c1);
    __nv_bfloat16 l0 = __float2bfloat16_rn(c0 - __bfloat162float(h0));
    __nv_bfloat16 l1 = __float2bfloat16_rn(c1 - __bfloat162float(h1));
    hp = (uint32_t)__bfloat16_as_ushort(h0) | ((uint32_t)__bfloat16_as_ushort(h1) << 16);
    lp = (uint32_t)__bfloat16_as_ushort(l0) | ((uint32_t)__bfloat16_as_ushort(l1) << 16);
}

// --------------------------- CSR build kernels ------------------------------
__global__ void k_hist(int* cnt, const int* __restrict__ dst, int E) {
    int e = blockIdx.x * blockDim.x + threadIdx.x;
    if (e < E) atomicAdd(&cnt[dst[e]], 1);
}
__global__ void k_scan_block(const int* __restrict__ cnt, int* __restrict__ ptr,
                             int* __restrict__ bsum, float* __restrict__ dis, int n) {
    __shared__ int sm[1024];
    int i = blockIdx.x * 1024 + threadIdx.x;
    int v = (i < n) ? cnt[i] : 0;
    if (i < n) dis[i] = rsqrtf((float)v + 1.0f);
    sm[threadIdx.x] = v;
    __syncthreads();
    for (int off = 1; off < 1024; off <<= 1) {
        int t = (threadIdx.x >= off) ? sm[threadIdx.x - off] : 0;
        __syncthreads();
        sm[threadIdx.x] += t;
        __syncthreads();
    }
    if (i < n) ptr[i] = sm[threadIdx.x] - v;
    if (threadIdx.x == 1023) bsum[blockIdx.x] = sm[1023];
}
__global__ void k_scan_bsum(int* bsum, int nb, int* totalOut) {
    __shared__ int sm[256];
    int v = (threadIdx.x < nb) ? bsum[threadIdx.x] : 0;
    sm[threadIdx.x] = v;
    __syncthreads();
    for (int off = 1; off < 256; off <<= 1) {
        int t = (threadIdx.x >= off) ? sm[threadIdx.x - off] : 0;
        __syncthreads();
        sm[threadIdx.x] += t;
        __syncthreads();
    }
    if (threadIdx.x < nb) bsum[threadIdx.x] = sm[threadIdx.x] - v;
    if (threadIdx.x == 255) *totalOut = sm[255];
}
__global__ void k_scan_add(int* __restrict__ ptr, const int* __restrict__ bsum,
                           int* __restrict__ cursor, int n) {
    int i = blockIdx.x * blockDim.x + threadIdx.x;
    if (i < n) {
        int p = ptr[i] + bsum[i >> 10];
        ptr[i] = p;
        cursor[i] = p;
    }
}
__global__ void k_fill_csr(const int* __restrict__ src, const int* __restrict__ dst,
                           int* cursor, int* __restrict__ csr, int E) {
    int e = blockIdx.x * blockDim.x + threadIdx.x;
    if (e < E) {
        int pos = atomicAdd(&cursor[dst[e]], 1);
        csr[pos] = src[e];
    }
}

// ---------------------------- misc small kernels ----------------------------
// weight fp32 -> bf16 hi/lo; also zeroes the degree counter (fused launch)
__global__ void k_convW_all(const float* __restrict__ W1, const float* __restrict__ W2,
                            const float* __restrict__ W3, const float* __restrict__ L1w,
                            const float* __restrict__ L2w,
                            __nv_bfloat16* __restrict__ hi, __nv_bfloat16* __restrict__ lo,
                            int* __restrict__ cnt, int Nn)
{
    const int n1 = 5120, n2 = n1 + 32768, n3 = n2 + 32768,
              n4 = n3 + 2621440, n5 = n4 + 65536;
    int i = blockIdx.x * blockDim.x + threadIdx.x;
    if (i < Nn) cnt[i] = 0;
    if (i >= n5) return;
    float v;
    if      (i < n1) v = W1[i];
    else if (i < n2) v = W2[i - n1];
    else if (i < n3) v = W3[i - n2];
    else if (i < n4) v = L1w[i - n3];
    else             v = L2w[i - n4];
    __nv_bfloat16 h = __float2bfloat16_rn(v);
    hi[i] = h;
    lo[i] = __float2bfloat16_rn(v - __bfloat162float(h));
}

__global__ void k_reduce_split(const float* __restrict__ P, const float* __restrict__ bias,
                               __nv_bfloat16* __restrict__ Ohi, __nv_bfloat16* __restrict__ Olo,
                               int total, int ncols, int nsplit)
{
    int i = blockIdx.x * blockDim.x + threadIdx.x;
    if (i >= total) return;
    float s = bias[i % ncols];
    for (int z = 0; z < nsplit; z++) s += P[(long long)z * total + i];
    float v = lrelu_f(s);
    __nv_bfloat16 h = __float2bfloat16_rn(v);
    Ohi[i] = h;
    Olo[i] = __float2bfloat16_rn(v - __bfloat162float(h));
}

// ------------------------------ CSR gathers ---------------------------------
__global__ void __launch_bounds__(256)
k_gather128(const float* __restrict__ H, const float* __restrict__ aggb,
            __nv_bfloat16* __restrict__ Ohi, __nv_bfloat16* __restrict__ Olo,
            const int* __restrict__ ptr, const int* __restrict__ csr,
            const float* __restrict__ dis, int Nn, int doLrelu)
{
    int node = (int)(((long long)blockIdx.x * blockDim.x + threadIdx.x) >> 5);
    int lane = threadIdx.x & 31;
    if (node >= Nn) return;

    int p0 = ptr[node];
    int p1 = ptr[node + 1];
    float dn = dis[node];

    float4 acc = *(const float4*)(H + (long long)node * 128 + lane * 4);
    int p = p0;
    for (; p + 1 < p1; p += 2) {
        int s0 = csr[p], s1 = csr[p + 1];
        float4 v0 = *(const float4*)(H + (long long)s0 * 128 + lane * 4);
        float4 v1 = *(const float4*)(H + (long long)s1 * 128 + lane * 4);
        acc.x += v0.x + v1.x; acc.y += v0.y + v1.y;
        acc.z += v0.z + v1.z; acc.w += v0.w + v1.w;
    }
    if (p < p1) {
        int s0 = csr[p];
        float4 v0 = *(const float4*)(H + (long long)s0 * 128 + lane * 4);
        acc.x += v0.x; acc.y += v0.y; acc.z += v0.z; acc.w += v0.w;
    }
    acc.x *= dn; acc.y *= dn; acc.z *= dn; acc.w *= dn;
    if (aggb) {
        float4 bv = *(const float4*)(aggb + lane * 4);
        acc.x += bv.x; acc.y += bv.y; acc.z += bv.z; acc.w += bv.w;
    }
    if (doLrelu) {
        acc.x = lrelu_f(acc.x); acc.y = lrelu_f(acc.y);
        acc.z = lrelu_f(acc.z); acc.w = lrelu_f(acc.w);
    }
    uint32_t h0, l0, h1, l1;
    split2(acc.x, acc.y, h0, l0);
    split2(acc.z, acc.w, h1, l1);
    long long o = (long long)node * 128 + lane * 4;
    *(uint2*)(Ohi + o) = make_uint2(h0, h1);
    *(uint2*)(Olo + o) = make_uint2(l0, l1);
}

__global__ void __launch_bounds__(256)
k_gather40(const float* __restrict__ X,
           __nv_bfloat16* __restrict__ Ohi, __nv_bfloat16* __restrict__ Olo,
           const int* __restrict__ ptr, const int* __restrict__ csr,
           const float* __restrict__ dis, int Nn)
{
    int node = (int)(((long long)blockIdx.x * blockDim.x + threadIdx.x) >> 5);
    int lane = threadIdx.x & 31;
    if (node >= Nn) return;

    int p0 = ptr[node];
    int p1 = ptr[node + 1];
    float dn = dis[node];
    float d2 = dn * dn;

    long long base = (long long)node * 40;
    float a0 = X[base + lane] * d2;
    float a1 = (lane < 8) ? X[base + 32 + lane] * d2 : 0.f;
    for (int p = p0; p < p1; p++) {
        int s = csr[p];
        float nm = dn * dis[s];
        long long hb = (long long)s * 40;
        a0 += X[hb + lane] * nm;
        if (lane < 8) a1 += X[hb + 32 + lane] * nm;
    }
    __nv_bfloat16 h = __float2bfloat16_rn(a0);
    Ohi[base + lane] = h;
    Olo[base + lane] = __float2bfloat16_rn(a0 - __bfloat162float(h));
    if (lane < 8) {
        __nv_bfloat16 h1 = __float2bfloat16_rn(a1);
        Ohi[base + 32 + lane] = h1;
        Olo[base + 32 + lane] = __float2bfloat16_rn(a1 - __bfloat162float(h1));
    }
}

// ------------------------ tensor-core bf16x3 GEMM ---------------------------
__global__ void __launch_bounds__(256, 2)
k_mma_gemm(const __nv_bfloat16* __restrict__ Ahi, const __nv_bfloat16* __restrict__ Alo,
           const __nv_bfloat16* __restrict__ Whi, const __nv_bfloat16* __restrict__ Wlo,
           float* __restrict__ H,
           __nv_bfloat16* __restrict__ Ohi, __nv_bfloat16* __restrict__ Olo,
           const float* __restrict__ bias, const float* __restrict__ rowScale,
           int M, int Nout, int K, int kLen, int lreluOut, int kSplit)
{
    extern __shared__ __align__(128) char smem[];
    const uint32_t sb = smem_u32(smem);
    const int tid  = threadIdx.x;
    const int wid  = tid >> 5;
    const int lane = tid & 31;
    const int g    = lane >> 2;
    const int tig  = lane & 3;
    const int warpM = wid >> 1;
    const int warpN = wid & 1;
    const int mBase = blockIdx.y * TILE_M;
    const int nBase = blockIdx.x * TILE_N;
    const long long zOff = (long long)blockIdx.z * kLen;

    float acc[2][8][4];
#pragma unroll
    for (int i = 0; i < 2; i++)
#pragma unroll
        for (int j = 0; j < 8; j++)
#pragma unroll
            for (int q = 0; q < 4; q++) acc[i][j][q] = 0.f;

    uint32_t aAddrH[2], aAddrL[2], bAddrH[2][2], bAddrL[2][2];
    {
#pragma unroll
        for (int ms = 0; ms < 2; ms++) {
            uint32_t row = (uint32_t)(warpM * 32 + ms * 16 + (lane & 15));
            uint32_t sw  = (row >> 1) & 3;
            uint32_t off = row * SROW + (((lane >> 4) ^ sw) << 4);
            aAddrH[ms] = sb + SOFF_AH + off;
            aAddrL[ms] = sb + SOFF_AL + off;
        }
        uint32_t bR0 = (uint32_t)(warpN * 64 + ((lane >> 4) & 1) * 8 + (lane & 7));
        uint32_t g0  = (lane >> 3) & 1;
#pragma unroll
        for (int nh = 0; nh < 2; nh++)
#pragma unroll
            for (int p = 0; p < 2; p++) {
                uint32_t row = bR0 + (uint32_t)(nh * 32 + p * 16);
                uint32_t sw  = (row >> 1) & 3;
                uint32_t off = row * SROW + ((g0 ^ sw) << 4);
                bAddrH[nh][p] = sb + SOFF_WH + off;
                bAddrL[nh][p] = sb + SOFF_WL + off;
            }
    }

    auto issueStage = [&](int stg, int kb) {
        const uint32_t so = sb + (uint32_t)(stg * STAGE_STRIDE);
#pragma unroll
        for (int q = tid; q < 512; q += 256) {
            int row = q >> 2, kg = q & 3;
            long long gk = zOff + kb + kg * 8;
            uint32_t sw   = ((uint32_t)row >> 1) & 3;
            uint32_t doff = (uint32_t)(row * SROW) + (((uint32_t)kg ^ sw) << 4);
            {
                int gm = mBase + row;
                bool ok = (gm < M) && (gk + 8 <= (long long)K);
                long long aoff = ok ? ((long long)gm * K + gk) : 0;
                int ss = ok ? 16 : 0;
                cp16(so + SOFF_AH + doff, Ahi + aoff, ss);
                cp16(so + SOFF_AL + doff, Alo + aoff, ss);
            }
            {
                bool ok = (gk + 8 <= (long long)K);
                long long woff = ok ? ((long long)(nBase + row) * K + gk) : 0;
                int ss = ok ? 16 : 0;
                cp16(so + SOFF_WH + doff, Whi + woff, ss);
                cp16(so + SOFF_WL + doff, Wlo + woff, ss);
            }
        }
    };

    issueStage(0, 0);
    CP_COMMIT();
    if (KC < kLen) { issueStage(1, KC); CP_COMMIT(); }

    int s = 0;
    for (int kb = 0; kb < kLen; kb += KC) {
        if (kb + KC >= kLen) CP_WAIT0(); else CP_WAIT1();
        __syncthreads();

        const int kn = kb + 2 * KC;
        if (kn < kLen) {
            int s2 = s + 2; if (s2 >= 3) s2 -= 3;
            issueStage(s2, kn);
            CP_COMMIT();
        }

        const uint32_t so = (uint32_t)(s * STAGE_STRIDE);
#pragma unroll
        for (int kk = 0; kk < 2; kk++) {
            const uint32_t kx = (uint32_t)(kk << 5);
            uint32_t AH[2][4], AL[2][4];
#pragma unroll
            for (int ms = 0; ms < 2; ms++) {
                LDMX4(AH[ms], (aAddrH[ms] + so) ^ kx);
                LDMX4(AL[ms], (aAddrL[ms] + so) ^ kx);
            }
#pragma unroll
            for (int nh = 0; nh < 2; nh++) {
#pragma unroll
                for (int p = 0; p < 2; p++) {
                    uint32_t BH[4], BL[4];
                    LDMX4(BH, (bAddrH[nh][p] + so) ^ kx);
                    LDMX4(BL, (bAddrL[nh][p] + so) ^ kx);
                    const int j0 = nh * 4 + p * 2;
#pragma unroll
                    for (int ms = 0; ms < 2; ms++) {
                        mma16816(acc[ms][j0],     AH[ms], BH);
                        mma16816(acc[ms][j0],     AH[ms], BL);
                        mma16816(acc[ms][j0],     AL[ms], BH);
                        mma16816(acc[ms][j0 + 1], AH[ms], BH + 2);
                        mma16816(acc[ms][j0 + 1], AH[ms], BL + 2);
                        mma16816(acc[ms][j0 + 1], AL[ms], BH + 2);
                    }
                }
            }
        }
        s = (s == 2) ? 0 : s + 1;
    }

    const int mW = mBase + warpM * 32;
    const long long zPart = (long long)blockIdx.z * M * Nout;
#pragma unroll
    for (int ms = 0; ms < 2; ms++) {
#pragma unroll
        for (int half = 0; half < 2; half++) {
            int row = mW + ms * 16 + g + half * 8;
            if (row >= M) continue;
            long long ro = (long long)row * Nout;
            float rs = 1.f;
            if (rowScale) rs = rowScale[row];
#pragma unroll
            for (int ns = 0; ns < 8; ns++) {
                int col = nBase + warpN * 64 + ns * 8 + 2 * tig;
                float c0 = acc[ms][ns][half * 2 + 0];
                float c1 = acc[ms][ns][half * 2 + 1];
                if (kSplit > 1) {
                    *(float2*)(H + zPart + ro + col) = make_float2(c0, c1);
                } else {
                    if (bias) { c0 += __ldg(&bias[col]); c1 += __ldg(&bias[col + 1]); }
                    if (lreluOut) { c0 = lrelu_f(c0); c1 = lrelu_f(c1); }
                    if (Ohi) {
                        uint32_t hp, lp;
                        split2(c0, c1, hp, lp);
                        *(uint32_t*)(Ohi + ro + col) = hp;
                        *(uint32_t*)(Olo + ro + col) = lp;
                    } else {
                        *(float2*)(H + ro + col) = make_float2(c0 * rs, c1 * rs);
                    }
                }
            }
        }
    }
}

// ---------------- final linear + sigmoid (fused L2 split-K reduce) -----------
__global__ void k_mlp_out(const float* __restrict__ P, const float* __restrict__ L2b,
                          const float* __restrict__ L3w, const float* __restrict__ L3b,
                          float* __restrict__ out, int G, int nsplit)
{
    int w    = (blockIdx.x * blockDim.x + threadIdx.x) >> 5;
    int lane = threadIdx.x & 31;
    if (w >= G) return;
    const int total = G * 128;
    float s = 0.f;
#pragma unroll
    for (int c = lane; c < 128; c += 32) {
        float v = __ldg(&L2b[c]);
        long long idx = (long long)w * 128 + c;
        for (int z = 0; z < nsplit; z++) v += P[(long long)z * total + idx];
        s += lrelu_f(v) * __ldg(&L3w[c]);
    }
#pragma unroll
    for (int off = 16; off; off >>= 1) s += __shfl_xor_sync(0xffffffffu, s, off);
    if (lane == 0) out[w] = 1.f / (1.f + expf(-(s + L3b[0])));
}

// ------------------------------- launch ------------------------------------
extern "C" void kernel_launch(void* const* d_in, const int* in_sizes, int n_in,
                              void* d_out, int out_size)
{
    const float* x   = (const float*)d_in[0];
    const int*   ei  = (const int*)d_in[1];
    const float* b1 = (const float*)d_in[3];
    const float* b2 = (const float*)d_in[5];
    const float* b3 = (const float*)d_in[7];
    const float* L1b = (const float*)d_in[9];
    const float* L2b = (const float*)d_in[11];
    const float* L3w = (const float*)d_in[12]; const float* L3b = (const float*)d_in[13];
    float* out = (float*)d_out;

    const int C = 40;
    const int N = in_sizes[0] / C;     // 200000
    const int E = in_sizes[1] / 2;     // 1000000
    const int G = N / 40;              // 5000

    const int* srcIdx = ei;
    const int* dstIdx = ei + E;

    float *bufA, *bufC, *dis;
    __nv_bfloat16 *whi, *wlo, *hiA, *loA, *hiB, *loB;
    int *ptr, *cursor, *csr, *bsum;
    cudaGetSymbolAddress((void**)&bufA, g_bufA);
    cudaGetSymbolAddress((void**)&bufC, g_bufC);
    cudaGetSymbolAddress((void**)&dis,  g_dis);
    cudaGetSymbolAddress((void**)&whi,  g_whi);
    cudaGetSymbolAddress((void**)&wlo,  g_wlo);
    cudaGetSymbolAddress((void**)&hiA,  g_hiA);
    cudaGetSymbolAddress((void**)&loA,  g_loA);
    cudaGetSymbolAddress((void**)&hiB,  g_hiB);
    cudaGetSymbolAddress((void**)&loB,  g_loB);
    cudaGetSymbolAddress((void**)&ptr,    g_ptr);
    cudaGetSymbolAddress((void**)&cursor, g_cursor);
    cudaGetSymbolAddress((void**)&csr,    g_csr);
    cudaGetSymbolAddress((void**)&bsum,   g_bsum);

    cudaFuncSetAttribute(k_mma_gemm, cudaFuncAttributeMaxDynamicSharedMemorySize, SMB);

    const int O1 = 0;
    const int O2 = O1 + 128 * 40;
    const int O3 = O2 + 256 * 128;
    const int O4 = O3 + 128 * 256;
    const int O5 = O4 + 512 * 5120;
    const int WTOT = O5 + 128 * 512;   // 2757632

    // weight conversion + cursor zeroing (fused)
    k_convW_all<<<(WTOT + 255) / 256, 256>>>(
        (const float*)d_in[2], (const float*)d_in[4], (const float*)d_in[6],
        (const float*)d_in[8], (const float*)d_in[10], whi, wlo, cursor, N);

    // ---- CSR build + degree normalization ----
    const int nb = (N + 1023) / 1024;
    k_hist     <<<(E + 255) / 256, 256>>>(cursor, dstIdx, E);
    k_scan_block<<<nb, 1024>>>(cursor, ptr, bsum, dis, N);
    k_scan_bsum <<<1, 256>>>(bsum, nb, ptr + N);
    k_scan_add  <<<(N + 255) / 256, 256>>>(ptr, bsum, cursor, N);
    k_fill_csr  <<<(E + 255) / 256, 256>>>(srcIdx, dstIdx, cursor, csr, E);

    const int mTilesN = (N + 127) / 128;   // 1563
    const int mTilesG = (G + 127) / 128;   // 40
    const int gatherBlocks = (int)(((long long)N * 32 + 255) / 256);

    // ---- conv1 (aggregate-first): A1 = Âx -> presplit hiA/loA [N,40] ----
    k_gather40<<<gatherBlocks, 256>>>(x, hiA, loA, ptr, csr, dis, N);
    // GEMM1: P1' = lrelu(A1@W1^T + b1) * dis -> bufA fp32 [N,128]
    k_mma_gemm<<<dim3(1, mTilesN, 1), 256, SMB>>>(
        hiA, loA, whi + O1, wlo + O1, bufA, nullptr, nullptr,
        b1, dis, N, 128, 40, 64, 1, 1);

    // ---- conv2: A2 = dis*(P1'[d] + sum P1'[s]) -> hiB/loB ----
    k_gather128<<<gatherBlocks, 256>>>(bufA, nullptr, hiB, loB, ptr, csr, dis, N, 0);
    // GEMM2: lrelu(A2@W2^T + b2) -> presplit hiA/loA [N,256]
    k_mma_gemm<<<dim3(2, mTilesN, 1), 256, SMB>>>(
        hiB, loB, whi + O2, wlo + O2, nullptr, hiA, loA,
        b2, nullptr, N, 256, 128, 128, 1, 1);

    // ---- conv3 (transform-first): H3' = (in@W3^T)*dis -> bufA fp32 [N,128] ----
    k_mma_gemm<<<dim3(1, mTilesN, 1), 256, SMB>>>(
        hiA, loA, whi + O3, wlo + O3, bufA, nullptr, nullptr,
        nullptr, dis, N, 128, 256, 256, 0, 1);
    // gather: AGG3 = dis*(H3'[d] + sum H3'[s]) + b3, lrelu, presplit
    k_gather128<<<gatherBlocks, 256>>>(bufA, b3, hiB, loB, ptr, csr, dis, N, 1);

    // ---- MLP ----
    // L1 split-K x8 -> partials in bufA [8][G,512]; reduce -> presplit hiA/loA
    k_mma_gemm<<<dim3(4, mTilesG, 8), 256, SMB>>>(
        hiB, loB, whi + O4, wlo + O4, bufA, nullptr, nullptr,
        nullptr, nullptr, G, 512, 5120, 640, 0, 8);
    k_reduce_split<<<(G * 512 + 255) / 256, 256>>>(
        bufA, L1b, hiA, loA, G * 512, 512, 8);
    // L2 split-K x8 -> partials in bufC [8][G,128]; reduce fused into mlp_out
    k_mma_gemm<<<dim3(1, mTilesG, 8), 256, SMB>>>(
        hiA, loA, whi + O5, wlo + O5, bufC, nullptr, nullptr,
        nullptr, nullptr, G, 128, 512, 64, 0, 8);
    k_mlp_out<<<(G * 32 + 255) / 256, 256>>>(bufC, L2b, L3w, L3b, out, G, 8);
}